// round 10
// baseline (speedup 1.0000x reference)
#include <cuda_runtime.h>
#include <cuda_bf16.h>
#include <math.h>
#include <stdint.h>

#define N_NODES 100000
#define N_EDGES 800000
#define N_NTILE 782
#define N_ETILE 6250

// bf16 tile image: 128 rows x 136 bf16 (272B stride); hi tile then lo tile
#define TROW 272
#define TBYTES 34816
#define IMGB 69632

// ---------------- device scratch ----------------
__device__ float g_h[(size_t)N_NODES * 128];
__device__ float g_q[(size_t)N_NODES * 128];
__device__ float g_k[(size_t)N_NODES * 128];
__device__ float g_v[(size_t)N_NODES * 128];
__device__ float g_skip[(size_t)N_NODES * 128];
__device__ float g_numer[(size_t)N_NODES * 128];
__device__ float g_denom[(size_t)N_NODES * 8];
__device__ unsigned char g_himg[(size_t)N_NTILE * IMGB];
__device__ unsigned char g_eaimg[(size_t)N_ETILE * IMGB];
__device__ unsigned char g_wimg[(size_t)15 * IMGB];
// sort scratch
__device__ int g_count[N_NODES];
__device__ int g_off2[N_NODES];
__device__ int g_src_s[N_EDGES];
__device__ int g_dst_s[N_EDGES];
__device__ int g_perm[N_EDGES];

// ---------------- PTX helpers ----------------
__device__ __forceinline__ uint32_t smem_u32(const void* p) {
    uint32_t a;
    asm("{ .reg .u64 t; cvta.to.shared.u64 t, %1; cvt.u32.u64 %0, t; }" : "=r"(a) : "l"(p));
    return a;
}
__device__ __forceinline__ void ldsm4(uint32_t* r, uint32_t addr) {
    asm volatile("ldmatrix.sync.aligned.m8n8.x4.shared.b16 {%0,%1,%2,%3}, [%4];"
                 : "=r"(r[0]), "=r"(r[1]), "=r"(r[2]), "=r"(r[3]) : "r"(addr));
}
__device__ __forceinline__ void mma16816(float* c, const uint32_t* a, uint32_t b0, uint32_t b1) {
    asm volatile("mma.sync.aligned.m16n8k16.row.col.f32.bf16.bf16.f32 "
                 "{%0,%1,%2,%3}, {%4,%5,%6,%7}, {%8,%9}, {%0,%1,%2,%3};"
                 : "+f"(c[0]), "+f"(c[1]), "+f"(c[2]), "+f"(c[3])
                 : "r"(a[0]), "r"(a[1]), "r"(a[2]), "r"(a[3]), "r"(b0), "r"(b1));
}
__device__ __forceinline__ void red_add4(float* addr, float a, float b, float c, float d) {
    asm volatile("red.global.add.v4.f32 [%0], {%1, %2, %3, %4};"
                 :: "l"(addr), "f"(a), "f"(b), "f"(c), "f"(d) : "memory");
}
__device__ __forceinline__ void cp_async16(uint32_t dst, const void* src) {
    asm volatile("cp.async.cg.shared.global [%0], [%1], 16;" :: "r"(dst), "l"(src));
}
#define CP_COMMIT() asm volatile("cp.async.commit_group;" ::: "memory")
#define CP_WAIT0()  asm volatile("cp.async.wait_group 0;" ::: "memory")
#define GBAR(id)    asm volatile("bar.sync %0, 256;" :: "r"(id) : "memory")

__device__ __forceinline__ float pe_val(int t, int c) {
    int j = c >> 1;
    float freq = expf(-logf(10000.0f) * (float)(2 * j) * (1.0f / 16.0f));
    float ang = (float)t * freq;
    return (c & 1) ? cosf(ang) : sinf(ang);
}
__device__ __forceinline__ void split_store8(unsigned char* img, int off, const float* v) {
    unsigned int h[4], l[4];
#pragma unroll
    for (int i = 0; i < 4; ++i) {
        __nv_bfloat16 h0 = __float2bfloat16(v[2 * i]);
        __nv_bfloat16 h1 = __float2bfloat16(v[2 * i + 1]);
        __nv_bfloat16 l0 = __float2bfloat16(v[2 * i] - __bfloat162float(h0));
        __nv_bfloat16 l1 = __float2bfloat16(v[2 * i + 1] - __bfloat162float(h1));
        h[i] = (unsigned int)__bfloat16_as_ushort(h0) | ((unsigned int)__bfloat16_as_ushort(h1) << 16);
        l[i] = (unsigned int)__bfloat16_as_ushort(l0) | ((unsigned int)__bfloat16_as_ushort(l1) << 16);
    }
    *(uint4*)(img + off) = make_uint4(h[0], h[1], h[2], h[3]);
    *(uint4*)(img + TBYTES + off) = make_uint4(l[0], l[1], l[2], l[3]);
}

// 3-pass split-bf16 GEMM, 8-warp layout: warp (wr,wc) -> C[wr*32..+32][wc*64..+64]
__device__ __forceinline__ void gemm3(uint32_t aHi, uint32_t aLo, uint32_t bHi, uint32_t bLo,
                                      int lane, int wr, int wc, float c[2][8][4]) {
    int rA = lane & 15;
    int kA = (lane >> 4) << 3;
    int rB = ((lane >> 4) << 3) + (lane & 7);
    int kB = ((lane >> 3) & 1) << 3;
    uint32_t aRow = (uint32_t)(wr * 32 + rA) * TROW;
    uint32_t bRow = (uint32_t)(wc * 64 + rB) * TROW;
    for (int pass = 0; pass < 3; ++pass) {
        uint32_t aB = (pass < 2) ? aHi : aLo;
        uint32_t bB = (pass == 1) ? bLo : bHi;
#pragma unroll
        for (int k16 = 0; k16 < 8; ++k16) {
            uint32_t ka = (uint32_t)(k16 * 16 + kA) * 2;
            uint32_t kb = (uint32_t)(k16 * 16 + kB) * 2;
            uint32_t a[2][4];
            ldsm4(a[0], aB + aRow + ka);
            ldsm4(a[1], aB + aRow + 16 * TROW + ka);
            uint32_t b[4][4];
#pragma unroll
            for (int p = 0; p < 4; ++p) ldsm4(b[p], bB + bRow + p * 16 * TROW + kb);
#pragma unroll
            for (int t = 0; t < 2; ++t)
#pragma unroll
                for (int nt = 0; nt < 8; ++nt)
                    mma16816(c[t][nt], a[t], b[nt >> 1][(nt & 1) * 2], b[nt >> 1][(nt & 1) * 2 + 1]);
        }
    }
}

// ---------------- sort-by-dst ----------------
__global__ void zero_count_kernel() {
    int i = blockIdx.x * blockDim.x + threadIdx.x;
    if (i < N_NODES) g_count[i] = 0;
}
__global__ void hist_kernel(const int* __restrict__ ei) {
    int e = blockIdx.x * blockDim.x + threadIdx.x;
    if (e < N_EDGES) atomicAdd(&g_count[ei[N_EDGES + e]], 1);
}
__global__ void scan_kernel() {
    __shared__ int warp_sums[32];
    __shared__ int s_carry;
    int tid = threadIdx.x;
    int lane = tid & 31, wid = tid >> 5;
    if (tid == 0) s_carry = 0;
    __syncthreads();
    for (int base = 0; base < N_NODES; base += 1024) {
        int idx = base + tid;
        int v = (idx < N_NODES) ? g_count[idx] : 0;
        int inc = v;
#pragma unroll
        for (int o = 1; o < 32; o <<= 1) {
            int t = __shfl_up_sync(0xffffffffu, inc, o);
            if (lane >= o) inc += t;
        }
        if (lane == 31) warp_sums[wid] = inc;
        __syncthreads();
        if (wid == 0) {
            int w = warp_sums[lane];
            int wi = w;
#pragma unroll
            for (int o = 1; o < 32; o <<= 1) {
                int t = __shfl_up_sync(0xffffffffu, wi, o);
                if (lane >= o) wi += t;
            }
            warp_sums[lane] = wi - w;
        }
        __syncthreads();
        int ex = inc - v + warp_sums[wid] + s_carry;
        if (idx < N_NODES) g_off2[idx] = ex;
        __syncthreads();
        if (tid == 1023) s_carry = ex + v;
        __syncthreads();
    }
}
__global__ void scatter_kernel(const int* __restrict__ ei) {
    int e = blockIdx.x * blockDim.x + threadIdx.x;
    if (e >= N_EDGES) return;
    int d = ei[N_EDGES + e];
    int pos = atomicAdd(&g_off2[d], 1);
    g_src_s[pos] = ei[e];
    g_dst_s[pos] = d;
    g_perm[pos] = e;
}

// ---------------- builders ----------------
__global__ void build_h_kernel(const float* __restrict__ x, const int* __restrict__ nlu) {
    int gid = blockIdx.x * blockDim.x + threadIdx.x;
    if (gid >= N_NODES * 16) return;
    int n = gid >> 4, j = gid & 15, c0 = j * 8;
    float v[8];
    if (c0 < 96) {
        float4 a = *(const float4*)(x + (size_t)n * 96 + c0);
        float4 b = *(const float4*)(x + (size_t)n * 96 + c0 + 4);
        v[0] = a.x; v[1] = a.y; v[2] = a.z; v[3] = a.w; v[4] = b.x; v[5] = b.y; v[6] = b.z; v[7] = b.w;
    } else {
        int t = nlu[n * 2 + ((c0 - 96) >> 4)];
        int cl = (c0 - 96) & 15;
#pragma unroll
        for (int i = 0; i < 8; ++i) v[i] = pe_val(t, cl + i);
    }
    split_store8(g_himg + (size_t)(n >> 7) * IMGB, (n & 127) * TROW + c0 * 2, v);
}
__global__ void build_eaimg_kernel(const float* __restrict__ eattr, const int* __restrict__ elu) {
    int gid = blockIdx.x * blockDim.x + threadIdx.x;
    if (gid >= N_EDGES * 16) return;
    int p = gid >> 4, j = gid & 15, c0 = j * 8;
    int e = g_perm[p];
    float v[8];
    if (c0 < 96) {
        float4 a = *(const float4*)(eattr + (size_t)e * 96 + c0);
        float4 b = *(const float4*)(eattr + (size_t)e * 96 + c0 + 4);
        v[0] = a.x; v[1] = a.y; v[2] = a.z; v[3] = a.w; v[4] = b.x; v[5] = b.y; v[6] = b.z; v[7] = b.w;
    } else {
        int t = elu[(size_t)e * 2 + ((c0 - 96) >> 4)];
        int cl = (c0 - 96) & 15;
#pragma unroll
        for (int i = 0; i < 8; ++i) v[i] = pe_val(t, cl + i);
    }
    split_store8(g_eaimg + (size_t)(p >> 7) * IMGB, (p & 127) * TROW + c0 * 2, v);
}
__global__ void prep_w_kernel(const float* __restrict__ Wq, const float* __restrict__ Wk,
                              const float* __restrict__ Wv, const float* __restrict__ Ws,
                              const float* __restrict__ We) {
    int gid = blockIdx.x * blockDim.x + threadIdx.x;
    if (gid >= 15 * 2048) return;
    int t = gid >> 11, rem = gid & 2047;
    int n = rem >> 4, j = rem & 15, k0 = j * 8;
    int l = t / 5, m = t % 5;
    const float* W = (m == 0) ? Wq : (m == 1) ? Wk : (m == 2) ? Wv : (m == 3) ? Ws : We;
    const float* base = W + (size_t)l * 16384;
    float v[8];
#pragma unroll
    for (int i = 0; i < 8; ++i) v[i] = base[(size_t)(k0 + i) * 128 + n];
    split_store8(g_wimg + (size_t)t * IMGB, n * TROW + k0 * 2, v);
}

// ---------------- node GEMM (unchanged) ----------------
#define OFF_NB 69632
#define OFF_NBIAS 139264
#define SMEM_NODE 139776
__global__ __launch_bounds__(256, 1)
void node_mma_kernel(const float* __restrict__ bq, const float* __restrict__ bk,
                     const float* __restrict__ bv, const float* __restrict__ bsk, int layer) {
    extern __shared__ __align__(16) unsigned char smem[];
    uint32_t sb = smem_u32(smem);
    int tid = threadIdx.x, wid = tid >> 5, lane = tid & 31;
    int wr = wid & 3, wc = wid >> 2;
    int tile = blockIdx.x, ysel = blockIdx.y;
    int gi = lane >> 2, tig = lane & 3;

    const uint4* aimg = (const uint4*)(g_himg + (size_t)tile * IMGB);
    uint4* sA = (uint4*)smem;
#pragma unroll
    for (int it = 0; it < 17; ++it) sA[it * 256 + tid] = aimg[it * 256 + tid];

    float* biasBuf = (float*)(smem + OFF_NBIAS);
    uint4* sB = (uint4*)(smem + OFF_NB);

    for (int w2 = 0; w2 < 2; ++w2) {
        int w = ysel * 2 + w2;
        __syncthreads();
        const uint4* bimg = (const uint4*)(g_wimg + (size_t)(layer * 5 + w) * IMGB);
#pragma unroll
        for (int it = 0; it < 17; ++it) sB[it * 256 + tid] = bimg[it * 256 + tid];
        if (tid < 128) {
            const float* bias = (w == 0) ? bq : (w == 1) ? bk : (w == 2) ? bv : bsk;
            biasBuf[tid] = bias[layer * 128 + tid];
        }
        __syncthreads();

        float c[2][8][4];
#pragma unroll
        for (int t = 0; t < 2; ++t)
#pragma unroll
            for (int nt = 0; nt < 8; ++nt)
#pragma unroll
                for (int j = 0; j < 4; ++j) c[t][nt][j] = 0.0f;

        gemm3(sb, sb + TBYTES, sb + OFF_NB, sb + OFF_NB + TBYTES, lane, wr, wc, c);

        float* out = (w == 0) ? g_q : (w == 1) ? g_k : (w == 2) ? g_v : g_skip;
#pragma unroll
        for (int t = 0; t < 2; ++t) {
#pragma unroll
            for (int half = 0; half < 2; ++half) {
                int node = tile * 128 + wr * 32 + t * 16 + gi + half * 8;
                if (node < N_NODES) {
                    float* op = out + (size_t)node * 128;
#pragma unroll
                    for (int nt = 0; nt < 8; ++nt) {
                        int col = wc * 64 + nt * 8 + tig * 2;
                        *(float2*)(op + col) = make_float2(c[t][nt][half * 2 + 0] + biasBuf[col],
                                                           c[t][nt][half * 2 + 1] + biasBuf[col + 1]);
                    }
                }
            }
        }
    }
}

// ---------------- edge kernel: 2 independent 8-warp tile streams per block ----------------
#define SMEM_EDGE 210944
__global__ __launch_bounds__(512, 1)
void edge_mma_kernel(int layer) {
    extern __shared__ __align__(16) unsigned char smem[];
    uint32_t sb = smem_u32(smem);
    int tid = threadIdx.x, wid = tid >> 5, lane = tid & 31;
    int g = wid >> 3;                 // stream group 0/1
    int gtid = tid & 255;
    int lw = wid & 7;
    int wr = lw & 3, wc = lw >> 2;
    int gi = lane >> 2, tig = lane & 3;
    int tx = gtid & 15, ty = gtid >> 4;
    int hd = tx >> 1, cb = tx << 3;
    int barid = 2 + g;

    // shared resident B (We image)
    const uint4* bimg = (const uint4*)(g_wimg + (size_t)(layer * 5 + 4) * IMGB);
    uint4* sB = (uint4*)smem;
    for (int i = tid; i < 4352; i += 512) sB[i] = bimg[i];
    __syncthreads();

    uint32_t aBuf = sb + 69632 + g * 69632;
    unsigned char* aPtr = smem + 69632 + g * 69632;
    float* est = (float*)aPtr;
    int* s_src = (int*)(smem + 208896 + g * 1024);
    int* s_dst = s_src + 128;

    int tile0 = blockIdx.x * 2 + g;
    const int stride = 296;           // 2 * gridDim.x (grid fixed at 148)

    if (tile0 < N_ETILE) {
        const unsigned char* src = g_eaimg + (size_t)tile0 * IMGB;
        for (int i = gtid; i < 4352; i += 256)
            cp_async16(aBuf + i * 16, src + (size_t)i * 16);
    }
    CP_COMMIT();

    for (int tile = tile0; tile < N_ETILE; tile += stride) {
        CP_WAIT0();
        GBAR(barid);                  // A(tile) visible group-wide
        if (gtid < 128) {
            s_src[gtid] = g_src_s[(tile << 7) + gtid];
            s_dst[gtid] = g_dst_s[(tile << 7) + gtid];
        }

        float c[2][8][4];
#pragma unroll
        for (int t = 0; t < 2; ++t)
#pragma unroll
            for (int nt = 0; nt < 8; ++nt)
#pragma unroll
                for (int j = 0; j < 4; ++j) c[t][nt][j] = 0.0f;

        gemm3(aBuf, aBuf + TBYTES, sb, sb + TBYTES, lane, wr, wc, c);

        GBAR(barid);                  // A reads done; s_src/s_dst stored
#pragma unroll
        for (int t = 0; t < 2; ++t)
#pragma unroll
            for (int half = 0; half < 2; ++half) {
                int r = wr * 32 + t * 16 + gi + half * 8;
#pragma unroll
                for (int nt = 0; nt < 8; ++nt) {
                    int col = wc * 64 + nt * 8 + tig * 2;
                    *(float2*)(est + r * 132 + col) = make_float2(c[t][nt][half * 2], c[t][nt][half * 2 + 1]);
                }
            }
        GBAR(barid);                  // est published

        // run-coalesced softmax epilogue: 8 edges/thread, q-reuse within runs
        int cur_d = -1;
        float4 q0, q1;
        float aN0 = 0.f, aN1 = 0.f, aN2 = 0.f, aN3 = 0.f;
        float aN4 = 0.f, aN5 = 0.f, aN6 = 0.f, aN7 = 0.f;
        float aD = 0.f;
#pragma unroll
        for (int i = 0; i < 8; ++i) {
            int er = ty * 8 + i;
            float4 e0v = *(const float4*)(est + er * 132 + cb);
            float4 e1v = *(const float4*)(est + er * 132 + cb + 4);
            float e8[8] = {e0v.x, e0v.y, e0v.z, e0v.w, e1v.x, e1v.y, e1v.z, e1v.w};
            int s = s_src[er], d = s_dst[er];
            if (d != cur_d) {
                if (cur_d >= 0) {
                    float* np = g_numer + (size_t)cur_d * 128 + cb;
                    red_add4(np,     aN0, aN1, aN2, aN3);
                    red_add4(np + 4, aN4, aN5, aN6, aN7);
                    if (!(tx & 1)) atomicAdd(g_denom + (size_t)cur_d * 8 + hd, aD);
                }
                cur_d = d;
                aN0 = aN1 = aN2 = aN3 = aN4 = aN5 = aN6 = aN7 = 0.f;
                aD = 0.f;
                const float* qp = g_q + (size_t)d * 128 + cb;
                q0 = *(const float4*)qp;
                q1 = *(const float4*)(qp + 4);
            }
            const float* kp = g_k + (size_t)s * 128 + cb;
            float4 k0 = *(const float4*)kp, k1 = *(const float4*)(kp + 4);
            float part = q0.x * (k0.x + e8[0]) + q0.y * (k0.y + e8[1])
                       + q0.z * (k0.z + e8[2]) + q0.w * (k0.w + e8[3])
                       + q1.x * (k1.x + e8[4]) + q1.y * (k1.y + e8[5])
                       + q1.z * (k1.z + e8[6]) + q1.w * (k1.w + e8[7]);
            float full = part + __shfl_xor_sync(0xffffffffu, part, 1);
            float p = __expf(full * 0.25f);  // shift-free softmax (alpha is O(1))
            const float* vp = g_v + (size_t)s * 128 + cb;
            float4 v0 = *(const float4*)vp, v1 = *(const float4*)(vp + 4);
            aN0 += p * (v0.x + e8[0]); aN1 += p * (v0.y + e8[1]);
            aN2 += p * (v0.z + e8[2]); aN3 += p * (v0.w + e8[3]);
            aN4 += p * (v1.x + e8[4]); aN5 += p * (v1.y + e8[5]);
            aN6 += p * (v1.z + e8[6]); aN7 += p * (v1.w + e8[7]);
            aD += p;
        }
        {
            float* np = g_numer + (size_t)cur_d * 128 + cb;
            red_add4(np,     aN0, aN1, aN2, aN3);
            red_add4(np + 4, aN4, aN5, aN6, aN7);
            if (!(tx & 1)) atomicAdd(g_denom + (size_t)cur_d * 8 + hd, aD);
        }
        GBAR(barid);                  // est consumed -> buffer reusable

        int next = tile + stride;
        if (next < N_ETILE) {
            const unsigned char* src = g_eaimg + (size_t)next * IMGB;
            for (int i = gtid; i < 4352; i += 256)
                cp_async16(aBuf + i * 16, src + (size_t)i * 16);
        }
        CP_COMMIT();
    }
}

// ---------------- node update ----------------
__global__ void update_h_kernel() {
    int gid = blockIdx.x * blockDim.x + threadIdx.x;
    if (gid >= N_NODES * 16) return;
    int n = gid >> 4, j = gid & 15, c0 = j * 8;
    float inv = 1.0f / (g_denom[n * 8 + (c0 >> 4)] + 1e-16f);
    float4 n0 = *(const float4*)(g_numer + (size_t)n * 128 + c0);
    float4 n1 = *(const float4*)(g_numer + (size_t)n * 128 + c0 + 4);
    float4 s0 = *(const float4*)(g_skip + (size_t)n * 128 + c0);
    float4 s1 = *(const float4*)(g_skip + (size_t)n * 128 + c0 + 4);
    float v[8];
    v[0] = fmaxf(n0.x * inv + s0.x, 0.f); v[1] = fmaxf(n0.y * inv + s0.y, 0.f);
    v[2] = fmaxf(n0.z * inv + s0.z, 0.f); v[3] = fmaxf(n0.w * inv + s0.w, 0.f);
    v[4] = fmaxf(n1.x * inv + s1.x, 0.f); v[5] = fmaxf(n1.y * inv + s1.y, 0.f);
    v[6] = fmaxf(n1.z * inv + s1.z, 0.f); v[7] = fmaxf(n1.w * inv + s1.w, 0.f);
    *(float4*)(g_h + (size_t)n * 128 + c0)     = make_float4(v[0], v[1], v[2], v[3]);
    *(float4*)(g_h + (size_t)n * 128 + c0 + 4) = make_float4(v[4], v[5], v[6], v[7]);
    split_store8(g_himg + (size_t)(n >> 7) * IMGB, (n & 127) * TROW + c0 * 2, v);
    float4 z = make_float4(0.f, 0.f, 0.f, 0.f);
    *(float4*)(g_numer + (size_t)n * 128 + c0)     = z;
    *(float4*)(g_numer + (size_t)n * 128 + c0 + 4) = z;
    if (!(j & 1)) g_denom[n * 8 + (j >> 1)] = 0.0f;
}

// ---------------- output GEMM ----------------
__global__ void out_gemm_kernel(const float* __restrict__ Wout, const float* __restrict__ bout,
                                float* __restrict__ out) {
    __shared__ float ws[128 * 16];
    __shared__ float hs[16 * 128];
    int tid = threadIdx.x;
    int row0 = blockIdx.x * 16;
#pragma unroll
    for (int it = 0; it < 8; ++it) {
        int idx = it * 256 + tid;
        ws[idx] = Wout[idx];
        int r = row0 + (idx >> 7);
        hs[idx] = (r < N_NODES) ? g_h[(size_t)row0 * 128 + idx] : 0.0f;
    }
    __syncthreads();
    int r = tid >> 4, c = tid & 15;
    float s = bout[c];
#pragma unroll 8
    for (int k = 0; k < 128; ++k) s += hs[r * 128 + k] * ws[k * 16 + c];
    int gr = row0 + r;
    if (gr < N_NODES) out[(size_t)gr * 16 + c] = s;
}

// ---------------- host ----------------
extern "C" void kernel_launch(void* const* d_in, const int* in_sizes, int n_in,
                              void* d_out, int out_size) {
    const float* x     = (const float*)d_in[0];
    const int*   nlu   = (const int*)  d_in[1];
    const int*   ei    = (const int*)  d_in[2];
    const float* eattr = (const float*)d_in[3];
    const int*   elu   = (const int*)  d_in[4];
    const float* Wq    = (const float*)d_in[5];
    const float* bq    = (const float*)d_in[6];
    const float* Wk    = (const float*)d_in[7];
    const float* bk    = (const float*)d_in[8];
    const float* Wv    = (const float*)d_in[9];
    const float* bv    = (const float*)d_in[10];
    const float* We    = (const float*)d_in[11];
    const float* Ws    = (const float*)d_in[12];
    const float* bs    = (const float*)d_in[13];
    const float* Wout  = (const float*)d_in[14];
    const float* bout  = (const float*)d_in[15];
    float* out = (float*)d_out;
    (void)in_sizes; (void)n_in; (void)out_size;

    cudaFuncSetAttribute(node_mma_kernel, cudaFuncAttributeMaxDynamicSharedMemorySize, SMEM_NODE);
    cudaFuncSetAttribute(edge_mma_kernel, cudaFuncAttributeMaxDynamicSharedMemorySize, SMEM_EDGE);

    zero_count_kernel<<<(N_NODES + 255) / 256, 256>>>();
    hist_kernel<<<(N_EDGES + 255) / 256, 256>>>(ei);
    scan_kernel<<<1, 1024>>>();
    scatter_kernel<<<(N_EDGES + 255) / 256, 256>>>(ei);

    build_h_kernel    <<<(N_NODES * 16 + 255) / 256, 256>>>(x, nlu);
    build_eaimg_kernel<<<(N_EDGES * 16 + 255) / 256, 256>>>(eattr, elu);
    prep_w_kernel     <<<(15 * 2048 + 255) / 256, 256>>>(Wq, Wk, Wv, Ws, We);

    for (int l = 0; l < 3; ++l) {
        node_mma_kernel<<<dim3(N_NTILE, 2), 256, SMEM_NODE>>>(bq, bk, bv, bs, l);
        edge_mma_kernel<<<148, 512, SMEM_EDGE>>>(l);
        update_h_kernel<<<(N_NODES * 16 + 255) / 256, 256>>>();
    }
    out_gemm_kernel<<<N_NODES / 16, 256>>>(Wout, bout, out);
}

// round 11
// speedup vs baseline: 1.0284x; 1.0284x over previous
#include <cuda_runtime.h>
#include <cuda_bf16.h>
#include <math.h>
#include <stdint.h>

#define N_NODES 100000
#define N_EDGES 800000
#define N_NTILE 782
#define N_ETILE 6250

// bf16 tile image: 128 rows x 136 bf16 (272B stride); hi tile then lo tile
#define TROW 272
#define TBYTES 34816
#define IMGB 69632

// ---------------- device scratch ----------------
__device__ float g_h[(size_t)N_NODES * 128];
__device__ float g_q[(size_t)N_NODES * 128];
__device__ float g_k[(size_t)N_NODES * 128];
__device__ float g_v[(size_t)N_NODES * 128];
__device__ float g_skip[(size_t)N_NODES * 128];
__device__ float g_numer[(size_t)N_NODES * 128];
__device__ float g_denom[(size_t)N_NODES * 8];
__device__ unsigned char g_himg[(size_t)N_NTILE * IMGB];
__device__ unsigned char g_eaimg[(size_t)N_ETILE * IMGB];
__device__ unsigned char g_wimg[(size_t)15 * IMGB];
// sort scratch
__device__ int g_count[N_NODES];
__device__ int g_off2[N_NODES];
__device__ int g_src_s[N_EDGES];
__device__ int g_dst_s[N_EDGES];
__device__ int g_perm[N_EDGES];

// ---------------- PTX helpers ----------------
__device__ __forceinline__ uint32_t smem_u32(const void* p) {
    uint32_t a;
    asm("{ .reg .u64 t; cvta.to.shared.u64 t, %1; cvt.u32.u64 %0, t; }" : "=r"(a) : "l"(p));
    return a;
}
__device__ __forceinline__ void ldsm4(uint32_t* r, uint32_t addr) {
    asm volatile("ldmatrix.sync.aligned.m8n8.x4.shared.b16 {%0,%1,%2,%3}, [%4];"
                 : "=r"(r[0]), "=r"(r[1]), "=r"(r[2]), "=r"(r[3]) : "r"(addr));
}
__device__ __forceinline__ void mma16816(float* c, const uint32_t* a, uint32_t b0, uint32_t b1) {
    asm volatile("mma.sync.aligned.m16n8k16.row.col.f32.bf16.bf16.f32 "
                 "{%0,%1,%2,%3}, {%4,%5,%6,%7}, {%8,%9}, {%0,%1,%2,%3};"
                 : "+f"(c[0]), "+f"(c[1]), "+f"(c[2]), "+f"(c[3])
                 : "r"(a[0]), "r"(a[1]), "r"(a[2]), "r"(a[3]), "r"(b0), "r"(b1));
}
__device__ __forceinline__ void red_add4(float* addr, float a, float b, float c, float d) {
    asm volatile("red.global.add.v4.f32 [%0], {%1, %2, %3, %4};"
                 :: "l"(addr), "f"(a), "f"(b), "f"(c), "f"(d) : "memory");
}
__device__ __forceinline__ void cp_async16(uint32_t dst, const void* src) {
    asm volatile("cp.async.cg.shared.global [%0], [%1], 16;" :: "r"(dst), "l"(src));
}
#define CP_COMMIT() asm volatile("cp.async.commit_group;" ::: "memory")
#define CP_WAIT0()  asm volatile("cp.async.wait_group 0;" ::: "memory")
#define BAR_SYNC(id, n)   asm volatile("bar.sync %0, %1;"   :: "r"(id), "r"(n) : "memory")
#define BAR_ARRIVE(id, n) asm volatile("bar.arrive %0, %1;" :: "r"(id), "r"(n) : "memory")

__device__ __forceinline__ float pe_val(int t, int c) {
    int j = c >> 1;
    float freq = expf(-logf(10000.0f) * (float)(2 * j) * (1.0f / 16.0f));
    float ang = (float)t * freq;
    return (c & 1) ? cosf(ang) : sinf(ang);
}
__device__ __forceinline__ void split_store8(unsigned char* img, int off, const float* v) {
    unsigned int h[4], l[4];
#pragma unroll
    for (int i = 0; i < 4; ++i) {
        __nv_bfloat16 h0 = __float2bfloat16(v[2 * i]);
        __nv_bfloat16 h1 = __float2bfloat16(v[2 * i + 1]);
        __nv_bfloat16 l0 = __float2bfloat16(v[2 * i] - __bfloat162float(h0));
        __nv_bfloat16 l1 = __float2bfloat16(v[2 * i + 1] - __bfloat162float(h1));
        h[i] = (unsigned int)__bfloat16_as_ushort(h0) | ((unsigned int)__bfloat16_as_ushort(h1) << 16);
        l[i] = (unsigned int)__bfloat16_as_ushort(l0) | ((unsigned int)__bfloat16_as_ushort(l1) << 16);
    }
    *(uint4*)(img + off) = make_uint4(h[0], h[1], h[2], h[3]);
    *(uint4*)(img + TBYTES + off) = make_uint4(l[0], l[1], l[2], l[3]);
}

// 3-pass split-bf16 GEMM, 8-warp layout: warp (wr,wc) -> C[wr*32..+32][wc*64..+64]
__device__ __forceinline__ void gemm3(uint32_t aHi, uint32_t aLo, uint32_t bHi, uint32_t bLo,
                                      int lane, int wr, int wc, float c[2][8][4]) {
    int rA = lane & 15;
    int kA = (lane >> 4) << 3;
    int rB = ((lane >> 4) << 3) + (lane & 7);
    int kB = ((lane >> 3) & 1) << 3;
    uint32_t aRow = (uint32_t)(wr * 32 + rA) * TROW;
    uint32_t bRow = (uint32_t)(wc * 64 + rB) * TROW;
    for (int pass = 0; pass < 3; ++pass) {
        uint32_t aB = (pass < 2) ? aHi : aLo;
        uint32_t bB = (pass == 1) ? bLo : bHi;
#pragma unroll
        for (int k16 = 0; k16 < 8; ++k16) {
            uint32_t ka = (uint32_t)(k16 * 16 + kA) * 2;
            uint32_t kb = (uint32_t)(k16 * 16 + kB) * 2;
            uint32_t a[2][4];
            ldsm4(a[0], aB + aRow + ka);
            ldsm4(a[1], aB + aRow + 16 * TROW + ka);
            uint32_t b[4][4];
#pragma unroll
            for (int p = 0; p < 4; ++p) ldsm4(b[p], bB + bRow + p * 16 * TROW + kb);
#pragma unroll
            for (int t = 0; t < 2; ++t)
#pragma unroll
                for (int nt = 0; nt < 8; ++nt)
                    mma16816(c[t][nt], a[t], b[nt >> 1][(nt & 1) * 2], b[nt >> 1][(nt & 1) * 2 + 1]);
        }
    }
}

// ---------------- sort-by-dst ----------------
__global__ void zero_count_kernel() {
    int i = blockIdx.x * blockDim.x + threadIdx.x;
    if (i < N_NODES) g_count[i] = 0;
}
__global__ void hist_kernel(const int* __restrict__ ei) {
    int e = blockIdx.x * blockDim.x + threadIdx.x;
    if (e < N_EDGES) atomicAdd(&g_count[ei[N_EDGES + e]], 1);
}
__global__ void scan_kernel() {
    __shared__ int warp_sums[32];
    __shared__ int s_carry;
    int tid = threadIdx.x;
    int lane = tid & 31, wid = tid >> 5;
    if (tid == 0) s_carry = 0;
    __syncthreads();
    for (int base = 0; base < N_NODES; base += 1024) {
        int idx = base + tid;
        int v = (idx < N_NODES) ? g_count[idx] : 0;
        int inc = v;
#pragma unroll
        for (int o = 1; o < 32; o <<= 1) {
            int t = __shfl_up_sync(0xffffffffu, inc, o);
            if (lane >= o) inc += t;
        }
        if (lane == 31) warp_sums[wid] = inc;
        __syncthreads();
        if (wid == 0) {
            int w = warp_sums[lane];
            int wi = w;
#pragma unroll
            for (int o = 1; o < 32; o <<= 1) {
                int t = __shfl_up_sync(0xffffffffu, wi, o);
                if (lane >= o) wi += t;
            }
            warp_sums[lane] = wi - w;
        }
        __syncthreads();
        int ex = inc - v + warp_sums[wid] + s_carry;
        if (idx < N_NODES) g_off2[idx] = ex;
        __syncthreads();
        if (tid == 1023) s_carry = ex + v;
        __syncthreads();
    }
}
__global__ void scatter_kernel(const int* __restrict__ ei) {
    int e = blockIdx.x * blockDim.x + threadIdx.x;
    if (e >= N_EDGES) return;
    int d = ei[N_EDGES + e];
    int pos = atomicAdd(&g_off2[d], 1);
    g_src_s[pos] = ei[e];
    g_dst_s[pos] = d;
    g_perm[pos] = e;
}

// ---------------- builders ----------------
__global__ void build_h_kernel(const float* __restrict__ x, const int* __restrict__ nlu) {
    int gid = blockIdx.x * blockDim.x + threadIdx.x;
    if (gid >= N_NODES * 16) return;
    int n = gid >> 4, j = gid & 15, c0 = j * 8;
    float v[8];
    if (c0 < 96) {
        float4 a = *(const float4*)(x + (size_t)n * 96 + c0);
        float4 b = *(const float4*)(x + (size_t)n * 96 + c0 + 4);
        v[0] = a.x; v[1] = a.y; v[2] = a.z; v[3] = a.w; v[4] = b.x; v[5] = b.y; v[6] = b.z; v[7] = b.w;
    } else {
        int t = nlu[n * 2 + ((c0 - 96) >> 4)];
        int cl = (c0 - 96) & 15;
#pragma unroll
        for (int i = 0; i < 8; ++i) v[i] = pe_val(t, cl + i);
    }
    split_store8(g_himg + (size_t)(n >> 7) * IMGB, (n & 127) * TROW + c0 * 2, v);
}
__global__ void build_eaimg_kernel(const float* __restrict__ eattr, const int* __restrict__ elu) {
    int gid = blockIdx.x * blockDim.x + threadIdx.x;
    if (gid >= N_EDGES * 16) return;
    int p = gid >> 4, j = gid & 15, c0 = j * 8;
    int e = g_perm[p];
    float v[8];
    if (c0 < 96) {
        float4 a = *(const float4*)(eattr + (size_t)e * 96 + c0);
        float4 b = *(const float4*)(eattr + (size_t)e * 96 + c0 + 4);
        v[0] = a.x; v[1] = a.y; v[2] = a.z; v[3] = a.w; v[4] = b.x; v[5] = b.y; v[6] = b.z; v[7] = b.w;
    } else {
        int t = elu[(size_t)e * 2 + ((c0 - 96) >> 4)];
        int cl = (c0 - 96) & 15;
#pragma unroll
        for (int i = 0; i < 8; ++i) v[i] = pe_val(t, cl + i);
    }
    split_store8(g_eaimg + (size_t)(p >> 7) * IMGB, (p & 127) * TROW + c0 * 2, v);
}
__global__ void prep_w_kernel(const float* __restrict__ Wq, const float* __restrict__ Wk,
                              const float* __restrict__ Wv, const float* __restrict__ Ws,
                              const float* __restrict__ We) {
    int gid = blockIdx.x * blockDim.x + threadIdx.x;
    if (gid >= 15 * 2048) return;
    int t = gid >> 11, rem = gid & 2047;
    int n = rem >> 4, j = rem & 15, k0 = j * 8;
    int l = t / 5, m = t % 5;
    const float* W = (m == 0) ? Wq : (m == 1) ? Wk : (m == 2) ? Wv : (m == 3) ? Ws : We;
    const float* base = W + (size_t)l * 16384;
    float v[8];
#pragma unroll
    for (int i = 0; i < 8; ++i) v[i] = base[(size_t)(k0 + i) * 128 + n];
    split_store8(g_wimg + (size_t)t * IMGB, n * TROW + k0 * 2, v);
}

// ---------------- node GEMM (unchanged) ----------------
#define OFF_NB 69632
#define OFF_NBIAS 139264
#define SMEM_NODE 139776
__global__ __launch_bounds__(256, 1)
void node_mma_kernel(const float* __restrict__ bq, const float* __restrict__ bk,
                     const float* __restrict__ bv, const float* __restrict__ bsk, int layer) {
    extern __shared__ __align__(16) unsigned char smem[];
    uint32_t sb = smem_u32(smem);
    int tid = threadIdx.x, wid = tid >> 5, lane = tid & 31;
    int wr = wid & 3, wc = wid >> 2;
    int tile = blockIdx.x, ysel = blockIdx.y;
    int gi = lane >> 2, tig = lane & 3;

    const uint4* aimg = (const uint4*)(g_himg + (size_t)tile * IMGB);
    uint4* sA = (uint4*)smem;
#pragma unroll
    for (int it = 0; it < 17; ++it) sA[it * 256 + tid] = aimg[it * 256 + tid];

    float* biasBuf = (float*)(smem + OFF_NBIAS);
    uint4* sB = (uint4*)(smem + OFF_NB);

    for (int w2 = 0; w2 < 2; ++w2) {
        int w = ysel * 2 + w2;
        __syncthreads();
        const uint4* bimg = (const uint4*)(g_wimg + (size_t)(layer * 5 + w) * IMGB);
#pragma unroll
        for (int it = 0; it < 17; ++it) sB[it * 256 + tid] = bimg[it * 256 + tid];
        if (tid < 128) {
            const float* bias = (w == 0) ? bq : (w == 1) ? bk : (w == 2) ? bv : bsk;
            biasBuf[tid] = bias[layer * 128 + tid];
        }
        __syncthreads();

        float c[2][8][4];
#pragma unroll
        for (int t = 0; t < 2; ++t)
#pragma unroll
            for (int nt = 0; nt < 8; ++nt)
#pragma unroll
                for (int j = 0; j < 4; ++j) c[t][nt][j] = 0.0f;

        gemm3(sb, sb + TBYTES, sb + OFF_NB, sb + OFF_NB + TBYTES, lane, wr, wc, c);

        float* out = (w == 0) ? g_q : (w == 1) ? g_k : (w == 2) ? g_v : g_skip;
#pragma unroll
        for (int t = 0; t < 2; ++t) {
#pragma unroll
            for (int half = 0; half < 2; ++half) {
                int node = tile * 128 + wr * 32 + t * 16 + gi + half * 8;
                if (node < N_NODES) {
                    float* op = out + (size_t)node * 128;
#pragma unroll
                    for (int nt = 0; nt < 8; ++nt) {
                        int col = wc * 64 + nt * 8 + tig * 2;
                        *(float2*)(op + col) = make_float2(c[t][nt][half * 2 + 0] + biasBuf[col],
                                                           c[t][nt][half * 2 + 1] + biasBuf[col + 1]);
                    }
                }
            }
        }
    }
}

// ---------------- edge kernel: producer/consumer warp specialization ----------------
// smem: [0,68K) B resident | [68K,136K) A/est buf0 | [136K,204K) A/est buf1
// barriers: full[b]=2+b (prod arrive, cons sync), free[b]=4+b (cons arrive, prod sync),
//           6 = producer-internal (256)
#define SMEM_EDGE 208896
__global__ __launch_bounds__(512, 1)
void edge_mma_kernel(int layer) {
    extern __shared__ __align__(16) unsigned char smem[];
    uint32_t sb = smem_u32(smem);
    int tid = threadIdx.x, wid = tid >> 5, lane = tid & 31;

    // cooperative resident-B load
    const uint4* bimg = (const uint4*)(g_wimg + (size_t)(layer * 5 + 4) * IMGB);
    uint4* sB = (uint4*)smem;
    for (int i = tid; i < 4352; i += 512) sB[i] = bimg[i];
    __syncthreads();

    if (wid < 8) {
        // ---- producers: A load -> gemm -> est ----
        int wr = wid & 3, wc = wid >> 2;
        int gi = lane >> 2, tig = lane & 3;
        int idx = 0;
        for (int tile = blockIdx.x; tile < N_ETILE; tile += 148, ++idx) {
            int b = idx & 1;
            uint32_t aBuf = sb + 69632 + b * 69632;
            BAR_SYNC(4 + b, 512);            // free[b]: epilogue(t-2) done
            const unsigned char* src = g_eaimg + (size_t)tile * IMGB;
            for (int i = tid; i < 4352; i += 256)
                cp_async16(aBuf + i * 16, src + (size_t)i * 16);
            CP_COMMIT();
            CP_WAIT0();
            BAR_SYNC(6, 256);                // all producers' A stores visible

            float c[2][8][4];
#pragma unroll
            for (int t = 0; t < 2; ++t)
#pragma unroll
                for (int nt = 0; nt < 8; ++nt)
#pragma unroll
                    for (int j = 0; j < 4; ++j) c[t][nt][j] = 0.0f;

            gemm3(aBuf, aBuf + TBYTES, sb, sb + TBYTES, lane, wr, wc, c);

            BAR_SYNC(6, 256);                // all gemm A reads done before est overlay
            float* est = (float*)(smem + 69632 + b * 69632);
#pragma unroll
            for (int t = 0; t < 2; ++t)
#pragma unroll
                for (int half = 0; half < 2; ++half) {
                    int r = wr * 32 + t * 16 + gi + half * 8;
#pragma unroll
                    for (int nt = 0; nt < 8; ++nt) {
                        int col = wc * 64 + nt * 8 + tig * 2;
                        *(float2*)(est + r * 132 + col) = make_float2(c[t][nt][half * 2], c[t][nt][half * 2 + 1]);
                    }
                }
            BAR_ARRIVE(2 + b, 512);          // full[b]
        }
    } else {
        // ---- consumers: gather/softmax/atomics ----
        int gtid = tid & 255;
        int tx = gtid & 15, ty = gtid >> 4;
        int hd = tx >> 1, cb = tx << 3;
        BAR_ARRIVE(4, 512);                  // pre-arm free[0]
        BAR_ARRIVE(5, 512);                  // pre-arm free[1]
        int idx = 0;
        for (int tile = blockIdx.x; tile < N_ETILE; tile += 148, ++idx) {
            int b = idx & 1;
            BAR_SYNC(2 + b, 512);            // full[b]
            const float* est = (const float*)(smem + 69632 + b * 69632);
            int e0 = tile << 7;

            int cur_d = -1;
            float4 q0, q1;
            float aN0 = 0.f, aN1 = 0.f, aN2 = 0.f, aN3 = 0.f;
            float aN4 = 0.f, aN5 = 0.f, aN6 = 0.f, aN7 = 0.f;
            float aD = 0.f;
#pragma unroll
            for (int i = 0; i < 8; ++i) {
                int er = ty * 8 + i;
                float4 e0v = *(const float4*)(est + er * 132 + cb);
                float4 e1v = *(const float4*)(est + er * 132 + cb + 4);
                float e8[8] = {e0v.x, e0v.y, e0v.z, e0v.w, e1v.x, e1v.y, e1v.z, e1v.w};
                int s = g_src_s[e0 + er];
                int d = g_dst_s[e0 + er];
                if (d != cur_d) {
                    if (cur_d >= 0) {
                        float* np = g_numer + (size_t)cur_d * 128 + cb;
                        red_add4(np,     aN0, aN1, aN2, aN3);
                        red_add4(np + 4, aN4, aN5, aN6, aN7);
                        if (!(tx & 1)) atomicAdd(g_denom + (size_t)cur_d * 8 + hd, aD);
                    }
                    cur_d = d;
                    aN0 = aN1 = aN2 = aN3 = aN4 = aN5 = aN6 = aN7 = 0.f;
                    aD = 0.f;
                    const float* qp = g_q + (size_t)d * 128 + cb;
                    q0 = *(const float4*)qp;
                    q1 = *(const float4*)(qp + 4);
                }
                const float* kp = g_k + (size_t)s * 128 + cb;
                float4 k0 = *(const float4*)kp, k1 = *(const float4*)(kp + 4);
                float part = q0.x * (k0.x + e8[0]) + q0.y * (k0.y + e8[1])
                           + q0.z * (k0.z + e8[2]) + q0.w * (k0.w + e8[3])
                           + q1.x * (k1.x + e8[4]) + q1.y * (k1.y + e8[5])
                           + q1.z * (k1.z + e8[6]) + q1.w * (k1.w + e8[7]);
                float full = part + __shfl_xor_sync(0xffffffffu, part, 1);
                float p = __expf(full * 0.25f);  // shift-free softmax (alpha is O(1))
                const float* vp = g_v + (size_t)s * 128 + cb;
                float4 v0 = *(const float4*)vp, v1 = *(const float4*)(vp + 4);
                aN0 += p * (v0.x + e8[0]); aN1 += p * (v0.y + e8[1]);
                aN2 += p * (v0.z + e8[2]); aN3 += p * (v0.w + e8[3]);
                aN4 += p * (v1.x + e8[4]); aN5 += p * (v1.y + e8[5]);
                aN6 += p * (v1.z + e8[6]); aN7 += p * (v1.w + e8[7]);
                aD += p;
            }
            {
                float* np = g_numer + (size_t)cur_d * 128 + cb;
                red_add4(np,     aN0, aN1, aN2, aN3);
                red_add4(np + 4, aN4, aN5, aN6, aN7);
                if (!(tx & 1)) atomicAdd(g_denom + (size_t)cur_d * 8 + hd, aD);
            }
            BAR_ARRIVE(4 + b, 512);          // free[b]
        }
    }
}

// ---------------- node update ----------------
__global__ void update_h_kernel() {
    int gid = blockIdx.x * blockDim.x + threadIdx.x;
    if (gid >= N_NODES * 16) return;
    int n = gid >> 4, j = gid & 15, c0 = j * 8;
    float inv = 1.0f / (g_denom[n * 8 + (c0 >> 4)] + 1e-16f);
    float4 n0 = *(const float4*)(g_numer + (size_t)n * 128 + c0);
    float4 n1 = *(const float4*)(g_numer + (size_t)n * 128 + c0 + 4);
    float4 s0 = *(const float4*)(g_skip + (size_t)n * 128 + c0);
    float4 s1 = *(const float4*)(g_skip + (size_t)n * 128 + c0 + 4);
    float v[8];
    v[0] = fmaxf(n0.x * inv + s0.x, 0.f); v[1] = fmaxf(n0.y * inv + s0.y, 0.f);
    v[2] = fmaxf(n0.z * inv + s0.z, 0.f); v[3] = fmaxf(n0.w * inv + s0.w, 0.f);
    v[4] = fmaxf(n1.x * inv + s1.x, 0.f); v[5] = fmaxf(n1.y * inv + s1.y, 0.f);
    v[6] = fmaxf(n1.z * inv + s1.z, 0.f); v[7] = fmaxf(n1.w * inv + s1.w, 0.f);
    *(float4*)(g_h + (size_t)n * 128 + c0)     = make_float4(v[0], v[1], v[2], v[3]);
    *(float4*)(g_h + (size_t)n * 128 + c0 + 4) = make_float4(v[4], v[5], v[6], v[7]);
    split_store8(g_himg + (size_t)(n >> 7) * IMGB, (n & 127) * TROW + c0 * 2, v);
    float4 z = make_float4(0.f, 0.f, 0.f, 0.f);
    *(float4*)(g_numer + (size_t)n * 128 + c0)     = z;
    *(float4*)(g_numer + (size_t)n * 128 + c0 + 4) = z;
    if (!(j & 1)) g_denom[n * 8 + (j >> 1)] = 0.0f;
}

// ---------------- output GEMM ----------------
__global__ void out_gemm_kernel(const float* __restrict__ Wout, const float* __restrict__ bout,
                                float* __restrict__ out) {
    __shared__ float ws[128 * 16];
    __shared__ float hs[16 * 128];
    int tid = threadIdx.x;
    int row0 = blockIdx.x * 16;
#pragma unroll
    for (int it = 0; it < 8; ++it) {
        int idx = it * 256 + tid;
        ws[idx] = Wout[idx];
        int r = row0 + (idx >> 7);
        hs[idx] = (r < N_NODES) ? g_h[(size_t)row0 * 128 + idx] : 0.0f;
    }
    __syncthreads();
    int r = tid >> 4, c = tid & 15;
    float s = bout[c];
#pragma unroll 8
    for (int k = 0; k < 128; ++k) s += hs[r * 128 + k] * ws[k * 16 + c];
    int gr = row0 + r;
    if (gr < N_NODES) out[(size_t)gr * 16 + c] = s;
}

// ---------------- host ----------------
extern "C" void kernel_launch(void* const* d_in, const int* in_sizes, int n_in,
                              void* d_out, int out_size) {
    const float* x     = (const float*)d_in[0];
    const int*   nlu   = (const int*)  d_in[1];
    const int*   ei    = (const int*)  d_in[2];
    const float* eattr = (const float*)d_in[3];
    const int*   elu   = (const int*)  d_in[4];
    const float* Wq    = (const float*)d_in[5];
    const float* bq    = (const float*)d_in[6];
    const float* Wk    = (const float*)d_in[7];
    const float* bk    = (const float*)d_in[8];
    const float* Wv    = (const float*)d_in[9];
    const float* bv    = (const float*)d_in[10];
    const float* We    = (const float*)d_in[11];
    const float* Ws    = (const float*)d_in[12];
    const float* bs    = (const float*)d_in[13];
    const float* Wout  = (const float*)d_in[14];
    const float* bout  = (const float*)d_in[15];
    float* out = (float*)d_out;
    (void)in_sizes; (void)n_in; (void)out_size;

    cudaFuncSetAttribute(node_mma_kernel, cudaFuncAttributeMaxDynamicSharedMemorySize, SMEM_NODE);
    cudaFuncSetAttribute(edge_mma_kernel, cudaFuncAttributeMaxDynamicSharedMemorySize, SMEM_EDGE);

    zero_count_kernel<<<(N_NODES + 255) / 256, 256>>>();
    hist_kernel<<<(N_EDGES + 255) / 256, 256>>>(ei);
    scan_kernel<<<1, 1024>>>();
    scatter_kernel<<<(N_EDGES + 255) / 256, 256>>>(ei);

    build_h_kernel    <<<(N_NODES * 16 + 255) / 256, 256>>>(x, nlu);
    build_eaimg_kernel<<<(N_EDGES * 16 + 255) / 256, 256>>>(eattr, elu);
    prep_w_kernel     <<<(15 * 2048 + 255) / 256, 256>>>(Wq, Wk, Wv, Ws, We);

    for (int l = 0; l < 3; ++l) {
        node_mma_kernel<<<dim3(N_NTILE, 2), 256, SMEM_NODE>>>(bq, bk, bv, bs, l);
        edge_mma_kernel<<<148, 512, SMEM_EDGE>>>(l);
        update_h_kernel<<<(N_NODES * 16 + 255) / 256, 256>>>();
    }
    out_gemm_kernel<<<N_NODES / 16, 256>>>(Wout, bout, out);
}

// round 12
// speedup vs baseline: 1.2953x; 1.2595x over previous
#include <cuda_runtime.h>
#include <cuda_fp16.h>
#include <math.h>
#include <stdint.h>

#define N_NODES 100000
#define N_EDGES 800000
#define N_NTILE 782
#define N_ETILE 6250

// fp16 tile image: 128 rows x 136 fp16 (272B stride)
#define TROW 272
#define TBYTES 34816          // one fp16 tile (A images: single; B images: hi at 0, lo at +TBYTES)
#define BIMGB 69632

// ---------------- device scratch ----------------
__device__ float g_h[(size_t)N_NODES * 128];
__device__ float g_q[(size_t)N_NODES * 128];
__device__ float g_k[(size_t)N_NODES * 128];
__device__ float g_v[(size_t)N_NODES * 128];
__device__ float g_skip[(size_t)N_NODES * 128];
__device__ float g_numer[(size_t)N_NODES * 128];
__device__ float g_denom[(size_t)N_NODES * 8];
__device__ unsigned char g_himg[(size_t)N_NTILE * TBYTES];    // h: single fp16
__device__ unsigned char g_eaimg[(size_t)N_ETILE * TBYTES];   // ea: single fp16
__device__ unsigned char g_wimg[(size_t)15 * BIMGB];          // W: dual fp16 (hi+lo)
// sort scratch
__device__ int g_count[N_NODES];
__device__ int g_off2[N_NODES];
__device__ int g_src_s[N_EDGES];
__device__ int g_dst_s[N_EDGES];
__device__ int g_perm[N_EDGES];

// ---------------- PTX helpers ----------------
__device__ __forceinline__ uint32_t smem_u32(const void* p) {
    uint32_t a;
    asm("{ .reg .u64 t; cvta.to.shared.u64 t, %1; cvt.u32.u64 %0, t; }" : "=r"(a) : "l"(p));
    return a;
}
__device__ __forceinline__ void ldsm4(uint32_t* r, uint32_t addr) {
    asm volatile("ldmatrix.sync.aligned.m8n8.x4.shared.b16 {%0,%1,%2,%3}, [%4];"
                 : "=r"(r[0]), "=r"(r[1]), "=r"(r[2]), "=r"(r[3]) : "r"(addr));
}
__device__ __forceinline__ void mma16816h(float* c, const uint32_t* a, uint32_t b0, uint32_t b1) {
    asm volatile("mma.sync.aligned.m16n8k16.row.col.f32.f16.f16.f32 "
                 "{%0,%1,%2,%3}, {%4,%5,%6,%7}, {%8,%9}, {%0,%1,%2,%3};"
                 : "+f"(c[0]), "+f"(c[1]), "+f"(c[2]), "+f"(c[3])
                 : "r"(a[0]), "r"(a[1]), "r"(a[2]), "r"(a[3]), "r"(b0), "r"(b1));
}
__device__ __forceinline__ void red_add4(float* addr, float a, float b, float c, float d) {
    asm volatile("red.global.add.v4.f32 [%0], {%1, %2, %3, %4};"
                 :: "l"(addr), "f"(a), "f"(b), "f"(c), "f"(d) : "memory");
}
__device__ __forceinline__ void cp_async16(uint32_t dst, const void* src) {
    asm volatile("cp.async.cg.shared.global [%0], [%1], 16;" :: "r"(dst), "l"(src));
}
#define CP_COMMIT() asm volatile("cp.async.commit_group;" ::: "memory")
#define CP_WAIT0()  asm volatile("cp.async.wait_group 0;" ::: "memory")
#define BAR_SYNC(id, n)   asm volatile("bar.sync %0, %1;"   :: "r"(id), "r"(n) : "memory")
#define BAR_ARRIVE(id, n) asm volatile("bar.arrive %0, %1;" :: "r"(id), "r"(n) : "memory")

__device__ __forceinline__ float pe_val(int t, int c) {
    int j = c >> 1;
    float freq = expf(-logf(10000.0f) * (float)(2 * j) * (1.0f / 16.0f));
    float ang = (float)t * freq;
    return (c & 1) ? cosf(ang) : sinf(ang);
}
// 8 floats -> 8 fp16 (16B) at img+off
__device__ __forceinline__ void store8_h16(unsigned char* img, int off, const float* v) {
    unsigned int h[4];
#pragma unroll
    for (int i = 0; i < 4; ++i) {
        __half h0 = __float2half_rn(v[2 * i]);
        __half h1 = __float2half_rn(v[2 * i + 1]);
        h[i] = (unsigned int)__half_as_ushort(h0) | ((unsigned int)__half_as_ushort(h1) << 16);
    }
    *(uint4*)(img + off) = make_uint4(h[0], h[1], h[2], h[3]);
}
// 8 floats -> fp16 hi at off, fp16 lo residual at off+TBYTES
__device__ __forceinline__ void store8_h16dual(unsigned char* img, int off, const float* v) {
    unsigned int h[4], l[4];
#pragma unroll
    for (int i = 0; i < 4; ++i) {
        __half h0 = __float2half_rn(v[2 * i]);
        __half h1 = __float2half_rn(v[2 * i + 1]);
        __half l0 = __float2half_rn(v[2 * i] - __half2float(h0));
        __half l1 = __float2half_rn(v[2 * i + 1] - __half2float(h1));
        h[i] = (unsigned int)__half_as_ushort(h0) | ((unsigned int)__half_as_ushort(h1) << 16);
        l[i] = (unsigned int)__half_as_ushort(l0) | ((unsigned int)__half_as_ushort(l1) << 16);
    }
    *(uint4*)(img + off) = make_uint4(h[0], h[1], h[2], h[3]);
    *(uint4*)(img + TBYTES + off) = make_uint4(l[0], l[1], l[2], l[3]);
}

// 2-pass fp16 GEMM (A single, B hi+lo), 8-warp layout: warp (wr,wc) -> C[wr*32..+32][wc*64..+64]
__device__ __forceinline__ void gemm2(uint32_t aBase, uint32_t bHi, uint32_t bLo,
                                      int lane, int wr, int wc, float c[2][8][4]) {
    int rA = lane & 15;
    int kA = (lane >> 4) << 3;
    int rB = ((lane >> 4) << 3) + (lane & 7);
    int kB = ((lane >> 3) & 1) << 3;
    uint32_t aRow = (uint32_t)(wr * 32 + rA) * TROW;
    uint32_t bRow = (uint32_t)(wc * 64 + rB) * TROW;
    for (int pass = 0; pass < 2; ++pass) {
        uint32_t bB = pass ? bLo : bHi;
#pragma unroll
        for (int k16 = 0; k16 < 8; ++k16) {
            uint32_t ka = (uint32_t)(k16 * 16 + kA) * 2;
            uint32_t kb = (uint32_t)(k16 * 16 + kB) * 2;
            uint32_t a[2][4];
            ldsm4(a[0], aBase + aRow + ka);
            ldsm4(a[1], aBase + aRow + 16 * TROW + ka);
            uint32_t b[4][4];
#pragma unroll
            for (int p = 0; p < 4; ++p) ldsm4(b[p], bB + bRow + p * 16 * TROW + kb);
#pragma unroll
            for (int t = 0; t < 2; ++t)
#pragma unroll
                for (int nt = 0; nt < 8; ++nt)
                    mma16816h(c[t][nt], a[t], b[nt >> 1][(nt & 1) * 2], b[nt >> 1][(nt & 1) * 2 + 1]);
        }
    }
}

// ---------------- sort-by-dst ----------------
__global__ void zero_count_kernel() {
    int i = blockIdx.x * blockDim.x + threadIdx.x;
    if (i < N_NODES) g_count[i] = 0;
}
__global__ void hist_kernel(const int* __restrict__ ei) {
    int e = blockIdx.x * blockDim.x + threadIdx.x;
    if (e < N_EDGES) atomicAdd(&g_count[ei[N_EDGES + e]], 1);
}
__global__ void scan_kernel() {
    __shared__ int warp_sums[32];
    __shared__ int s_carry;
    int tid = threadIdx.x;
    int lane = tid & 31, wid = tid >> 5;
    if (tid == 0) s_carry = 0;
    __syncthreads();
    for (int base = 0; base < N_NODES; base += 1024) {
        int idx = base + tid;
        int v = (idx < N_NODES) ? g_count[idx] : 0;
        int inc = v;
#pragma unroll
        for (int o = 1; o < 32; o <<= 1) {
            int t = __shfl_up_sync(0xffffffffu, inc, o);
            if (lane >= o) inc += t;
        }
        if (lane == 31) warp_sums[wid] = inc;
        __syncthreads();
        if (wid == 0) {
            int w = warp_sums[lane];
            int wi = w;
#pragma unroll
            for (int o = 1; o < 32; o <<= 1) {
                int t = __shfl_up_sync(0xffffffffu, wi, o);
                if (lane >= o) wi += t;
            }
            warp_sums[lane] = wi - w;
        }
        __syncthreads();
        int ex = inc - v + warp_sums[wid] + s_carry;
        if (idx < N_NODES) g_off2[idx] = ex;
        __syncthreads();
        if (tid == 1023) s_carry = ex + v;
        __syncthreads();
    }
}
__global__ void scatter_kernel(const int* __restrict__ ei) {
    int e = blockIdx.x * blockDim.x + threadIdx.x;
    if (e >= N_EDGES) return;
    int d = ei[N_EDGES + e];
    int pos = atomicAdd(&g_off2[d], 1);
    g_src_s[pos] = ei[e];
    g_dst_s[pos] = d;
    g_perm[pos] = e;
}

// ---------------- builders ----------------
__global__ void build_h_kernel(const float* __restrict__ x, const int* __restrict__ nlu) {
    int gid = blockIdx.x * blockDim.x + threadIdx.x;
    if (gid >= N_NODES * 16) return;
    int n = gid >> 4, j = gid & 15, c0 = j * 8;
    float v[8];
    if (c0 < 96) {
        float4 a = *(const float4*)(x + (size_t)n * 96 + c0);
        float4 b = *(const float4*)(x + (size_t)n * 96 + c0 + 4);
        v[0] = a.x; v[1] = a.y; v[2] = a.z; v[3] = a.w; v[4] = b.x; v[5] = b.y; v[6] = b.z; v[7] = b.w;
    } else {
        int t = nlu[n * 2 + ((c0 - 96) >> 4)];
        int cl = (c0 - 96) & 15;
#pragma unroll
        for (int i = 0; i < 8; ++i) v[i] = pe_val(t, cl + i);
    }
    store8_h16(g_himg + (size_t)(n >> 7) * TBYTES, (n & 127) * TROW + c0 * 2, v);
}
__global__ void build_eaimg_kernel(const float* __restrict__ eattr, const int* __restrict__ elu) {
    int gid = blockIdx.x * blockDim.x + threadIdx.x;
    if (gid >= N_EDGES * 16) return;
    int p = gid >> 4, j = gid & 15, c0 = j * 8;
    int e = g_perm[p];
    float v[8];
    if (c0 < 96) {
        float4 a = *(const float4*)(eattr + (size_t)e * 96 + c0);
        float4 b = *(const float4*)(eattr + (size_t)e * 96 + c0 + 4);
        v[0] = a.x; v[1] = a.y; v[2] = a.z; v[3] = a.w; v[4] = b.x; v[5] = b.y; v[6] = b.z; v[7] = b.w;
    } else {
        int t = elu[(size_t)e * 2 + ((c0 - 96) >> 4)];
        int cl = (c0 - 96) & 15;
#pragma unroll
        for (int i = 0; i < 8; ++i) v[i] = pe_val(t, cl + i);
    }
    store8_h16(g_eaimg + (size_t)(p >> 7) * TBYTES, (p & 127) * TROW + c0 * 2, v);
}
__global__ void prep_w_kernel(const float* __restrict__ Wq, const float* __restrict__ Wk,
                              const float* __restrict__ Wv, const float* __restrict__ Ws,
                              const float* __restrict__ We) {
    int gid = blockIdx.x * blockDim.x + threadIdx.x;
    if (gid >= 15 * 2048) return;
    int t = gid >> 11, rem = gid & 2047;
    int n = rem >> 4, j = rem & 15, k0 = j * 8;
    int l = t / 5, m = t % 5;
    const float* W = (m == 0) ? Wq : (m == 1) ? Wk : (m == 2) ? Wv : (m == 3) ? Ws : We;
    const float* base = W + (size_t)l * 16384;
    float v[8];
#pragma unroll
    for (int i = 0; i < 8; ++i) v[i] = base[(size_t)(k0 + i) * 128 + n];
    store8_h16dual(g_wimg + (size_t)t * BIMGB, n * TROW + k0 * 2, v);
}

// ---------------- node GEMM: A single fp16 + B dual fp16, 2 GEMMs per block ----------------
#define OFF_NB 34816
#define OFF_NBIAS 104448
#define SMEM_NODE 104960
__global__ __launch_bounds__(256)
void node_mma_kernel(const float* __restrict__ bq, const float* __restrict__ bk,
                     const float* __restrict__ bv, const float* __restrict__ bsk, int layer) {
    extern __shared__ __align__(16) unsigned char smem[];
    uint32_t sb = smem_u32(smem);
    int tid = threadIdx.x, wid = tid >> 5, lane = tid & 31;
    int wr = wid & 3, wc = wid >> 2;
    int tile = blockIdx.x, ysel = blockIdx.y;
    int gi = lane >> 2, tig = lane & 3;

    const uint4* aimg = (const uint4*)(g_himg + (size_t)tile * TBYTES);
    uint4* sA = (uint4*)smem;
    for (int i = tid; i < 2176; i += 256) sA[i] = aimg[i];

    float* biasBuf = (float*)(smem + OFF_NBIAS);
    uint4* sB = (uint4*)(smem + OFF_NB);

    for (int w2 = 0; w2 < 2; ++w2) {
        int w = ysel * 2 + w2;
        __syncthreads();
        const uint4* bimg = (const uint4*)(g_wimg + (size_t)(layer * 5 + w) * BIMGB);
        for (int i = tid; i < 4352; i += 256) sB[i] = bimg[i];
        if (tid < 128) {
            const float* bias = (w == 0) ? bq : (w == 1) ? bk : (w == 2) ? bv : bsk;
            biasBuf[tid] = bias[layer * 128 + tid];
        }
        __syncthreads();

        float c[2][8][4];
#pragma unroll
        for (int t = 0; t < 2; ++t)
#pragma unroll
            for (int nt = 0; nt < 8; ++nt)
#pragma unroll
                for (int j = 0; j < 4; ++j) c[t][nt][j] = 0.0f;

        gemm2(sb, sb + OFF_NB, sb + OFF_NB + TBYTES, lane, wr, wc, c);

        float* out = (w == 0) ? g_q : (w == 1) ? g_k : (w == 2) ? g_v : g_skip;
#pragma unroll
        for (int t = 0; t < 2; ++t) {
#pragma unroll
            for (int half = 0; half < 2; ++half) {
                int node = tile * 128 + wr * 32 + t * 16 + gi + half * 8;
                if (node < N_NODES) {
                    float* op = out + (size_t)node * 128;
#pragma unroll
                    for (int nt = 0; nt < 8; ++nt) {
                        int col = wc * 64 + nt * 8 + tig * 2;
                        *(float2*)(op + col) = make_float2(c[t][nt][half * 2 + 0] + biasBuf[col],
                                                           c[t][nt][half * 2 + 1] + biasBuf[col + 1]);
                    }
                }
            }
        }
    }
}

// ---------------- edge kernel: producer/consumer warp specialization ----------------
// smem: [0,68K) B dual resident | [68K,136K) buf0 (A 34K + est overlay 68K) | [136K,204K) buf1
// barriers: full[b]=2+b, free[b]=4+b, 6 = producer-internal
#define SMEM_EDGE 208896
__global__ __launch_bounds__(512)
void edge_mma_kernel(int layer) {
    extern __shared__ __align__(16) unsigned char smem[];
    uint32_t sb = smem_u32(smem);
    int tid = threadIdx.x, wid = tid >> 5, lane = tid & 31;

    const uint4* bimg = (const uint4*)(g_wimg + (size_t)(layer * 5 + 4) * BIMGB);
    uint4* sB = (uint4*)smem;
    for (int i = tid; i < 4352; i += 512) sB[i] = bimg[i];
    __syncthreads();

    if (wid < 8) {
        // ---- producers: A load -> gemm -> est ----
        int wr = wid & 3, wc = wid >> 2;
        int gi = lane >> 2, tig = lane & 3;
        int idx = 0;
        for (int tile = blockIdx.x; tile < N_ETILE; tile += 148, ++idx) {
            int b = idx & 1;
            uint32_t aBuf = sb + 69632 + b * 69632;
            BAR_SYNC(4 + b, 512);
            const unsigned char* src = g_eaimg + (size_t)tile * TBYTES;
            for (int i = tid; i < 2176; i += 256)
                cp_async16(aBuf + i * 16, src + (size_t)i * 16);
            CP_COMMIT();
            CP_WAIT0();
            BAR_SYNC(6, 256);

            float c[2][8][4];
#pragma unroll
            for (int t = 0; t < 2; ++t)
#pragma unroll
                for (int nt = 0; nt < 8; ++nt)
#pragma unroll
                    for (int j = 0; j < 4; ++j) c[t][nt][j] = 0.0f;

            gemm2(aBuf, sb, sb + TBYTES, lane, wr, wc, c);

            BAR_SYNC(6, 256);
            float* est = (float*)(smem + 69632 + b * 69632);
#pragma unroll
            for (int t = 0; t < 2; ++t)
#pragma unroll
                for (int half = 0; half < 2; ++half) {
                    int r = wr * 32 + t * 16 + gi + half * 8;
#pragma unroll
                    for (int nt = 0; nt < 8; ++nt) {
                        int col = wc * 64 + nt * 8 + tig * 2;
                        *(float2*)(est + r * 132 + col) = make_float2(c[t][nt][half * 2], c[t][nt][half * 2 + 1]);
                    }
                }
            BAR_ARRIVE(2 + b, 512);
        }
    } else {
        // ---- consumers: gather/softmax/atomics ----
        int gtid = tid & 255;
        int tx = gtid & 15, ty = gtid >> 4;
        int hd = tx >> 1, cb = tx << 3;
        BAR_ARRIVE(4, 512);
        BAR_ARRIVE(5, 512);
        int idx = 0;
        for (int tile = blockIdx.x; tile < N_ETILE; tile += 148, ++idx) {
            int b = idx & 1;
            BAR_SYNC(2 + b, 512);
            const float* est = (const float*)(smem + 69632 + b * 69632);
            int e0 = tile << 7;

            int cur_d = -1;
            float4 q0, q1;
            float aN0 = 0.f, aN1 = 0.f, aN2 = 0.f, aN3 = 0.f;
            float aN4 = 0.f, aN5 = 0.f, aN6 = 0.f, aN7 = 0.f;
            float aD = 0.f;
#pragma unroll
            for (int i = 0; i < 8; ++i) {
                int er = ty * 8 + i;
                float4 e0v = *(const float4*)(est + er * 132 + cb);
                float4 e1v = *(const float4*)(est + er * 132 + cb + 4);
                float e8[8] = {e0v.x, e0v.y, e0v.z, e0v.w, e1v.x, e1v.y, e1v.z, e1v.w};
                int s = g_src_s[e0 + er];
                int d = g_dst_s[e0 + er];
                if (d != cur_d) {
                    if (cur_d >= 0) {
                        float* np = g_numer + (size_t)cur_d * 128 + cb;
                        red_add4(np,     aN0, aN1, aN2, aN3);
                        red_add4(np + 4, aN4, aN5, aN6, aN7);
                        if (!(tx & 1)) atomicAdd(g_denom + (size_t)cur_d * 8 + hd, aD);
                    }
                    cur_d = d;
                    aN0 = aN1 = aN2 = aN3 = aN4 = aN5 = aN6 = aN7 = 0.f;
                    aD = 0.f;
                    const float* qp = g_q + (size_t)d * 128 + cb;
                    q0 = *(const float4*)qp;
                    q1 = *(const float4*)(qp + 4);
                }
                const float* kp = g_k + (size_t)s * 128 + cb;
                float4 k0 = *(const float4*)kp, k1 = *(const float4*)(kp + 4);
                float part = q0.x * (k0.x + e8[0]) + q0.y * (k0.y + e8[1])
                           + q0.z * (k0.z + e8[2]) + q0.w * (k0.w + e8[3])
                           + q1.x * (k1.x + e8[4]) + q1.y * (k1.y + e8[5])
                           + q1.z * (k1.z + e8[6]) + q1.w * (k1.w + e8[7]);
                float full = part + __shfl_xor_sync(0xffffffffu, part, 1);
                float p = __expf(full * 0.25f);  // shift-free softmax (alpha is O(1))
                const float* vp = g_v + (size_t)s * 128 + cb;
                float4 v0 = *(const float4*)vp, v1 = *(const float4*)(vp + 4);
                aN0 += p * (v0.x + e8[0]); aN1 += p * (v0.y + e8[1]);
                aN2 += p * (v0.z + e8[2]); aN3 += p * (v0.w + e8[3]);
                aN4 += p * (v1.x + e8[4]); aN5 += p * (v1.y + e8[5]);
                aN6 += p * (v1.z + e8[6]); aN7 += p * (v1.w + e8[7]);
                aD += p;
            }
            {
                float* np = g_numer + (size_t)cur_d * 128 + cb;
                red_add4(np,     aN0, aN1, aN2, aN3);
                red_add4(np + 4, aN4, aN5, aN6, aN7);
                if (!(tx & 1)) atomicAdd(g_denom + (size_t)cur_d * 8 + hd, aD);
            }
            BAR_ARRIVE(4 + b, 512);
        }
    }
}

// ---------------- node update ----------------
__global__ void update_h_kernel() {
    int gid = blockIdx.x * blockDim.x + threadIdx.x;
    if (gid >= N_NODES * 16) return;
    int n = gid >> 4, j = gid & 15, c0 = j * 8;
    float inv = 1.0f / (g_denom[n * 8 + (c0 >> 4)] + 1e-16f);
    float4 n0 = *(const float4*)(g_numer + (size_t)n * 128 + c0);
    float4 n1 = *(const float4*)(g_numer + (size_t)n * 128 + c0 + 4);
    float4 s0 = *(const float4*)(g_skip + (size_t)n * 128 + c0);
    float4 s1 = *(const float4*)(g_skip + (size_t)n * 128 + c0 + 4);
    float v[8];
    v[0] = fmaxf(n0.x * inv + s0.x, 0.f); v[1] = fmaxf(n0.y * inv + s0.y, 0.f);
    v[2] = fmaxf(n0.z * inv + s0.z, 0.f); v[3] = fmaxf(n0.w * inv + s0.w, 0.f);
    v[4] = fmaxf(n1.x * inv + s1.x, 0.f); v[5] = fmaxf(n1.y * inv + s1.y, 0.f);
    v[6] = fmaxf(n1.z * inv + s1.z, 0.f); v[7] = fmaxf(n1.w * inv + s1.w, 0.f);
    *(float4*)(g_h + (size_t)n * 128 + c0)     = make_float4(v[0], v[1], v[2], v[3]);
    *(float4*)(g_h + (size_t)n * 128 + c0 + 4) = make_float4(v[4], v[5], v[6], v[7]);
    store8_h16(g_himg + (size_t)(n >> 7) * TBYTES, (n & 127) * TROW + c0 * 2, v);
    float4 z = make_float4(0.f, 0.f, 0.f, 0.f);
    *(float4*)(g_numer + (size_t)n * 128 + c0)     = z;
    *(float4*)(g_numer + (size_t)n * 128 + c0 + 4) = z;
    if (!(j & 1)) g_denom[n * 8 + (j >> 1)] = 0.0f;
}

// ---------------- output GEMM ----------------
__global__ void out_gemm_kernel(const float* __restrict__ Wout, const float* __restrict__ bout,
                                float* __restrict__ out) {
    __shared__ float ws[128 * 16];
    __shared__ float hs[16 * 128];
    int tid = threadIdx.x;
    int row0 = blockIdx.x * 16;
#pragma unroll
    for (int it = 0; it < 8; ++it) {
        int idx = it * 256 + tid;
        ws[idx] = Wout[idx];
        int r = row0 + (idx >> 7);
        hs[idx] = (r < N_NODES) ? g_h[(size_t)row0 * 128 + idx] : 0.0f;
    }
    __syncthreads();
    int r = tid >> 4, c = tid & 15;
    float s = bout[c];
#pragma unroll 8
    for (int k = 0; k < 128; ++k) s += hs[r * 128 + k] * ws[k * 16 + c];
    int gr = row0 + r;
    if (gr < N_NODES) out[(size_t)gr * 16 + c] = s;
}

// ---------------- host ----------------
extern "C" void kernel_launch(void* const* d_in, const int* in_sizes, int n_in,
                              void* d_out, int out_size) {
    const float* x     = (const float*)d_in[0];
    const int*   nlu   = (const int*)  d_in[1];
    const int*   ei    = (const int*)  d_in[2];
    const float* eattr = (const float*)d_in[3];
    const int*   elu   = (const int*)  d_in[4];
    const float* Wq    = (const float*)d_in[5];
    const float* bq    = (const float*)d_in[6];
    const float* Wk    = (const float*)d_in[7];
    const float* bk    = (const float*)d_in[8];
    const float* Wv    = (const float*)d_in[9];
    const float* bv    = (const float*)d_in[10];
    const float* We    = (const float*)d_in[11];
    const float* Ws    = (const float*)d_in[12];
    const float* bs    = (const float*)d_in[13];
    const float* Wout  = (const float*)d_in[14];
    const float* bout  = (const float*)d_in[15];
    float* out = (float*)d_out;
    (void)in_sizes; (void)n_in; (void)out_size;

    cudaFuncSetAttribute(node_mma_kernel, cudaFuncAttributeMaxDynamicSharedMemorySize, SMEM_NODE);
    cudaFuncSetAttribute(edge_mma_kernel, cudaFuncAttributeMaxDynamicSharedMemorySize, SMEM_EDGE);

    zero_count_kernel<<<(N_NODES + 255) / 256, 256>>>();
    hist_kernel<<<(N_EDGES + 255) / 256, 256>>>(ei);
    scan_kernel<<<1, 1024>>>();
    scatter_kernel<<<(N_EDGES + 255) / 256, 256>>>(ei);

    build_h_kernel    <<<(N_NODES * 16 + 255) / 256, 256>>>(x, nlu);
    build_eaimg_kernel<<<(N_EDGES * 16 + 255) / 256, 256>>>(eattr, elu);
    prep_w_kernel     <<<(15 * 2048 + 255) / 256, 256>>>(Wq, Wk, Wv, Ws, We);

    for (int l = 0; l < 3; ++l) {
        node_mma_kernel<<<dim3(N_NTILE, 2), 256, SMEM_NODE>>>(bq, bk, bv, bs, l);
        edge_mma_kernel<<<148, 512, SMEM_EDGE>>>(l);
        update_h_kernel<<<(N_NODES * 16 + 255) / 256, 256>>>();
    }
    out_gemm_kernel<<<N_NODES / 16, 256>>>(Wout, bout, out);
}

// round 13
// speedup vs baseline: 1.5127x; 1.1678x over previous
#include <cuda_runtime.h>
#include <cuda_fp16.h>
#include <math.h>
#include <stdint.h>

#define N_NODES 100000
#define N_EDGES 800000
#define N_NTILE 782
#define N_ETILE 6250

// fp16 tile image: 128 rows x 136 fp16 (272B stride)
#define TROW 272
#define TBYTES 34816

// ---------------- device scratch ----------------
__device__ float g_h[(size_t)N_NODES * 128];
__device__ float g_q[(size_t)N_NODES * 128];
__device__ float g_k[(size_t)N_NODES * 128];
__device__ float g_v[(size_t)N_NODES * 128];
__device__ float g_skip[(size_t)N_NODES * 128];
__device__ float g_numer[(size_t)N_NODES * 128];
__device__ float g_denom[(size_t)N_NODES * 8];
__device__ unsigned char g_himg[(size_t)N_NTILE * TBYTES];    // h: fp16
__device__ unsigned char g_eaimg[(size_t)N_ETILE * TBYTES];   // ea: fp16
__device__ unsigned char g_wimg[(size_t)15 * TBYTES];         // W: fp16
// sort scratch
__device__ int g_count[N_NODES];
__device__ int g_off2[N_NODES];
__device__ int g_src_s[N_EDGES];
__device__ int g_dst_s[N_EDGES];
__device__ int g_perm[N_EDGES];

// ---------------- PTX helpers ----------------
__device__ __forceinline__ uint32_t smem_u32(const void* p) {
    uint32_t a;
    asm("{ .reg .u64 t; cvta.to.shared.u64 t, %1; cvt.u32.u64 %0, t; }" : "=r"(a) : "l"(p));
    return a;
}
__device__ __forceinline__ void ldsm4(uint32_t* r, uint32_t addr) {
    asm volatile("ldmatrix.sync.aligned.m8n8.x4.shared.b16 {%0,%1,%2,%3}, [%4];"
                 : "=r"(r[0]), "=r"(r[1]), "=r"(r[2]), "=r"(r[3]) : "r"(addr));
}
__device__ __forceinline__ void mma16816h(float* c, const uint32_t* a, uint32_t b0, uint32_t b1) {
    asm volatile("mma.sync.aligned.m16n8k16.row.col.f32.f16.f16.f32 "
                 "{%0,%1,%2,%3}, {%4,%5,%6,%7}, {%8,%9}, {%0,%1,%2,%3};"
                 : "+f"(c[0]), "+f"(c[1]), "+f"(c[2]), "+f"(c[3])
                 : "r"(a[0]), "r"(a[1]), "r"(a[2]), "r"(a[3]), "r"(b0), "r"(b1));
}
__device__ __forceinline__ void red_add4(float* addr, float a, float b, float c, float d) {
    asm volatile("red.global.add.v4.f32 [%0], {%1, %2, %3, %4};"
                 :: "l"(addr), "f"(a), "f"(b), "f"(c), "f"(d) : "memory");
}
__device__ __forceinline__ void cp_async16(uint32_t dst, const void* src) {
    asm volatile("cp.async.cg.shared.global [%0], [%1], 16;" :: "r"(dst), "l"(src));
}
#define CP_COMMIT() asm volatile("cp.async.commit_group;" ::: "memory")
#define CP_WAIT0()  asm volatile("cp.async.wait_group 0;" ::: "memory")
#define BAR_SYNC(id, n)   asm volatile("bar.sync %0, %1;"   :: "r"(id), "r"(n) : "memory")
#define BAR_ARRIVE(id, n) asm volatile("bar.arrive %0, %1;" :: "r"(id), "r"(n) : "memory")

__device__ __forceinline__ float pe_val(int t, int c) {
    int j = c >> 1;
    float freq = expf(-logf(10000.0f) * (float)(2 * j) * (1.0f / 16.0f));
    float ang = (float)t * freq;
    return (c & 1) ? cosf(ang) : sinf(ang);
}
// 8 floats -> 8 fp16 (16B) at img+off
__device__ __forceinline__ void store8_h16(unsigned char* img, int off, const float* v) {
    unsigned int h[4];
#pragma unroll
    for (int i = 0; i < 4; ++i) {
        __half h0 = __float2half_rn(v[2 * i]);
        __half h1 = __float2half_rn(v[2 * i + 1]);
        h[i] = (unsigned int)__half_as_ushort(h0) | ((unsigned int)__half_as_ushort(h1) << 16);
    }
    *(uint4*)(img + off) = make_uint4(h[0], h[1], h[2], h[3]);
}

// single-pass fp16 GEMM, 8-warp layout: warp (wr,wc) -> C[wr*32..+32][wc*64..+64]
__device__ __forceinline__ void gemm1(uint32_t aBase, uint32_t bBase,
                                      int lane, int wr, int wc, float c[2][8][4]) {
    int rA = lane & 15;
    int kA = (lane >> 4) << 3;
    int rB = ((lane >> 4) << 3) + (lane & 7);
    int kB = ((lane >> 3) & 1) << 3;
    uint32_t aRow = aBase + (uint32_t)(wr * 32 + rA) * TROW;
    uint32_t bRow = bBase + (uint32_t)(wc * 64 + rB) * TROW;
#pragma unroll
    for (int k16 = 0; k16 < 8; ++k16) {
        uint32_t ka = (uint32_t)(k16 * 16 + kA) * 2;
        uint32_t kb = (uint32_t)(k16 * 16 + kB) * 2;
        uint32_t a[2][4];
        ldsm4(a[0], aRow + ka);
        ldsm4(a[1], aRow + 16 * TROW + ka);
        uint32_t b[4][4];
#pragma unroll
        for (int p = 0; p < 4; ++p) ldsm4(b[p], bRow + p * 16 * TROW + kb);
#pragma unroll
        for (int t = 0; t < 2; ++t)
#pragma unroll
            for (int nt = 0; nt < 8; ++nt)
                mma16816h(c[t][nt], a[t], b[nt >> 1][(nt & 1) * 2], b[nt >> 1][(nt & 1) * 2 + 1]);
    }
}

// ---------------- sort-by-dst ----------------
__global__ void zero_count_kernel() {
    int i = blockIdx.x * blockDim.x + threadIdx.x;
    if (i < N_NODES) g_count[i] = 0;
}
__global__ void hist_kernel(const int* __restrict__ ei) {
    int e = blockIdx.x * blockDim.x + threadIdx.x;
    if (e < N_EDGES) atomicAdd(&g_count[ei[N_EDGES + e]], 1);
}
__global__ void scan_kernel() {
    __shared__ int warp_sums[32];
    __shared__ int s_carry;
    int tid = threadIdx.x;
    int lane = tid & 31, wid = tid >> 5;
    if (tid == 0) s_carry = 0;
    __syncthreads();
    for (int base = 0; base < N_NODES; base += 1024) {
        int idx = base + tid;
        int v = (idx < N_NODES) ? g_count[idx] : 0;
        int inc = v;
#pragma unroll
        for (int o = 1; o < 32; o <<= 1) {
            int t = __shfl_up_sync(0xffffffffu, inc, o);
            if (lane >= o) inc += t;
        }
        if (lane == 31) warp_sums[wid] = inc;
        __syncthreads();
        if (wid == 0) {
            int w = warp_sums[lane];
            int wi = w;
#pragma unroll
            for (int o = 1; o < 32; o <<= 1) {
                int t = __shfl_up_sync(0xffffffffu, wi, o);
                if (lane >= o) wi += t;
            }
            warp_sums[lane] = wi - w;
        }
        __syncthreads();
        int ex = inc - v + warp_sums[wid] + s_carry;
        if (idx < N_NODES) g_off2[idx] = ex;
        __syncthreads();
        if (tid == 1023) s_carry = ex + v;
        __syncthreads();
    }
}
__global__ void scatter_kernel(const int* __restrict__ ei) {
    int e = blockIdx.x * blockDim.x + threadIdx.x;
    if (e >= N_EDGES) return;
    int d = ei[N_EDGES + e];
    int pos = atomicAdd(&g_off2[d], 1);
    g_src_s[pos] = ei[e];
    g_dst_s[pos] = d;
    g_perm[pos] = e;
}

// ---------------- builders ----------------
__global__ void build_h_kernel(const float* __restrict__ x, const int* __restrict__ nlu) {
    int gid = blockIdx.x * blockDim.x + threadIdx.x;
    if (gid >= N_NODES * 16) return;
    int n = gid >> 4, j = gid & 15, c0 = j * 8;
    float v[8];
    if (c0 < 96) {
        float4 a = *(const float4*)(x + (size_t)n * 96 + c0);
        float4 b = *(const float4*)(x + (size_t)n * 96 + c0 + 4);
        v[0] = a.x; v[1] = a.y; v[2] = a.z; v[3] = a.w; v[4] = b.x; v[5] = b.y; v[6] = b.z; v[7] = b.w;
    } else {
        int t = nlu[n * 2 + ((c0 - 96) >> 4)];
        int cl = (c0 - 96) & 15;
#pragma unroll
        for (int i = 0; i < 8; ++i) v[i] = pe_val(t, cl + i);
    }
    store8_h16(g_himg + (size_t)(n >> 7) * TBYTES, (n & 127) * TROW + c0 * 2, v);
}
__global__ void build_eaimg_kernel(const float* __restrict__ eattr, const int* __restrict__ elu) {
    int gid = blockIdx.x * blockDim.x + threadIdx.x;
    if (gid >= N_EDGES * 16) return;
    int p = gid >> 4, j = gid & 15, c0 = j * 8;
    int e = g_perm[p];
    float v[8];
    if (c0 < 96) {
        float4 a = *(const float4*)(eattr + (size_t)e * 96 + c0);
        float4 b = *(const float4*)(eattr + (size_t)e * 96 + c0 + 4);
        v[0] = a.x; v[1] = a.y; v[2] = a.z; v[3] = a.w; v[4] = b.x; v[5] = b.y; v[6] = b.z; v[7] = b.w;
    } else {
        int t = elu[(size_t)e * 2 + ((c0 - 96) >> 4)];
        int cl = (c0 - 96) & 15;
#pragma unroll
        for (int i = 0; i < 8; ++i) v[i] = pe_val(t, cl + i);
    }
    store8_h16(g_eaimg + (size_t)(p >> 7) * TBYTES, (p & 127) * TROW + c0 * 2, v);
}
__global__ void prep_w_kernel(const float* __restrict__ Wq, const float* __restrict__ Wk,
                              const float* __restrict__ Wv, const float* __restrict__ Ws,
                              const float* __restrict__ We) {
    int gid = blockIdx.x * blockDim.x + threadIdx.x;
    if (gid >= 15 * 2048) return;
    int t = gid >> 11, rem = gid & 2047;
    int n = rem >> 4, j = rem & 15, k0 = j * 8;
    int l = t / 5, m = t % 5;
    const float* W = (m == 0) ? Wq : (m == 1) ? Wk : (m == 2) ? Wv : (m == 3) ? Ws : We;
    const float* base = W + (size_t)l * 16384;
    float v[8];
#pragma unroll
    for (int i = 0; i < 8; ++i) v[i] = base[(size_t)(k0 + i) * 128 + n];
    store8_h16(g_wimg + (size_t)t * TBYTES, n * TROW + k0 * 2, v);
}

// ---------------- node GEMM: single-pass fp16, 2 GEMMs per block ----------------
#define OFF_NB 34816
#define OFF_NBIAS 69632
#define SMEM_NODE 70144
__global__ __launch_bounds__(256)
void node_mma_kernel(const float* __restrict__ bq, const float* __restrict__ bk,
                     const float* __restrict__ bv, const float* __restrict__ bsk, int layer) {
    extern __shared__ __align__(16) unsigned char smem[];
    uint32_t sb = smem_u32(smem);
    int tid = threadIdx.x, wid = tid >> 5, lane = tid & 31;
    int wr = wid & 3, wc = wid >> 2;
    int tile = blockIdx.x, ysel = blockIdx.y;
    int gi = lane >> 2, tig = lane & 3;

    const uint4* aimg = (const uint4*)(g_himg + (size_t)tile * TBYTES);
    uint4* sA = (uint4*)smem;
    for (int i = tid; i < 2176; i += 256) sA[i] = aimg[i];

    float* biasBuf = (float*)(smem + OFF_NBIAS);
    uint4* sB = (uint4*)(smem + OFF_NB);

    for (int w2 = 0; w2 < 2; ++w2) {
        int w = ysel * 2 + w2;
        __syncthreads();
        const uint4* bimg = (const uint4*)(g_wimg + (size_t)(layer * 5 + w) * TBYTES);
        for (int i = tid; i < 2176; i += 256) sB[i] = bimg[i];
        if (tid < 128) {
            const float* bias = (w == 0) ? bq : (w == 1) ? bk : (w == 2) ? bv : bsk;
            biasBuf[tid] = bias[layer * 128 + tid];
        }
        __syncthreads();

        float c[2][8][4];
#pragma unroll
        for (int t = 0; t < 2; ++t)
#pragma unroll
            for (int nt = 0; nt < 8; ++nt)
#pragma unroll
                for (int j = 0; j < 4; ++j) c[t][nt][j] = 0.0f;

        gemm1(sb, sb + OFF_NB, lane, wr, wc, c);

        float* out = (w == 0) ? g_q : (w == 1) ? g_k : (w == 2) ? g_v : g_skip;
#pragma unroll
        for (int t = 0; t < 2; ++t) {
#pragma unroll
            for (int half = 0; half < 2; ++half) {
                int node = tile * 128 + wr * 32 + t * 16 + gi + half * 8;
                if (node < N_NODES) {
                    float* op = out + (size_t)node * 128;
#pragma unroll
                    for (int nt = 0; nt < 8; ++nt) {
                        int col = wc * 64 + nt * 8 + tig * 2;
                        *(float2*)(op + col) = make_float2(c[t][nt][half * 2 + 0] + biasBuf[col],
                                                           c[t][nt][half * 2 + 1] + biasBuf[col + 1]);
                    }
                }
            }
        }
    }
}

// ---------------- edge kernel: producer/consumer warp specialization ----------------
// smem: [0,34K) B resident | [34K,102K) buf0 (A 34K, est overlay 68K) | [102K,170K) buf1
// barriers: full[b]=2+b, free[b]=4+b, 6 = producer-internal
#define EB_BUF0 34816
#define EB_BUFSZ 69632
#define SMEM_EDGE 174080
__global__ __launch_bounds__(512)
void edge_mma_kernel(int layer) {
    extern __shared__ __align__(16) unsigned char smem[];
    uint32_t sb = smem_u32(smem);
    int tid = threadIdx.x, wid = tid >> 5, lane = tid & 31;

    const uint4* bimg = (const uint4*)(g_wimg + (size_t)(layer * 5 + 4) * TBYTES);
    uint4* sB = (uint4*)smem;
    for (int i = tid; i < 2176; i += 512) sB[i] = bimg[i];
    __syncthreads();

    if (wid < 8) {
        // ---- producers: A load -> gemm -> est ----
        int wr = wid & 3, wc = wid >> 2;
        int gi = lane >> 2, tig = lane & 3;
        int idx = 0;
        for (int tile = blockIdx.x; tile < N_ETILE; tile += 148, ++idx) {
            int b = idx & 1;
            uint32_t aBuf = sb + EB_BUF0 + b * EB_BUFSZ;
            BAR_SYNC(4 + b, 512);
            const unsigned char* src = g_eaimg + (size_t)tile * TBYTES;
            for (int i = tid; i < 2176; i += 256)
                cp_async16(aBuf + i * 16, src + (size_t)i * 16);
            CP_COMMIT();
            CP_WAIT0();
            BAR_SYNC(6, 256);

            float c[2][8][4];
#pragma unroll
            for (int t = 0; t < 2; ++t)
#pragma unroll
                for (int nt = 0; nt < 8; ++nt)
#pragma unroll
                    for (int j = 0; j < 4; ++j) c[t][nt][j] = 0.0f;

            gemm1(aBuf, sb, lane, wr, wc, c);

            BAR_SYNC(6, 256);
            float* est = (float*)(smem + EB_BUF0 + b * EB_BUFSZ);
#pragma unroll
            for (int t = 0; t < 2; ++t)
#pragma unroll
                for (int half = 0; half < 2; ++half) {
                    int r = wr * 32 + t * 16 + gi + half * 8;
#pragma unroll
                    for (int nt = 0; nt < 8; ++nt) {
                        int col = wc * 64 + nt * 8 + tig * 2;
                        *(float2*)(est + r * 132 + col) = make_float2(c[t][nt][half * 2], c[t][nt][half * 2 + 1]);
                    }
                }
            BAR_ARRIVE(2 + b, 512);
        }
    } else {
        // ---- consumers: gather/softmax/atomics ----
        int gtid = tid & 255;
        int tx = gtid & 15, ty = gtid >> 4;
        int hd = tx >> 1, cb = tx << 3;
        BAR_ARRIVE(4, 512);
        BAR_ARRIVE(5, 512);
        int idx = 0;
        for (int tile = blockIdx.x; tile < N_ETILE; tile += 148, ++idx) {
            int b = idx & 1;
            BAR_SYNC(2 + b, 512);
            const float* est = (const float*)(smem + EB_BUF0 + b * EB_BUFSZ);
            int e0 = tile << 7;

            int cur_d = -1;
            float4 q0, q1;
            float aN0 = 0.f, aN1 = 0.f, aN2 = 0.f, aN3 = 0.f;
            float aN4 = 0.f, aN5 = 0.f, aN6 = 0.f, aN7 = 0.f;
            float aD = 0.f;
#pragma unroll
            for (int i = 0; i < 8; ++i) {
                int er = ty * 8 + i;
                float4 e0v = *(const float4*)(est + er * 132 + cb);
                float4 e1v = *(const float4*)(est + er * 132 + cb + 4);
                float e8[8] = {e0v.x, e0v.y, e0v.z, e0v.w, e1v.x, e1v.y, e1v.z, e1v.w};
                int s = g_src_s[e0 + er];
                int d = g_dst_s[e0 + er];
                if (d != cur_d) {
                    if (cur_d >= 0) {
                        float* np = g_numer + (size_t)cur_d * 128 + cb;
                        red_add4(np,     aN0, aN1, aN2, aN3);
                        red_add4(np + 4, aN4, aN5, aN6, aN7);
                        if (!(tx & 1)) atomicAdd(g_denom + (size_t)cur_d * 8 + hd, aD);
                    }
                    cur_d = d;
                    aN0 = aN1 = aN2 = aN3 = aN4 = aN5 = aN6 = aN7 = 0.f;
                    aD = 0.f;
                    const float* qp = g_q + (size_t)d * 128 + cb;
                    q0 = *(const float4*)qp;
                    q1 = *(const float4*)(qp + 4);
                }
                const float* kp = g_k + (size_t)s * 128 + cb;
                float4 k0 = *(const float4*)kp, k1 = *(const float4*)(kp + 4);
                float part = q0.x * (k0.x + e8[0]) + q0.y * (k0.y + e8[1])
                           + q0.z * (k0.z + e8[2]) + q0.w * (k0.w + e8[3])
                           + q1.x * (k1.x + e8[4]) + q1.y * (k1.y + e8[5])
                           + q1.z * (k1.z + e8[6]) + q1.w * (k1.w + e8[7]);
                float full = part + __shfl_xor_sync(0xffffffffu, part, 1);
                float p = __expf(full * 0.25f);  // shift-free softmax (alpha is O(1))
                const float* vp = g_v + (size_t)s * 128 + cb;
                float4 v0 = *(const float4*)vp, v1 = *(const float4*)(vp + 4);
                aN0 += p * (v0.x + e8[0]); aN1 += p * (v0.y + e8[1]);
                aN2 += p * (v0.z + e8[2]); aN3 += p * (v0.w + e8[3]);
                aN4 += p * (v1.x + e8[4]); aN5 += p * (v1.y + e8[5]);
                aN6 += p * (v1.z + e8[6]); aN7 += p * (v1.w + e8[7]);
                aD += p;
            }
            {
                float* np = g_numer + (size_t)cur_d * 128 + cb;
                red_add4(np,     aN0, aN1, aN2, aN3);
                red_add4(np + 4, aN4, aN5, aN6, aN7);
                if (!(tx & 1)) atomicAdd(g_denom + (size_t)cur_d * 8 + hd, aD);
            }
            BAR_ARRIVE(4 + b, 512);
        }
    }
}

// ---------------- node update ----------------
__global__ void update_h_kernel() {
    int gid = blockIdx.x * blockDim.x + threadIdx.x;
    if (gid >= N_NODES * 16) return;
    int n = gid >> 4, j = gid & 15, c0 = j * 8;
    float inv = 1.0f / (g_denom[n * 8 + (c0 >> 4)] + 1e-16f);
    float4 n0 = *(const float4*)(g_numer + (size_t)n * 128 + c0);
    float4 n1 = *(const float4*)(g_numer + (size_t)n * 128 + c0 + 4);
    float4 s0 = *(const float4*)(g_skip + (size_t)n * 128 + c0);
    float4 s1 = *(const float4*)(g_skip + (size_t)n * 128 + c0 + 4);
    float v[8];
    v[0] = fmaxf(n0.x * inv + s0.x, 0.f); v[1] = fmaxf(n0.y * inv + s0.y, 0.f);
    v[2] = fmaxf(n0.z * inv + s0.z, 0.f); v[3] = fmaxf(n0.w * inv + s0.w, 0.f);
    v[4] = fmaxf(n1.x * inv + s1.x, 0.f); v[5] = fmaxf(n1.y * inv + s1.y, 0.f);
    v[6] = fmaxf(n1.z * inv + s1.z, 0.f); v[7] = fmaxf(n1.w * inv + s1.w, 0.f);
    *(float4*)(g_h + (size_t)n * 128 + c0)     = make_float4(v[0], v[1], v[2], v[3]);
    *(float4*)(g_h + (size_t)n * 128 + c0 + 4) = make_float4(v[4], v[5], v[6], v[7]);
    store8_h16(g_himg + (size_t)(n >> 7) * TBYTES, (n & 127) * TROW + c0 * 2, v);
    float4 z = make_float4(0.f, 0.f, 0.f, 0.f);
    *(float4*)(g_numer + (size_t)n * 128 + c0)     = z;
    *(float4*)(g_numer + (size_t)n * 128 + c0 + 4) = z;
    if (!(j & 1)) g_denom[n * 8 + (j >> 1)] = 0.0f;
}

// ---------------- output GEMM ----------------
__global__ void out_gemm_kernel(const float* __restrict__ Wout, const float* __restrict__ bout,
                                float* __restrict__ out) {
    __shared__ float ws[128 * 16];
    __shared__ float hs[16 * 128];
    int tid = threadIdx.x;
    int row0 = blockIdx.x * 16;
#pragma unroll
    for (int it = 0; it < 8; ++it) {
        int idx = it * 256 + tid;
        ws[idx] = Wout[idx];
        int r = row0 + (idx >> 7);
        hs[idx] = (r < N_NODES) ? g_h[(size_t)row0 * 128 + idx] : 0.0f;
    }
    __syncthreads();
    int r = tid >> 4, c = tid & 15;
    float s = bout[c];
#pragma unroll 8
    for (int k = 0; k < 128; ++k) s += hs[r * 128 + k] * ws[k * 16 + c];
    int gr = row0 + r;
    if (gr < N_NODES) out[(size_t)gr * 16 + c] = s;
}

// ---------------- host ----------------
extern "C" void kernel_launch(void* const* d_in, const int* in_sizes, int n_in,
                              void* d_out, int out_size) {
    const float* x     = (const float*)d_in[0];
    const int*   nlu   = (const int*)  d_in[1];
    const int*   ei    = (const int*)  d_in[2];
    const float* eattr = (const float*)d_in[3];
    const int*   elu   = (const int*)  d_in[4];
    const float* Wq    = (const float*)d_in[5];
    const float* bq    = (const float*)d_in[6];
    const float* Wk    = (const float*)d_in[7];
    const float* bk    = (const float*)d_in[8];
    const float* Wv    = (const float*)d_in[9];
    const float* bv    = (const float*)d_in[10];
    const float* We    = (const float*)d_in[11];
    const float* Ws    = (const float*)d_in[12];
    const float* bs    = (const float*)d_in[13];
    const float* Wout  = (const float*)d_in[14];
    const float* bout  = (const float*)d_in[15];
    float* out = (float*)d_out;
    (void)in_sizes; (void)n_in; (void)out_size;

    cudaFuncSetAttribute(node_mma_kernel, cudaFuncAttributeMaxDynamicSharedMemorySize, SMEM_NODE);
    cudaFuncSetAttribute(edge_mma_kernel, cudaFuncAttributeMaxDynamicSharedMemorySize, SMEM_EDGE);

    zero_count_kernel<<<(N_NODES + 255) / 256, 256>>>();
    hist_kernel<<<(N_EDGES + 255) / 256, 256>>>(ei);
    scan_kernel<<<1, 1024>>>();
    scatter_kernel<<<(N_EDGES + 255) / 256, 256>>>(ei);

    build_h_kernel    <<<(N_NODES * 16 + 255) / 256, 256>>>(x, nlu);
    build_eaimg_kernel<<<(N_EDGES * 16 + 255) / 256, 256>>>(eattr, elu);
    prep_w_kernel     <<<(15 * 2048 + 255) / 256, 256>>>(Wq, Wk, Wv, Ws, We);

    for (int l = 0; l < 3; ++l) {
        node_mma_kernel<<<dim3(N_NTILE, 2), 256, SMEM_NODE>>>(bq, bk, bv, bs, l);
        edge_mma_kernel<<<148, 512, SMEM_EDGE>>>(l);
        update_h_kernel<<<(N_NODES * 16 + 255) / 256, 256>>>();
    }
    out_gemm_kernel<<<N_NODES / 16, 256>>>(Wout, bout, out);
}

// round 14
// speedup vs baseline: 1.6505x; 1.0911x over previous
#include <cuda_runtime.h>
#include <cuda_fp16.h>
#include <math.h>
#include <stdint.h>

#define N_NODES 100000
#define N_EDGES 800000
#define N_NTILE 782
#define N_ETILE 6250

// fp16 tile image: 128 rows x 136 fp16 (272B stride)
#define TROW 272
#define TBYTES 34816

// ---------------- device scratch ----------------
__device__ float g_h[(size_t)N_NODES * 128];
__device__ __half g_qh[(size_t)N_NODES * 128];
__device__ __half g_kh[(size_t)N_NODES * 128];
__device__ __half g_vh[(size_t)N_NODES * 128];
__device__ float g_skip[(size_t)N_NODES * 128];
__device__ float g_numer[(size_t)N_NODES * 128];
__device__ float g_denom[(size_t)N_NODES * 8];
__device__ unsigned char g_himg[(size_t)N_NTILE * TBYTES];    // h: fp16
__device__ unsigned char g_eaimg[(size_t)N_ETILE * TBYTES];   // ea: fp16
__device__ unsigned char g_wimg[(size_t)15 * TBYTES];         // W: fp16
// sort scratch
__device__ int g_count[N_NODES];
__device__ int g_off2[N_NODES];
__device__ int g_src_s[N_EDGES];
__device__ int g_dst_s[N_EDGES];
__device__ int g_perm[N_EDGES];

// ---------------- PTX helpers ----------------
__device__ __forceinline__ uint32_t smem_u32(const void* p) {
    uint32_t a;
    asm("{ .reg .u64 t; cvta.to.shared.u64 t, %1; cvt.u32.u64 %0, t; }" : "=r"(a) : "l"(p));
    return a;
}
__device__ __forceinline__ void ldsm4(uint32_t* r, uint32_t addr) {
    asm volatile("ldmatrix.sync.aligned.m8n8.x4.shared.b16 {%0,%1,%2,%3}, [%4];"
                 : "=r"(r[0]), "=r"(r[1]), "=r"(r[2]), "=r"(r[3]) : "r"(addr));
}
__device__ __forceinline__ void mma16816h(float* c, const uint32_t* a, uint32_t b0, uint32_t b1) {
    asm volatile("mma.sync.aligned.m16n8k16.row.col.f32.f16.f16.f32 "
                 "{%0,%1,%2,%3}, {%4,%5,%6,%7}, {%8,%9}, {%0,%1,%2,%3};"
                 : "+f"(c[0]), "+f"(c[1]), "+f"(c[2]), "+f"(c[3])
                 : "r"(a[0]), "r"(a[1]), "r"(a[2]), "r"(a[3]), "r"(b0), "r"(b1));
}
__device__ __forceinline__ void red_add4(float* addr, float a, float b, float c, float d) {
    asm volatile("red.global.add.v4.f32 [%0], {%1, %2, %3, %4};"
                 :: "l"(addr), "f"(a), "f"(b), "f"(c), "f"(d) : "memory");
}
__device__ __forceinline__ void cp_async16(uint32_t dst, const void* src) {
    asm volatile("cp.async.cg.shared.global [%0], [%1], 16;" :: "r"(dst), "l"(src));
}
#define CP_COMMIT() asm volatile("cp.async.commit_group;" ::: "memory")
#define CP_WAIT0()  asm volatile("cp.async.wait_group 0;" ::: "memory")
#define BAR_SYNC(id, n)   asm volatile("bar.sync %0, %1;"   :: "r"(id), "r"(n) : "memory")
#define BAR_ARRIVE(id, n) asm volatile("bar.arrive %0, %1;" :: "r"(id), "r"(n) : "memory")

__device__ __forceinline__ float pe_val(int t, int c) {
    int j = c >> 1;
    float freq = expf(-logf(10000.0f) * (float)(2 * j) * (1.0f / 16.0f));
    float ang = (float)t * freq;
    return (c & 1) ? cosf(ang) : sinf(ang);
}
// 8 floats -> 8 fp16 (16B) at img+off
__device__ __forceinline__ void store8_h16(unsigned char* img, int off, const float* v) {
    unsigned int h[4];
#pragma unroll
    for (int i = 0; i < 4; ++i) {
        __half h0 = __float2half_rn(v[2 * i]);
        __half h1 = __float2half_rn(v[2 * i + 1]);
        h[i] = (unsigned int)__half_as_ushort(h0) | ((unsigned int)__half_as_ushort(h1) << 16);
    }
    *(uint4*)(img + off) = make_uint4(h[0], h[1], h[2], h[3]);
}
// load 8 fp16 from gmem (16B) -> 8 floats
__device__ __forceinline__ void load8_h16(const __half* p, float* f) {
    uint4 raw = *(const uint4*)p;
    const __half2* h2 = (const __half2*)&raw;
#pragma unroll
    for (int i = 0; i < 4; ++i) {
        float2 t = __half22float2(h2[i]);
        f[2 * i] = t.x;
        f[2 * i + 1] = t.y;
    }
}

// single-pass fp16 GEMM, 8-warp layout: warp (wr,wc) -> C[wr*32..+32][wc*64..+64]
__device__ __forceinline__ void gemm1(uint32_t aBase, uint32_t bBase,
                                      int lane, int wr, int wc, float c[2][8][4]) {
    int rA = lane & 15;
    int kA = (lane >> 4) << 3;
    int rB = ((lane >> 4) << 3) + (lane & 7);
    int kB = ((lane >> 3) & 1) << 3;
    uint32_t aRow = aBase + (uint32_t)(wr * 32 + rA) * TROW;
    uint32_t bRow = bBase + (uint32_t)(wc * 64 + rB) * TROW;
#pragma unroll
    for (int k16 = 0; k16 < 8; ++k16) {
        uint32_t ka = (uint32_t)(k16 * 16 + kA) * 2;
        uint32_t kb = (uint32_t)(k16 * 16 + kB) * 2;
        uint32_t a[2][4];
        ldsm4(a[0], aRow + ka);
        ldsm4(a[1], aRow + 16 * TROW + ka);
        uint32_t b[4][4];
#pragma unroll
        for (int p = 0; p < 4; ++p) ldsm4(b[p], bRow + p * 16 * TROW + kb);
#pragma unroll
        for (int t = 0; t < 2; ++t)
#pragma unroll
            for (int nt = 0; nt < 8; ++nt)
                mma16816h(c[t][nt], a[t], b[nt >> 1][(nt & 1) * 2], b[nt >> 1][(nt & 1) * 2 + 1]);
    }
}

// ---------------- sort-by-dst ----------------
__global__ void zero_count_kernel() {
    int i = blockIdx.x * blockDim.x + threadIdx.x;
    if (i < N_NODES) g_count[i] = 0;
}
__global__ void hist_kernel(const int* __restrict__ ei) {
    int e = blockIdx.x * blockDim.x + threadIdx.x;
    if (e < N_EDGES) atomicAdd(&g_count[ei[N_EDGES + e]], 1);
}
__global__ void scan_kernel() {
    __shared__ int warp_sums[32];
    __shared__ int s_carry;
    int tid = threadIdx.x;
    int lane = tid & 31, wid = tid >> 5;
    if (tid == 0) s_carry = 0;
    __syncthreads();
    for (int base = 0; base < N_NODES; base += 1024) {
        int idx = base + tid;
        int v = (idx < N_NODES) ? g_count[idx] : 0;
        int inc = v;
#pragma unroll
        for (int o = 1; o < 32; o <<= 1) {
            int t = __shfl_up_sync(0xffffffffu, inc, o);
            if (lane >= o) inc += t;
        }
        if (lane == 31) warp_sums[wid] = inc;
        __syncthreads();
        if (wid == 0) {
            int w = warp_sums[lane];
            int wi = w;
#pragma unroll
            for (int o = 1; o < 32; o <<= 1) {
                int t = __shfl_up_sync(0xffffffffu, wi, o);
                if (lane >= o) wi += t;
            }
            warp_sums[lane] = wi - w;
        }
        __syncthreads();
        int ex = inc - v + warp_sums[wid] + s_carry;
        if (idx < N_NODES) g_off2[idx] = ex;
        __syncthreads();
        if (tid == 1023) s_carry = ex + v;
        __syncthreads();
    }
}
__global__ void scatter_kernel(const int* __restrict__ ei) {
    int e = blockIdx.x * blockDim.x + threadIdx.x;
    if (e >= N_EDGES) return;
    int d = ei[N_EDGES + e];
    int pos = atomicAdd(&g_off2[d], 1);
    g_src_s[pos] = ei[e];
    g_dst_s[pos] = d;
    g_perm[pos] = e;
}

// ---------------- builders ----------------
__global__ void build_h_kernel(const float* __restrict__ x, const int* __restrict__ nlu) {
    int gid = blockIdx.x * blockDim.x + threadIdx.x;
    if (gid >= N_NODES * 16) return;
    int n = gid >> 4, j = gid & 15, c0 = j * 8;
    float v[8];
    if (c0 < 96) {
        float4 a = *(const float4*)(x + (size_t)n * 96 + c0);
        float4 b = *(const float4*)(x + (size_t)n * 96 + c0 + 4);
        v[0] = a.x; v[1] = a.y; v[2] = a.z; v[3] = a.w; v[4] = b.x; v[5] = b.y; v[6] = b.z; v[7] = b.w;
    } else {
        int t = nlu[n * 2 + ((c0 - 96) >> 4)];
        int cl = (c0 - 96) & 15;
#pragma unroll
        for (int i = 0; i < 8; ++i) v[i] = pe_val(t, cl + i);
    }
    store8_h16(g_himg + (size_t)(n >> 7) * TBYTES, (n & 127) * TROW + c0 * 2, v);
}
__global__ void build_eaimg_kernel(const float* __restrict__ eattr, const int* __restrict__ elu) {
    int gid = blockIdx.x * blockDim.x + threadIdx.x;
    if (gid >= N_EDGES * 16) return;
    int p = gid >> 4, j = gid & 15, c0 = j * 8;
    int e = g_perm[p];
    float v[8];
    if (c0 < 96) {
        float4 a = *(const float4*)(eattr + (size_t)e * 96 + c0);
        float4 b = *(const float4*)(eattr + (size_t)e * 96 + c0 + 4);
        v[0] = a.x; v[1] = a.y; v[2] = a.z; v[3] = a.w; v[4] = b.x; v[5] = b.y; v[6] = b.z; v[7] = b.w;
    } else {
        int t = elu[(size_t)e * 2 + ((c0 - 96) >> 4)];
        int cl = (c0 - 96) & 15;
#pragma unroll
        for (int i = 0; i < 8; ++i) v[i] = pe_val(t, cl + i);
    }
    store8_h16(g_eaimg + (size_t)(p >> 7) * TBYTES, (p & 127) * TROW + c0 * 2, v);
}
__global__ void prep_w_kernel(const float* __restrict__ Wq, const float* __restrict__ Wk,
                              const float* __restrict__ Wv, const float* __restrict__ Ws,
                              const float* __restrict__ We) {
    int gid = blockIdx.x * blockDim.x + threadIdx.x;
    if (gid >= 15 * 2048) return;
    int t = gid >> 11, rem = gid & 2047;
    int n = rem >> 4, j = rem & 15, k0 = j * 8;
    int l = t / 5, m = t % 5;
    const float* W = (m == 0) ? Wq : (m == 1) ? Wk : (m == 2) ? Wv : (m == 3) ? Ws : We;
    const float* base = W + (size_t)l * 16384;
    float v[8];
#pragma unroll
    for (int i = 0; i < 8; ++i) v[i] = base[(size_t)(k0 + i) * 128 + n];
    store8_h16(g_wimg + (size_t)t * TBYTES, n * TROW + k0 * 2, v);
}

// ---------------- node GEMM: single-pass fp16, q/k/v written as fp16 tables ----------------
#define OFF_NB 34816
#define OFF_NBIAS 69632
#define SMEM_NODE 70144
__global__ __launch_bounds__(256)
void node_mma_kernel(const float* __restrict__ bq, const float* __restrict__ bk,
                     const float* __restrict__ bv, const float* __restrict__ bsk, int layer) {
    extern __shared__ __align__(16) unsigned char smem[];
    uint32_t sb = smem_u32(smem);
    int tid = threadIdx.x, wid = tid >> 5, lane = tid & 31;
    int wr = wid & 3, wc = wid >> 2;
    int tile = blockIdx.x, ysel = blockIdx.y;
    int gi = lane >> 2, tig = lane & 3;

    const uint4* aimg = (const uint4*)(g_himg + (size_t)tile * TBYTES);
    uint4* sA = (uint4*)smem;
    for (int i = tid; i < 2176; i += 256) sA[i] = aimg[i];

    float* biasBuf = (float*)(smem + OFF_NBIAS);
    uint4* sB = (uint4*)(smem + OFF_NB);

    for (int w2 = 0; w2 < 2; ++w2) {
        int w = ysel * 2 + w2;
        __syncthreads();
        const uint4* bimg = (const uint4*)(g_wimg + (size_t)(layer * 5 + w) * TBYTES);
        for (int i = tid; i < 2176; i += 256) sB[i] = bimg[i];
        if (tid < 128) {
            const float* bias = (w == 0) ? bq : (w == 1) ? bk : (w == 2) ? bv : bsk;
            biasBuf[tid] = bias[layer * 128 + tid];
        }
        __syncthreads();

        float c[2][8][4];
#pragma unroll
        for (int t = 0; t < 2; ++t)
#pragma unroll
            for (int nt = 0; nt < 8; ++nt)
#pragma unroll
                for (int j = 0; j < 4; ++j) c[t][nt][j] = 0.0f;

        gemm1(sb, sb + OFF_NB, lane, wr, wc, c);

#pragma unroll
        for (int t = 0; t < 2; ++t) {
#pragma unroll
            for (int half = 0; half < 2; ++half) {
                int node = tile * 128 + wr * 32 + t * 16 + gi + half * 8;
                if (node < N_NODES) {
                    if (w < 3) {
                        __half* oph = ((w == 0) ? g_qh : (w == 1) ? g_kh : g_vh) + (size_t)node * 128;
#pragma unroll
                        for (int nt = 0; nt < 8; ++nt) {
                            int col = wc * 64 + nt * 8 + tig * 2;
                            *(__half2*)(oph + col) = __floats2half2_rn(c[t][nt][half * 2 + 0] + biasBuf[col],
                                                                       c[t][nt][half * 2 + 1] + biasBuf[col + 1]);
                        }
                    } else {
                        float* op = g_skip + (size_t)node * 128;
#pragma unroll
                        for (int nt = 0; nt < 8; ++nt) {
                            int col = wc * 64 + nt * 8 + tig * 2;
                            *(float2*)(op + col) = make_float2(c[t][nt][half * 2 + 0] + biasBuf[col],
                                                               c[t][nt][half * 2 + 1] + biasBuf[col + 1]);
                        }
                    }
                }
            }
        }
    }
}

// ---------------- edge kernel: producer/consumer warp specialization ----------------
// smem: [0,34K) B resident | [34K,102K) buf0 (A 34K, est overlay 68K) | [102K,170K) buf1
// barriers: full[b]=2+b, free[b]=4+b, 6 = producer-internal
#define EB_BUF0 34816
#define EB_BUFSZ 69632
#define SMEM_EDGE 174080
__global__ __launch_bounds__(512)
void edge_mma_kernel(int layer) {
    extern __shared__ __align__(16) unsigned char smem[];
    uint32_t sb = smem_u32(smem);
    int tid = threadIdx.x, wid = tid >> 5, lane = tid & 31;

    const uint4* bimg = (const uint4*)(g_wimg + (size_t)(layer * 5 + 4) * TBYTES);
    uint4* sB = (uint4*)smem;
    for (int i = tid; i < 2176; i += 512) sB[i] = bimg[i];
    __syncthreads();

    if (wid < 8) {
        // ---- producers: A load -> gemm -> est ----
        int wr = wid & 3, wc = wid >> 2;
        int gi = lane >> 2, tig = lane & 3;
        int idx = 0;
        for (int tile = blockIdx.x; tile < N_ETILE; tile += 148, ++idx) {
            int b = idx & 1;
            uint32_t aBuf = sb + EB_BUF0 + b * EB_BUFSZ;
            BAR_SYNC(4 + b, 512);
            const unsigned char* src = g_eaimg + (size_t)tile * TBYTES;
            for (int i = tid; i < 2176; i += 256)
                cp_async16(aBuf + i * 16, src + (size_t)i * 16);
            CP_COMMIT();
            CP_WAIT0();
            BAR_SYNC(6, 256);

            float c[2][8][4];
#pragma unroll
            for (int t = 0; t < 2; ++t)
#pragma unroll
                for (int nt = 0; nt < 8; ++nt)
#pragma unroll
                    for (int j = 0; j < 4; ++j) c[t][nt][j] = 0.0f;

            gemm1(aBuf, sb, lane, wr, wc, c);

            BAR_SYNC(6, 256);
            float* est = (float*)(smem + EB_BUF0 + b * EB_BUFSZ);
#pragma unroll
            for (int t = 0; t < 2; ++t)
#pragma unroll
                for (int half = 0; half < 2; ++half) {
                    int r = wr * 32 + t * 16 + gi + half * 8;
#pragma unroll
                    for (int nt = 0; nt < 8; ++nt) {
                        int col = wc * 64 + nt * 8 + tig * 2;
                        *(float2*)(est + r * 132 + col) = make_float2(c[t][nt][half * 2], c[t][nt][half * 2 + 1]);
                    }
                }
            BAR_ARRIVE(2 + b, 512);
        }
    } else {
        // ---- consumers: gather/softmax/atomics (fp16 q/k/v tables) ----
        int gtid = tid & 255;
        int tx = gtid & 15, ty = gtid >> 4;
        int hd = tx >> 1, cb = tx << 3;
        BAR_ARRIVE(4, 512);
        BAR_ARRIVE(5, 512);
        int idx = 0;
        for (int tile = blockIdx.x; tile < N_ETILE; tile += 148, ++idx) {
            int b = idx & 1;
            BAR_SYNC(2 + b, 512);
            const float* est = (const float*)(smem + EB_BUF0 + b * EB_BUFSZ);
            int e0 = tile << 7;

            int cur_d = -1;
            float qf[8];
            float aN0 = 0.f, aN1 = 0.f, aN2 = 0.f, aN3 = 0.f;
            float aN4 = 0.f, aN5 = 0.f, aN6 = 0.f, aN7 = 0.f;
            float aD = 0.f;
#pragma unroll
            for (int i = 0; i < 8; ++i) {
                int er = ty * 8 + i;
                float4 e0v = *(const float4*)(est + er * 132 + cb);
                float4 e1v = *(const float4*)(est + er * 132 + cb + 4);
                float e8[8] = {e0v.x, e0v.y, e0v.z, e0v.w, e1v.x, e1v.y, e1v.z, e1v.w};
                int s = g_src_s[e0 + er];
                int d = g_dst_s[e0 + er];
                if (d != cur_d) {
                    if (cur_d >= 0) {
                        float* np = g_numer + (size_t)cur_d * 128 + cb;
                        red_add4(np,     aN0, aN1, aN2, aN3);
                        red_add4(np + 4, aN4, aN5, aN6, aN7);
                        if (!(tx & 1)) atomicAdd(g_denom + (size_t)cur_d * 8 + hd, aD);
                    }
                    cur_d = d;
                    aN0 = aN1 = aN2 = aN3 = aN4 = aN5 = aN6 = aN7 = 0.f;
                    aD = 0.f;
                    load8_h16(g_qh + (size_t)d * 128 + cb, qf);
                }
                float kf[8], vf[8];
                load8_h16(g_kh + (size_t)s * 128 + cb, kf);
                load8_h16(g_vh + (size_t)s * 128 + cb, vf);
                float part = qf[0] * (kf[0] + e8[0]) + qf[1] * (kf[1] + e8[1])
                           + qf[2] * (kf[2] + e8[2]) + qf[3] * (kf[3] + e8[3])
                           + qf[4] * (kf[4] + e8[4]) + qf[5] * (kf[5] + e8[5])
                           + qf[6] * (kf[6] + e8[6]) + qf[7] * (kf[7] + e8[7]);
                float full = part + __shfl_xor_sync(0xffffffffu, part, 1);
                float p = __expf(full * 0.25f);  // shift-free softmax (alpha is O(1))
                aN0 += p * (vf[0] + e8[0]); aN1 += p * (vf[1] + e8[1]);
                aN2 += p * (vf[2] + e8[2]); aN3 += p * (vf[3] + e8[3]);
                aN4 += p * (vf[4] + e8[4]); aN5 += p * (vf[5] + e8[5]);
                aN6 += p * (vf[6] + e8[6]); aN7 += p * (vf[7] + e8[7]);
                aD += p;
            }
            {
                float* np = g_numer + (size_t)cur_d * 128 + cb;
                red_add4(np,     aN0, aN1, aN2, aN3);
                red_add4(np + 4, aN4, aN5, aN6, aN7);
                if (!(tx & 1)) atomicAdd(g_denom + (size_t)cur_d * 8 + hd, aD);
            }
            BAR_ARRIVE(4 + b, 512);
        }
    }
}

// ---------------- node update ----------------
__global__ void update_h_kernel() {
    int gid = blockIdx.x * blockDim.x + threadIdx.x;
    if (gid >= N_NODES * 16) return;
    int n = gid >> 4, j = gid & 15, c0 = j * 8;
    float inv = 1.0f / (g_denom[n * 8 + (c0 >> 4)] + 1e-16f);
    float4 n0 = *(const float4*)(g_numer + (size_t)n * 128 + c0);
    float4 n1 = *(const float4*)(g_numer + (size_t)n * 128 + c0 + 4);
    float4 s0 = *(const float4*)(g_skip + (size_t)n * 128 + c0);
    float4 s1 = *(const float4*)(g_skip + (size_t)n * 128 + c0 + 4);
    float v[8];
    v[0] = fmaxf(n0.x * inv + s0.x, 0.f); v[1] = fmaxf(n0.y * inv + s0.y, 0.f);
    v[2] = fmaxf(n0.z * inv + s0.z, 0.f); v[3] = fmaxf(n0.w * inv + s0.w, 0.f);
    v[4] = fmaxf(n1.x * inv + s1.x, 0.f); v[5] = fmaxf(n1.y * inv + s1.y, 0.f);
    v[6] = fmaxf(n1.z * inv + s1.z, 0.f); v[7] = fmaxf(n1.w * inv + s1.w, 0.f);
    *(float4*)(g_h + (size_t)n * 128 + c0)     = make_float4(v[0], v[1], v[2], v[3]);
    *(float4*)(g_h + (size_t)n * 128 + c0 + 4) = make_float4(v[4], v[5], v[6], v[7]);
    store8_h16(g_himg + (size_t)(n >> 7) * TBYTES, (n & 127) * TROW + c0 * 2, v);
    float4 z = make_float4(0.f, 0.f, 0.f, 0.f);
    *(float4*)(g_numer + (size_t)n * 128 + c0)     = z;
    *(float4*)(g_numer + (size_t)n * 128 + c0 + 4) = z;
    if (!(j & 1)) g_denom[n * 8 + (j >> 1)] = 0.0f;
}

// ---------------- output GEMM ----------------
__global__ void out_gemm_kernel(const float* __restrict__ Wout, const float* __restrict__ bout,
                                float* __restrict__ out) {
    __shared__ float ws[128 * 16];
    __shared__ float hs[16 * 128];
    int tid = threadIdx.x;
    int row0 = blockIdx.x * 16;
#pragma unroll
    for (int it = 0; it < 8; ++it) {
        int idx = it * 256 + tid;
        ws[idx] = Wout[idx];
        int r = row0 + (idx >> 7);
        hs[idx] = (r < N_NODES) ? g_h[(size_t)row0 * 128 + idx] : 0.0f;
    }
    __syncthreads();
    int r = tid >> 4, c = tid & 15;
    float s = bout[c];
#pragma unroll 8
    for (int k = 0; k < 128; ++k) s += hs[r * 128 + k] * ws[k * 16 + c];
    int gr = row0 + r;
    if (gr < N_NODES) out[(size_t)gr * 16 + c] = s;
}

// ---------------- host ----------------
extern "C" void kernel_launch(void* const* d_in, const int* in_sizes, int n_in,
                              void* d_out, int out_size) {
    const float* x     = (const float*)d_in[0];
    const int*   nlu   = (const int*)  d_in[1];
    const int*   ei    = (const int*)  d_in[2];
    const float* eattr = (const float*)d_in[3];
    const int*   elu   = (const int*)  d_in[4];
    const float* Wq    = (const float*)d_in[5];
    const float* bq    = (const float*)d_in[6];
    const float* Wk    = (const float*)d_in[7];
    const float* bk    = (const float*)d_in[8];
    const float* Wv    = (const float*)d_in[9];
    const float* bv    = (const float*)d_in[10];
    const float* We    = (const float*)d_in[11];
    const float* Ws    = (const float*)d_in[12];
    const float* bs    = (const float*)d_in[13];
    const float* Wout  = (const float*)d_in[14];
    const float* bout  = (const float*)d_in[15];
    float* out = (float*)d_out;
    (void)in_sizes; (void)n_in; (void)out_size;

    cudaFuncSetAttribute(node_mma_kernel, cudaFuncAttributeMaxDynamicSharedMemorySize, SMEM_NODE);
    cudaFuncSetAttribute(edge_mma_kernel, cudaFuncAttributeMaxDynamicSharedMemorySize, SMEM_EDGE);

    zero_count_kernel<<<(N_NODES + 255) / 256, 256>>>();
    hist_kernel<<<(N_EDGES + 255) / 256, 256>>>(ei);
    scan_kernel<<<1, 1024>>>();
    scatter_kernel<<<(N_EDGES + 255) / 256, 256>>>(ei);

    build_h_kernel    <<<(N_NODES * 16 + 255) / 256, 256>>>(x, nlu);
    build_eaimg_kernel<<<(N_EDGES * 16 + 255) / 256, 256>>>(eattr, elu);
    prep_w_kernel     <<<(15 * 2048 + 255) / 256, 256>>>(Wq, Wk, Wv, Ws, We);

    for (int l = 0; l < 3; ++l) {
        node_mma_kernel<<<dim3(N_NTILE, 2), 256, SMEM_NODE>>>(bq, bk, bv, bs, l);
        edge_mma_kernel<<<148, 512, SMEM_EDGE>>>(l);
        update_h_kernel<<<(N_NODES * 16 + 255) / 256, 256>>>();
    }
    out_gemm_kernel<<<N_NODES / 16, 256>>>(Wout, bout, out);
}

// round 15
// speedup vs baseline: 2.0518x; 1.2432x over previous
#include <cuda_runtime.h>
#include <cuda_fp16.h>
#include <math.h>
#include <stdint.h>

#define N_NODES 100000
#define N_EDGES 800000
#define N_NTILE 782
#define N_ETILE 6250

// fp16 tile image: 128 rows x 136 fp16 (272B stride)
#define TROW 272
#define TBYTES 34816

// ---------------- device scratch ----------------
__device__ float g_h[(size_t)N_NODES * 128];
__device__ __half g_qh[(size_t)N_NODES * 128];
__device__ __half g_kh[(size_t)N_NODES * 128];
__device__ __half g_vh[(size_t)N_NODES * 128];
__device__ float g_skip[(size_t)N_NODES * 128];
__device__ float g_numer[(size_t)N_NODES * 128];
__device__ float g_denom[(size_t)N_NODES * 8];
__device__ unsigned char g_himg[(size_t)N_NTILE * TBYTES];    // h: fp16
__device__ unsigned char g_eaimg[(size_t)N_ETILE * TBYTES];   // ea: fp16
__device__ unsigned char g_wimg[(size_t)15 * TBYTES];         // W: fp16
// sort scratch
__device__ int g_count[N_NODES];
__device__ int g_off2[N_NODES];
__device__ int g_bsum[128];
__device__ int g_src_s[N_EDGES];
__device__ int g_dst_s[N_EDGES];
__device__ int g_perm[N_EDGES];

// ---------------- PTX helpers ----------------
__device__ __forceinline__ uint32_t smem_u32(const void* p) {
    uint32_t a;
    asm("{ .reg .u64 t; cvta.to.shared.u64 t, %1; cvt.u32.u64 %0, t; }" : "=r"(a) : "l"(p));
    return a;
}
__device__ __forceinline__ void ldsm4(uint32_t* r, uint32_t addr) {
    asm volatile("ldmatrix.sync.aligned.m8n8.x4.shared.b16 {%0,%1,%2,%3}, [%4];"
                 : "=r"(r[0]), "=r"(r[1]), "=r"(r[2]), "=r"(r[3]) : "r"(addr));
}
__device__ __forceinline__ void mma16816h(float* c, const uint32_t* a, uint32_t b0, uint32_t b1) {
    asm volatile("mma.sync.aligned.m16n8k16.row.col.f32.f16.f16.f32 "
                 "{%0,%1,%2,%3}, {%4,%5,%6,%7}, {%8,%9}, {%0,%1,%2,%3};"
                 : "+f"(c[0]), "+f"(c[1]), "+f"(c[2]), "+f"(c[3])
                 : "r"(a[0]), "r"(a[1]), "r"(a[2]), "r"(a[3]), "r"(b0), "r"(b1));
}
__device__ __forceinline__ void red_add4(float* addr, float a, float b, float c, float d) {
    asm volatile("red.global.add.v4.f32 [%0], {%1, %2, %3, %4};"
                 :: "l"(addr), "f"(a), "f"(b), "f"(c), "f"(d) : "memory");
}
__device__ __forceinline__ void cp_async16(uint32_t dst, const void* src) {
    asm volatile("cp.async.cg.shared.global [%0], [%1], 16;" :: "r"(dst), "l"(src));
}
#define CP_COMMIT() asm volatile("cp.async.commit_group;" ::: "memory")
#define CP_WAIT0()  asm volatile("cp.async.wait_group 0;" ::: "memory")
#define BAR_SYNC(id, n)   asm volatile("bar.sync %0, %1;"   :: "r"(id), "r"(n) : "memory")
#define BAR_ARRIVE(id, n) asm volatile("bar.arrive %0, %1;" :: "r"(id), "r"(n) : "memory")

__device__ __forceinline__ float pe_val(int t, int c) {
    int j = c >> 1;
    float freq = expf(-logf(10000.0f) * (float)(2 * j) * (1.0f / 16.0f));
    float ang = (float)t * freq;
    return (c & 1) ? cosf(ang) : sinf(ang);
}
// 8 floats -> 8 fp16 (16B) at img+off
__device__ __forceinline__ void store8_h16(unsigned char* img, int off, const float* v) {
    unsigned int h[4];
#pragma unroll
    for (int i = 0; i < 4; ++i) {
        __half h0 = __float2half_rn(v[2 * i]);
        __half h1 = __float2half_rn(v[2 * i + 1]);
        h[i] = (unsigned int)__half_as_ushort(h0) | ((unsigned int)__half_as_ushort(h1) << 16);
    }
    *(uint4*)(img + off) = make_uint4(h[0], h[1], h[2], h[3]);
}
// 16B of 8 fp16 -> 8 floats
__device__ __forceinline__ void cvt8_h16(uint4 raw, float* f) {
    const __half2* h2 = (const __half2*)&raw;
#pragma unroll
    for (int i = 0; i < 4; ++i) {
        float2 t = __half22float2(h2[i]);
        f[2 * i] = t.x;
        f[2 * i + 1] = t.y;
    }
}
__device__ __forceinline__ void load8_h16(const __half* p, float* f) {
    cvt8_h16(*(const uint4*)p, f);
}

// single-pass fp16 GEMM, 8-warp layout: warp (wr,wc) -> C[wr*32..+32][wc*64..+64]
__device__ __forceinline__ void gemm1(uint32_t aBase, uint32_t bBase,
                                      int lane, int wr, int wc, float c[2][8][4]) {
    int rA = lane & 15;
    int kA = (lane >> 4) << 3;
    int rB = ((lane >> 4) << 3) + (lane & 7);
    int kB = ((lane >> 3) & 1) << 3;
    uint32_t aRow = aBase + (uint32_t)(wr * 32 + rA) * TROW;
    uint32_t bRow = bBase + (uint32_t)(wc * 64 + rB) * TROW;
#pragma unroll
    for (int k16 = 0; k16 < 8; ++k16) {
        uint32_t ka = (uint32_t)(k16 * 16 + kA) * 2;
        uint32_t kb = (uint32_t)(k16 * 16 + kB) * 2;
        uint32_t a[2][4];
        ldsm4(a[0], aRow + ka);
        ldsm4(a[1], aRow + 16 * TROW + ka);
        uint32_t b[4][4];
#pragma unroll
        for (int p = 0; p < 4; ++p) ldsm4(b[p], bRow + p * 16 * TROW + kb);
#pragma unroll
        for (int t = 0; t < 2; ++t)
#pragma unroll
            for (int nt = 0; nt < 8; ++nt)
                mma16816h(c[t][nt], a[t], b[nt >> 1][(nt & 1) * 2], b[nt >> 1][(nt & 1) * 2 + 1]);
    }
}

// 32x32-chunk fp16 GEMM: warp wr rows [wr*32,+32), cols [colBase,+32), 32 accum regs
__device__ __forceinline__ void gemm_c32(uint32_t aBase, uint32_t bBase,
                                         int lane, int wr, int colBase, float c[2][4][4]) {
    int rA = lane & 15;
    int kA = (lane >> 4) << 3;
    int rB = ((lane >> 4) << 3) + (lane & 7);
    int kB = ((lane >> 3) & 1) << 3;
    uint32_t aRow = aBase + (uint32_t)(wr * 32 + rA) * TROW;
    uint32_t bRow = bBase + (uint32_t)(colBase + rB) * TROW;
#pragma unroll
    for (int k16 = 0; k16 < 8; ++k16) {
        uint32_t ka = (uint32_t)(k16 * 16 + kA) * 2;
        uint32_t kb = (uint32_t)(k16 * 16 + kB) * 2;
        uint32_t a[2][4];
        ldsm4(a[0], aRow + ka);
        ldsm4(a[1], aRow + 16 * TROW + ka);
        uint32_t b[2][4];
        ldsm4(b[0], bRow + kb);
        ldsm4(b[1], bRow + 16 * TROW + kb);
#pragma unroll
        for (int t = 0; t < 2; ++t)
#pragma unroll
            for (int nt = 0; nt < 4; ++nt)
                mma16816h(c[t][nt], a[t], b[nt >> 1][(nt & 1) * 2], b[nt >> 1][(nt & 1) * 2 + 1]);
    }
}

// ---------------- sort-by-dst ----------------
__global__ void zero_count_kernel() {
    int i = blockIdx.x * blockDim.x + threadIdx.x;
    if (i < N_NODES) g_count[i] = 0;
}
__global__ void hist_kernel(const int* __restrict__ ei) {
    int e = blockIdx.x * blockDim.x + threadIdx.x;
    if (e < N_EDGES) atomicAdd(&g_count[ei[N_EDGES + e]], 1);
}
// multi-block scan: pass1 (per-1024-chunk exclusive scan + block sum)
__global__ void scan_p1_kernel() {
    __shared__ int warp_sums[32];
    int tid = threadIdx.x;
    int lane = tid & 31, wid = tid >> 5;
    int idx = blockIdx.x * 1024 + tid;
    int v = (idx < N_NODES) ? g_count[idx] : 0;
    int inc = v;
#pragma unroll
    for (int o = 1; o < 32; o <<= 1) {
        int t = __shfl_up_sync(0xffffffffu, inc, o);
        if (lane >= o) inc += t;
    }
    if (lane == 31) warp_sums[wid] = inc;
    __syncthreads();
    if (wid == 0) {
        int w = warp_sums[lane];
        int wi = w;
#pragma unroll
        for (int o = 1; o < 32; o <<= 1) {
            int t = __shfl_up_sync(0xffffffffu, wi, o);
            if (lane >= o) wi += t;
        }
        warp_sums[lane] = wi - w;
    }
    __syncthreads();
    int ex = inc - v + warp_sums[wid];
    if (idx < N_NODES) g_off2[idx] = ex;
    if (tid == 1023) g_bsum[blockIdx.x] = ex + v;
}
__global__ void scan_p2_kernel(int nblocks) {
    if (threadIdx.x == 0) {
        int acc = 0;
        for (int i = 0; i < nblocks; ++i) {
            int t = g_bsum[i];
            g_bsum[i] = acc;
            acc += t;
        }
    }
}
__global__ void scan_p3_kernel() {
    int idx = blockIdx.x * 1024 + threadIdx.x;
    if (idx < N_NODES) g_off2[idx] += g_bsum[blockIdx.x];
}
__global__ void scatter_kernel(const int* __restrict__ ei) {
    int e = blockIdx.x * blockDim.x + threadIdx.x;
    if (e >= N_EDGES) return;
    int d = ei[N_EDGES + e];
    int pos = atomicAdd(&g_off2[d], 1);
    g_src_s[pos] = ei[e];
    g_dst_s[pos] = d;
    g_perm[pos] = e;
}

// ---------------- builders ----------------
__global__ void build_h_kernel(const float* __restrict__ x, const int* __restrict__ nlu) {
    int gid = blockIdx.x * blockDim.x + threadIdx.x;
    if (gid >= N_NODES * 16) return;
    int n = gid >> 4, j = gid & 15, c0 = j * 8;
    float v[8];
    if (c0 < 96) {
        float4 a = *(const float4*)(x + (size_t)n * 96 + c0);
        float4 b = *(const float4*)(x + (size_t)n * 96 + c0 + 4);
        v[0] = a.x; v[1] = a.y; v[2] = a.z; v[3] = a.w; v[4] = b.x; v[5] = b.y; v[6] = b.z; v[7] = b.w;
    } else {
        int t = nlu[n * 2 + ((c0 - 96) >> 4)];
        int cl = (c0 - 96) & 15;
#pragma unroll
        for (int i = 0; i < 8; ++i) v[i] = pe_val(t, cl + i);
    }
    store8_h16(g_himg + (size_t)(n >> 7) * TBYTES, (n & 127) * TROW + c0 * 2, v);
}
__global__ void build_eaimg_kernel(const float* __restrict__ eattr, const int* __restrict__ elu) {
    int gid = blockIdx.x * blockDim.x + threadIdx.x;
    if (gid >= N_EDGES * 16) return;
    int p = gid >> 4, j = gid & 15, c0 = j * 8;
    int e = g_perm[p];
    float v[8];
    if (c0 < 96) {
        float4 a = *(const float4*)(eattr + (size_t)e * 96 + c0);
        float4 b = *(const float4*)(eattr + (size_t)e * 96 + c0 + 4);
        v[0] = a.x; v[1] = a.y; v[2] = a.z; v[3] = a.w; v[4] = b.x; v[5] = b.y; v[6] = b.z; v[7] = b.w;
    } else {
        int t = elu[(size_t)e * 2 + ((c0 - 96) >> 4)];
        int cl = (c0 - 96) & 15;
#pragma unroll
        for (int i = 0; i < 8; ++i) v[i] = pe_val(t, cl + i);
    }
    store8_h16(g_eaimg + (size_t)(p >> 7) * TBYTES, (p & 127) * TROW + c0 * 2, v);
}
__global__ void prep_w_kernel(const float* __restrict__ Wq, const float* __restrict__ Wk,
                              const float* __restrict__ Wv, const float* __restrict__ Ws,
                              const float* __restrict__ We) {
    int gid = blockIdx.x * blockDim.x + threadIdx.x;
    if (gid >= 15 * 2048) return;
    int t = gid >> 11, rem = gid & 2047;
    int n = rem >> 4, j = rem & 15, k0 = j * 8;
    int l = t / 5, m = t % 5;
    const float* W = (m == 0) ? Wq : (m == 1) ? Wk : (m == 2) ? Wv : (m == 3) ? Ws : We;
    const float* base = W + (size_t)l * 16384;
    float v[8];
#pragma unroll
    for (int i = 0; i < 8; ++i) v[i] = base[(size_t)(k0 + i) * 128 + n];
    store8_h16(g_wimg + (size_t)t * TBYTES, n * TROW + k0 * 2, v);
}

// ---------------- node GEMM: single-pass fp16, q/k/v written as fp16 tables ----------------
#define OFF_NB 34816
#define OFF_NBIAS 69632
#define SMEM_NODE 70144
__global__ __launch_bounds__(256)
void node_mma_kernel(const float* __restrict__ bq, const float* __restrict__ bk,
                     const float* __restrict__ bv, const float* __restrict__ bsk, int layer) {
    extern __shared__ __align__(16) unsigned char smem[];
    uint32_t sb = smem_u32(smem);
    int tid = threadIdx.x, wid = tid >> 5, lane = tid & 31;
    int wr = wid & 3, wc = wid >> 2;
    int tile = blockIdx.x, ysel = blockIdx.y;
    int gi = lane >> 2, tig = lane & 3;

    const uint4* aimg = (const uint4*)(g_himg + (size_t)tile * TBYTES);
    uint4* sA = (uint4*)smem;
    for (int i = tid; i < 2176; i += 256) sA[i] = aimg[i];

    float* biasBuf = (float*)(smem + OFF_NBIAS);
    uint4* sB = (uint4*)(smem + OFF_NB);

    for (int w2 = 0; w2 < 2; ++w2) {
        int w = ysel * 2 + w2;
        __syncthreads();
        const uint4* bimg = (const uint4*)(g_wimg + (size_t)(layer * 5 + w) * TBYTES);
        for (int i = tid; i < 2176; i += 256) sB[i] = bimg[i];
        if (tid < 128) {
            const float* bias = (w == 0) ? bq : (w == 1) ? bk : (w == 2) ? bv : bsk;
            biasBuf[tid] = bias[layer * 128 + tid];
        }
        __syncthreads();

        float c[2][8][4];
#pragma unroll
        for (int t = 0; t < 2; ++t)
#pragma unroll
            for (int nt = 0; nt < 8; ++nt)
#pragma unroll
                for (int j = 0; j < 4; ++j) c[t][nt][j] = 0.0f;

        gemm1(sb, sb + OFF_NB, lane, wr, wc, c);

#pragma unroll
        for (int t = 0; t < 2; ++t) {
#pragma unroll
            for (int half = 0; half < 2; ++half) {
                int node = tile * 128 + wr * 32 + t * 16 + gi + half * 8;
                if (node < N_NODES) {
                    if (w < 3) {
                        __half* oph = ((w == 0) ? g_qh : (w == 1) ? g_kh : g_vh) + (size_t)node * 128;
#pragma unroll
                        for (int nt = 0; nt < 8; ++nt) {
                            int col = wc * 64 + nt * 8 + tig * 2;
                            *(__half2*)(oph + col) = __floats2half2_rn(c[t][nt][half * 2 + 0] + biasBuf[col],
                                                                       c[t][nt][half * 2 + 1] + biasBuf[col + 1]);
                        }
                    } else {
                        float* op = g_skip + (size_t)node * 128;
#pragma unroll
                        for (int nt = 0; nt < 8; ++nt) {
                            int col = wc * 64 + nt * 8 + tig * 2;
                            *(float2*)(op + col) = make_float2(c[t][nt][half * 2 + 0] + biasBuf[col],
                                                               c[t][nt][half * 2 + 1] + biasBuf[col + 1]);
                        }
                    }
                }
            }
        }
    }
}

// ---------------- edge kernel: 8 producer warps + 2x8 consumer-group warps ----------------
// smem: [0,34K) B | [34K,68K) A0 | [68K,102K) A1 | [102K,136K) est0 fp16 | [136K,170K) est1 fp16
// barriers: full[g]=2+g (prod arrive 256, group g sync 256), free[g]=4+g (group g arrive, prod sync), 6=prod-internal
#define EB_A0 34816
#define EB_EST0 104448
#define SMEM_EDGE 174080
__global__ __launch_bounds__(768)
void edge_mma_kernel(int layer) {
    extern __shared__ __align__(16) unsigned char smem[];
    uint32_t sb = smem_u32(smem);
    int tid = threadIdx.x, wid = tid >> 5, lane = tid & 31;

    // cooperative resident-B load
    const uint4* bimg = (const uint4*)(g_wimg + (size_t)(layer * 5 + 4) * TBYTES);
    uint4* sB = (uint4*)smem;
    for (int i = tid; i < 2176; i += 768) sB[i] = bimg[i];
    __syncthreads();

    if (wid < 8) {
        // ---- producers ----
        int wr = wid & 3, wc = wid >> 2;
        int gi = lane >> 2, tig = lane & 3;
        int idx = 0;
        for (int tile = blockIdx.x; tile < N_ETILE; tile += 148, ++idx) {
            int b = idx & 1;
            uint32_t aBuf = sb + EB_A0 + b * TBYTES;
            BAR_SYNC(4 + b, 512);
            const unsigned char* src = g_eaimg + (size_t)tile * TBYTES;
            for (int i = tid; i < 2176; i += 256)
                cp_async16(aBuf + i * 16, src + (size_t)i * 16);
            CP_COMMIT();
            CP_WAIT0();
            BAR_SYNC(6, 256);

            unsigned char* est = smem + EB_EST0 + b * TBYTES;
#pragma unroll
            for (int h = 0; h < 2; ++h) {
                int colBase = wc * 64 + h * 32;
                float c[2][4][4];
#pragma unroll
                for (int t = 0; t < 2; ++t)
#pragma unroll
                    for (int nt = 0; nt < 4; ++nt)
#pragma unroll
                        for (int j = 0; j < 4; ++j) c[t][nt][j] = 0.0f;

                gemm_c32(aBuf, sb, lane, wr, colBase, c);

#pragma unroll
                for (int t = 0; t < 2; ++t)
#pragma unroll
                    for (int half = 0; half < 2; ++half) {
                        int r = wr * 32 + t * 16 + gi + half * 8;
#pragma unroll
                        for (int nt = 0; nt < 4; ++nt) {
                            int col = colBase + nt * 8 + tig * 2;
                            *(__half2*)(est + r * TROW + col * 2) =
                                __floats2half2_rn(c[t][nt][half * 2], c[t][nt][half * 2 + 1]);
                        }
                    }
            }
            BAR_ARRIVE(2 + b, 512);
        }
    } else {
        // ---- consumer group g consumes buffer g, tiles with idx%2==g ----
        int g = (wid >= 16) ? 1 : 0;
        int gtid = tid & 255;
        int tx = gtid & 15, ty = gtid >> 4;
        int hd = tx >> 1, cb = tx << 3;
        const unsigned char* est = smem + EB_EST0 + g * TBYTES;
        BAR_ARRIVE(4 + g, 512);
        for (int tile = blockIdx.x + g * 148; tile < N_ETILE; tile += 296) {
            BAR_SYNC(2 + g, 512);
            int e0 = tile << 7;

            int cur_d = -1;
            float qf[8];
            float aN0 = 0.f, aN1 = 0.f, aN2 = 0.f, aN3 = 0.f;
            float aN4 = 0.f, aN5 = 0.f, aN6 = 0.f, aN7 = 0.f;
            float aD = 0.f;
#pragma unroll
            for (int i = 0; i < 8; ++i) {
                int er = ty * 8 + i;
                float e8[8];
                cvt8_h16(*(const uint4*)(est + er * TROW + cb * 2), e8);
                int s = g_src_s[e0 + er];
                int d = g_dst_s[e0 + er];
                if (d != cur_d) {
                    if (cur_d >= 0) {
                        float* np = g_numer + (size_t)cur_d * 128 + cb;
                        red_add4(np,     aN0, aN1, aN2, aN3);
                        red_add4(np + 4, aN4, aN5, aN6, aN7);
                        if (!(tx & 1)) atomicAdd(g_denom + (size_t)cur_d * 8 + hd, aD);
                    }
                    cur_d = d;
                    aN0 = aN1 = aN2 = aN3 = aN4 = aN5 = aN6 = aN7 = 0.f;
                    aD = 0.f;
                    load8_h16(g_qh + (size_t)d * 128 + cb, qf);
                }
                float kf[8], vf[8];
                load8_h16(g_kh + (size_t)s * 128 + cb, kf);
                load8_h16(g_vh + (size_t)s * 128 + cb, vf);
                float part = qf[0] * (kf[0] + e8[0]) + qf[1] * (kf[1] + e8[1])
                           + qf[2] * (kf[2] + e8[2]) + qf[3] * (kf[3] + e8[3])
                           + qf[4] * (kf[4] + e8[4]) + qf[5] * (kf[5] + e8[5])
                           + qf[6] * (kf[6] + e8[6]) + qf[7] * (kf[7] + e8[7]);
                float full = part + __shfl_xor_sync(0xffffffffu, part, 1);
                float p = __expf(full * 0.25f);  // shift-free softmax (alpha is O(1))
                aN0 += p * (vf[0] + e8[0]); aN1 += p * (vf[1] + e8[1]);
                aN2 += p * (vf[2] + e8[2]); aN3 += p * (vf[3] + e8[3]);
                aN4 += p * (vf[4] + e8[4]); aN5 += p * (vf[5] + e8[5]);
                aN6 += p * (vf[6] + e8[6]); aN7 += p * (vf[7] + e8[7]);
                aD += p;
            }
            {
                float* np = g_numer + (size_t)cur_d * 128 + cb;
                red_add4(np,     aN0, aN1, aN2, aN3);
                red_add4(np + 4, aN4, aN5, aN6, aN7);
                if (!(tx & 1)) atomicAdd(g_denom + (size_t)cur_d * 8 + hd, aD);
            }
            BAR_ARRIVE(4 + g, 512);
        }
    }
}

// ---------------- node update ----------------
__global__ void update_h_kernel() {
    int gid = blockIdx.x * blockDim.x + threadIdx.x;
    if (gid >= N_NODES * 16) return;
    int n = gid >> 4, j = gid & 15, c0 = j * 8;
    float inv = 1.0f / (g_denom[n * 8 + (c0 >> 4)] + 1e-16f);
    float4 n0 = *(const float4*)(g_numer + (size_t)n * 128 + c0);
    float4 n1 = *(const float4*)(g_numer + (size_t)n * 128 + c0 + 4);
    float4 s0 = *(const float4*)(g_skip + (size_t)n * 128 + c0);
    float4 s1 = *(const float4*)(g_skip + (size_t)n * 128 + c0 + 4);
    float v[8];
    v[0] = fmaxf(n0.x * inv + s0.x, 0.f); v[1] = fmaxf(n0.y * inv + s0.y, 0.f);
    v[2] = fmaxf(n0.z * inv + s0.z, 0.f); v[3] = fmaxf(n0.w * inv + s0.w, 0.f);
    v[4] = fmaxf(n1.x * inv + s1.x, 0.f); v[5] = fmaxf(n1.y * inv + s1.y, 0.f);
    v[6] = fmaxf(n1.z * inv + s1.z, 0.f); v[7] = fmaxf(n1.w * inv + s1.w, 0.f);
    *(float4*)(g_h + (size_t)n * 128 + c0)     = make_float4(v[0], v[1], v[2], v[3]);
    *(float4*)(g_h + (size_t)n * 128 + c0 + 4) = make_float4(v[4], v[5], v[6], v[7]);
    store8_h16(g_himg + (size_t)(n >> 7) * TBYTES, (n & 127) * TROW + c0 * 2, v);
    float4 z = make_float4(0.f, 0.f, 0.f, 0.f);
    *(float4*)(g_numer + (size_t)n * 128 + c0)     = z;
    *(float4*)(g_numer + (size_t)n * 128 + c0 + 4) = z;
    if (!(j & 1)) g_denom[n * 8 + (j >> 1)] = 0.0f;
}

// ---------------- output GEMM ----------------
__global__ void out_gemm_kernel(const float* __restrict__ Wout, const float* __restrict__ bout,
                                float* __restrict__ out) {
    __shared__ float ws[128 * 16];
    __shared__ float hs[16 * 128];
    int tid = threadIdx.x;
    int row0 = blockIdx.x * 16;
#pragma unroll
    for (int it = 0; it < 8; ++it) {
        int idx = it * 256 + tid;
        ws[idx] = Wout[idx];
        int r = row0 + (idx >> 7);
        hs[idx] = (r < N_NODES) ? g_h[(size_t)row0 * 128 + idx] : 0.0f;
    }
    __syncthreads();
    int r = tid >> 4, c = tid & 15;
    float s = bout[c];
#pragma unroll 8
    for (int k = 0; k < 128; ++k) s += hs[r * 128 + k] * ws[k * 16 + c];
    int gr = row0 + r;
    if (gr < N_NODES) out[(size_t)gr * 16 + c] = s;
}

// ---------------- host ----------------
extern "C" void kernel_launch(void* const* d_in, const int* in_sizes, int n_in,
                              void* d_out, int out_size) {
    const float* x     = (const float*)d_in[0];
    const int*   nlu   = (const int*)  d_in[1];
    const int*   ei    = (const int*)  d_in[2];
    const float* eattr = (const float*)d_in[3];
    const int*   elu   = (const int*)  d_in[4];
    const float* Wq    = (const float*)d_in[5];
    const float* bq    = (const float*)d_in[6];
    const float* Wk    = (const float*)d_in[7];
    const float* bk    = (const float*)d_in[8];
    const float* Wv    = (const float*)d_in[9];
    const float* bv    = (const float*)d_in[10];
    const float* We    = (const float*)d_in[11];
    const float* Ws    = (const float*)d_in[12];
    const float* bs    = (const float*)d_in[13];
    const float* Wout  = (const float*)d_in[14];
    const float* bout  = (const float*)d_in[15];
    float* out = (float*)d_out;
    (void)in_sizes; (void)n_in; (void)out_size;

    cudaFuncSetAttribute(node_mma_kernel, cudaFuncAttributeMaxDynamicSharedMemorySize, SMEM_NODE);
    cudaFuncSetAttribute(edge_mma_kernel, cudaFuncAttributeMaxDynamicSharedMemorySize, SMEM_EDGE);

    const int SCAN_BLOCKS = (N_NODES + 1023) / 1024;   // 98
    zero_count_kernel<<<(N_NODES + 255) / 256, 256>>>();
    hist_kernel<<<(N_EDGES + 255) / 256, 256>>>(ei);
    scan_p1_kernel<<<SCAN_BLOCKS, 1024>>>();
    scan_p2_kernel<<<1, 32>>>(SCAN_BLOCKS);
    scan_p3_kernel<<<SCAN_BLOCKS, 1024>>>();
    scatter_kernel<<<(N_EDGES + 255) / 256, 256>>>(ei);

    build_h_kernel    <<<(N_NODES * 16 + 255) / 256, 256>>>(x, nlu);
    build_eaimg_kernel<<<(N_EDGES * 16 + 255) / 256, 256>>>(eattr, elu);
    prep_w_kernel     <<<(15 * 2048 + 255) / 256, 256>>>(Wq, Wk, Wv, Ws, We);

    for (int l = 0; l < 3; ++l) {
        node_mma_kernel<<<dim3(N_NTILE, 2), 256, SMEM_NODE>>>(bq, bk, bv, bs, l);
        edge_mma_kernel<<<148, 768, SMEM_EDGE>>>(l);
        update_h_kernel<<<(N_NODES * 16 + 255) / 256, 256>>>();
    }
    out_gemm_kernel<<<N_NODES / 16, 256>>>(Wout, bout, out);
}

// round 16
// speedup vs baseline: 2.1360x; 1.0410x over previous
#include <cuda_runtime.h>
#include <cuda_fp16.h>
#include <math.h>
#include <stdint.h>

#define N_NODES 100000
#define N_EDGES 800000
#define N_NTILE 782
#define N_ETILE 6250

// fp16 tile image: 128 rows x 136 fp16 (272B stride)
#define TROW 272
#define TBYTES 34816

// ---------------- device scratch ----------------
__device__ __half g_qh[(size_t)N_NODES * 128];
__device__ __half g_kvh[(size_t)N_NODES * 256];   // interleaved: node*256 + (col/8)*16 + col%8 (k), +8 (v)
__device__ float g_skip[(size_t)N_NODES * 128];
__device__ float g_numer[(size_t)N_NODES * 128];
__device__ float g_denom[(size_t)N_NODES * 8];
__device__ unsigned char g_himg[(size_t)N_NTILE * TBYTES];    // h: fp16 (GEMM A + out_gemm input)
__device__ unsigned char g_eaimg[(size_t)N_ETILE * TBYTES];   // ea: fp16
__device__ unsigned char g_wimg[(size_t)15 * TBYTES];         // W: fp16
// sort scratch
__device__ int g_count[N_NODES];
__device__ int g_off2[N_NODES];
__device__ int g_bsum[128];
__device__ int g_src_s[N_EDGES];
__device__ int g_dst_s[N_EDGES];
__device__ int g_perm[N_EDGES];

// ---------------- PTX helpers ----------------
__device__ __forceinline__ uint32_t smem_u32(const void* p) {
    uint32_t a;
    asm("{ .reg .u64 t; cvta.to.shared.u64 t, %1; cvt.u32.u64 %0, t; }" : "=r"(a) : "l"(p));
    return a;
}
__device__ __forceinline__ void ldsm4(uint32_t* r, uint32_t addr) {
    asm volatile("ldmatrix.sync.aligned.m8n8.x4.shared.b16 {%0,%1,%2,%3}, [%4];"
                 : "=r"(r[0]), "=r"(r[1]), "=r"(r[2]), "=r"(r[3]) : "r"(addr));
}
__device__ __forceinline__ void mma16816h(float* c, const uint32_t* a, uint32_t b0, uint32_t b1) {
    asm volatile("mma.sync.aligned.m16n8k16.row.col.f32.f16.f16.f32 "
                 "{%0,%1,%2,%3}, {%4,%5,%6,%7}, {%8,%9}, {%0,%1,%2,%3};"
                 : "+f"(c[0]), "+f"(c[1]), "+f"(c[2]), "+f"(c[3])
                 : "r"(a[0]), "r"(a[1]), "r"(a[2]), "r"(a[3]), "r"(b0), "r"(b1));
}
__device__ __forceinline__ void red_add4(float* addr, float a, float b, float c, float d) {
    asm volatile("red.global.add.v4.f32 [%0], {%1, %2, %3, %4};"
                 :: "l"(addr), "f"(a), "f"(b), "f"(c), "f"(d) : "memory");
}
__device__ __forceinline__ void cp_async16(uint32_t dst, const void* src) {
    asm volatile("cp.async.cg.shared.global [%0], [%1], 16;" :: "r"(dst), "l"(src));
}
#define CP_COMMIT() asm volatile("cp.async.commit_group;" ::: "memory")
#define CP_WAIT0()  asm volatile("cp.async.wait_group 0;" ::: "memory")
#define BAR_SYNC(id, n)   asm volatile("bar.sync %0, %1;"   :: "r"(id), "r"(n) : "memory")
#define BAR_ARRIVE(id, n) asm volatile("bar.arrive %0, %1;" :: "r"(id), "r"(n) : "memory")

__device__ __forceinline__ float pe_val(int t, int c) {
    int j = c >> 1;
    float freq = expf(-logf(10000.0f) * (float)(2 * j) * (1.0f / 16.0f));
    float ang = (float)t * freq;
    return (c & 1) ? cosf(ang) : sinf(ang);
}
__device__ __forceinline__ void store8_h16(unsigned char* img, int off, const float* v) {
    unsigned int h[4];
#pragma unroll
    for (int i = 0; i < 4; ++i) {
        __half h0 = __float2half_rn(v[2 * i]);
        __half h1 = __float2half_rn(v[2 * i + 1]);
        h[i] = (unsigned int)__half_as_ushort(h0) | ((unsigned int)__half_as_ushort(h1) << 16);
    }
    *(uint4*)(img + off) = make_uint4(h[0], h[1], h[2], h[3]);
}
__device__ __forceinline__ void cvt8_h16(uint4 raw, float* f) {
    const __half2* h2 = (const __half2*)&raw;
#pragma unroll
    for (int i = 0; i < 4; ++i) {
        float2 t = __half22float2(h2[i]);
        f[2 * i] = t.x;
        f[2 * i + 1] = t.y;
    }
}
__device__ __forceinline__ void load8_h16(const __half* p, float* f) {
    cvt8_h16(*(const uint4*)p, f);
}

// single-pass fp16 GEMM, 8-warp layout: warp (wr,wc) -> C[wr*32..+32][wc*64..+64]
__device__ __forceinline__ void gemm1(uint32_t aBase, uint32_t bBase,
                                      int lane, int wr, int wc, float c[2][8][4]) {
    int rA = lane & 15;
    int kA = (lane >> 4) << 3;
    int rB = ((lane >> 4) << 3) + (lane & 7);
    int kB = ((lane >> 3) & 1) << 3;
    uint32_t aRow = aBase + (uint32_t)(wr * 32 + rA) * TROW;
    uint32_t bRow = bBase + (uint32_t)(wc * 64 + rB) * TROW;
#pragma unroll
    for (int k16 = 0; k16 < 8; ++k16) {
        uint32_t ka = (uint32_t)(k16 * 16 + kA) * 2;
        uint32_t kb = (uint32_t)(k16 * 16 + kB) * 2;
        uint32_t a[2][4];
        ldsm4(a[0], aRow + ka);
        ldsm4(a[1], aRow + 16 * TROW + ka);
        uint32_t b[4][4];
#pragma unroll
        for (int p = 0; p < 4; ++p) ldsm4(b[p], bRow + p * 16 * TROW + kb);
#pragma unroll
        for (int t = 0; t < 2; ++t)
#pragma unroll
            for (int nt = 0; nt < 8; ++nt)
                mma16816h(c[t][nt], a[t], b[nt >> 1][(nt & 1) * 2], b[nt >> 1][(nt & 1) * 2 + 1]);
    }
}

// 32x32-chunk fp16 GEMM: warp wr rows [wr*32,+32), cols [colBase,+32), 32 accum regs
__device__ __forceinline__ void gemm_c32(uint32_t aBase, uint32_t bBase,
                                         int lane, int wr, int colBase, float c[2][4][4]) {
    int rA = lane & 15;
    int kA = (lane >> 4) << 3;
    int rB = ((lane >> 4) << 3) + (lane & 7);
    int kB = ((lane >> 3) & 1) << 3;
    uint32_t aRow = aBase + (uint32_t)(wr * 32 + rA) * TROW;
    uint32_t bRow = bBase + (uint32_t)(colBase + rB) * TROW;
#pragma unroll
    for (int k16 = 0; k16 < 8; ++k16) {
        uint32_t ka = (uint32_t)(k16 * 16 + kA) * 2;
        uint32_t kb = (uint32_t)(k16 * 16 + kB) * 2;
        uint32_t a[2][4];
        ldsm4(a[0], aRow + ka);
        ldsm4(a[1], aRow + 16 * TROW + ka);
        uint32_t b[2][4];
        ldsm4(b[0], bRow + kb);
        ldsm4(b[1], bRow + 16 * TROW + kb);
#pragma unroll
        for (int t = 0; t < 2; ++t)
#pragma unroll
            for (int nt = 0; nt < 4; ++nt)
                mma16816h(c[t][nt], a[t], b[nt >> 1][(nt & 1) * 2], b[nt >> 1][(nt & 1) * 2 + 1]);
    }
}

// ---------------- sort-by-dst ----------------
__global__ void zero_count_kernel() {
    int i = blockIdx.x * blockDim.x + threadIdx.x;
    if (i < N_NODES) g_count[i] = 0;
}
__global__ void hist_kernel(const int* __restrict__ ei) {
    int e = blockIdx.x * blockDim.x + threadIdx.x;
    if (e < N_EDGES) atomicAdd(&g_count[ei[N_EDGES + e]], 1);
}
__global__ void scan_p1_kernel() {
    __shared__ int warp_sums[32];
    int tid = threadIdx.x;
    int lane = tid & 31, wid = tid >> 5;
    int idx = blockIdx.x * 1024 + tid;
    int v = (idx < N_NODES) ? g_count[idx] : 0;
    int inc = v;
#pragma unroll
    for (int o = 1; o < 32; o <<= 1) {
        int t = __shfl_up_sync(0xffffffffu, inc, o);
        if (lane >= o) inc += t;
    }
    if (lane == 31) warp_sums[wid] = inc;
    __syncthreads();
    if (wid == 0) {
        int w = warp_sums[lane];
        int wi = w;
#pragma unroll
        for (int o = 1; o < 32; o <<= 1) {
            int t = __shfl_up_sync(0xffffffffu, wi, o);
            if (lane >= o) wi += t;
        }
        warp_sums[lane] = wi - w;
    }
    __syncthreads();
    int ex = inc - v + warp_sums[wid];
    if (idx < N_NODES) g_off2[idx] = ex;
    if (tid == 1023) g_bsum[blockIdx.x] = ex + v;
}
__global__ void scan_p2_kernel(int nblocks) {
    if (threadIdx.x == 0) {
        int acc = 0;
        for (int i = 0; i < nblocks; ++i) {
            int t = g_bsum[i];
            g_bsum[i] = acc;
            acc += t;
        }
    }
}
__global__ void scan_p3_kernel() {
    int idx = blockIdx.x * 1024 + threadIdx.x;
    if (idx < N_NODES) g_off2[idx] += g_bsum[blockIdx.x];
}
__global__ void scatter_kernel(const int* __restrict__ ei) {
    int e = blockIdx.x * blockDim.x + threadIdx.x;
    if (e >= N_EDGES) return;
    int d = ei[N_EDGES + e];
    int pos = atomicAdd(&g_off2[d], 1);
    g_src_s[pos] = ei[e];
    g_dst_s[pos] = d;
    g_perm[pos] = e;
}

// ---------------- builders ----------------
__global__ void build_h_kernel(const float* __restrict__ x, const int* __restrict__ nlu) {
    int gid = blockIdx.x * blockDim.x + threadIdx.x;
    if (gid >= N_NODES * 16) return;
    int n = gid >> 4, j = gid & 15, c0 = j * 8;
    float v[8];
    if (c0 < 96) {
        float4 a = *(const float4*)(x + (size_t)n * 96 + c0);
        float4 b = *(const float4*)(x + (size_t)n * 96 + c0 + 4);
        v[0] = a.x; v[1] = a.y; v[2] = a.z; v[3] = a.w; v[4] = b.x; v[5] = b.y; v[6] = b.z; v[7] = b.w;
    } else {
        int t = nlu[n * 2 + ((c0 - 96) >> 4)];
        int cl = (c0 - 96) & 15;
#pragma unroll
        for (int i = 0; i < 8; ++i) v[i] = pe_val(t, cl + i);
    }
    store8_h16(g_himg + (size_t)(n >> 7) * TBYTES, (n & 127) * TROW + c0 * 2, v);
}
__global__ void build_eaimg_kernel(const float* __restrict__ eattr, const int* __restrict__ elu) {
    int gid = blockIdx.x * blockDim.x + threadIdx.x;
    if (gid >= N_EDGES * 16) return;
    int p = gid >> 4, j = gid & 15, c0 = j * 8;
    int e = g_perm[p];
    float v[8];
    if (c0 < 96) {
        float4 a = *(const float4*)(eattr + (size_t)e * 96 + c0);
        float4 b = *(const float4*)(eattr + (size_t)e * 96 + c0 + 4);
        v[0] = a.x; v[1] = a.y; v[2] = a.z; v[3] = a.w; v[4] = b.x; v[5] = b.y; v[6] = b.z; v[7] = b.w;
    } else {
        int t = elu[(size_t)e * 2 + ((c0 - 96) >> 4)];
        int cl = (c0 - 96) & 15;
#pragma unroll
        for (int i = 0; i < 8; ++i) v[i] = pe_val(t, cl + i);
    }
    store8_h16(g_eaimg + (size_t)(p >> 7) * TBYTES, (p & 127) * TROW + c0 * 2, v);
}
__global__ void prep_w_kernel(const float* __restrict__ Wq, const float* __restrict__ Wk,
                              const float* __restrict__ Wv, const float* __restrict__ Ws,
                              const float* __restrict__ We) {
    int gid = blockIdx.x * blockDim.x + threadIdx.x;
    if (gid >= 15 * 2048) return;
    int t = gid >> 11, rem = gid & 2047;
    int n = rem >> 4, j = rem & 15, k0 = j * 8;
    int l = t / 5, m = t % 5;
    const float* W = (m == 0) ? Wq : (m == 1) ? Wk : (m == 2) ? Wv : (m == 3) ? Ws : We;
    const float* base = W + (size_t)l * 16384;
    float v[8];
#pragma unroll
    for (int i = 0; i < 8; ++i) v[i] = base[(size_t)(k0 + i) * 128 + n];
    store8_h16(g_wimg + (size_t)t * TBYTES, n * TROW + k0 * 2, v);
}

// ---------------- node GEMM: single-pass fp16; q -> g_qh, k/v -> interleaved g_kvh ----------------
#define OFF_NB 34816
#define OFF_NBIAS 69632
#define SMEM_NODE 70144
__global__ __launch_bounds__(256)
void node_mma_kernel(const float* __restrict__ bq, const float* __restrict__ bk,
                     const float* __restrict__ bv, const float* __restrict__ bsk, int layer) {
    extern __shared__ __align__(16) unsigned char smem[];
    uint32_t sb = smem_u32(smem);
    int tid = threadIdx.x, wid = tid >> 5, lane = tid & 31;
    int wr = wid & 3, wc = wid >> 2;
    int tile = blockIdx.x, ysel = blockIdx.y;
    int gi = lane >> 2, tig = lane & 3;

    const uint4* aimg = (const uint4*)(g_himg + (size_t)tile * TBYTES);
    uint4* sA = (uint4*)smem;
    for (int i = tid; i < 2176; i += 256) sA[i] = aimg[i];

    float* biasBuf = (float*)(smem + OFF_NBIAS);
    uint4* sB = (uint4*)(smem + OFF_NB);

    for (int w2 = 0; w2 < 2; ++w2) {
        int w = ysel * 2 + w2;
        __syncthreads();
        const uint4* bimg = (const uint4*)(g_wimg + (size_t)(layer * 5 + w) * TBYTES);
        for (int i = tid; i < 2176; i += 256) sB[i] = bimg[i];
        if (tid < 128) {
            const float* bias = (w == 0) ? bq : (w == 1) ? bk : (w == 2) ? bv : bsk;
            biasBuf[tid] = bias[layer * 128 + tid];
        }
        __syncthreads();

        float c[2][8][4];
#pragma unroll
        for (int t = 0; t < 2; ++t)
#pragma unroll
            for (int nt = 0; nt < 8; ++nt)
#pragma unroll
                for (int j = 0; j < 4; ++j) c[t][nt][j] = 0.0f;

        gemm1(sb, sb + OFF_NB, lane, wr, wc, c);

#pragma unroll
        for (int t = 0; t < 2; ++t) {
#pragma unroll
            for (int half = 0; half < 2; ++half) {
                int node = tile * 128 + wr * 32 + t * 16 + gi + half * 8;
                if (node < N_NODES) {
                    if (w == 0) {
                        __half* oph = g_qh + (size_t)node * 128;
#pragma unroll
                        for (int nt = 0; nt < 8; ++nt) {
                            int col = wc * 64 + nt * 8 + tig * 2;
                            *(__half2*)(oph + col) = __floats2half2_rn(c[t][nt][half * 2 + 0] + biasBuf[col],
                                                                       c[t][nt][half * 2 + 1] + biasBuf[col + 1]);
                        }
                    } else if (w < 3) {
                        // k (w==1) -> chunk offset 0; v (w==2) -> chunk offset 8
                        __half* oph = g_kvh + (size_t)node * 256 + (w == 2 ? 8 : 0);
#pragma unroll
                        for (int nt = 0; nt < 8; ++nt) {
                            int col = wc * 64 + nt * 8 + tig * 2;
                            *(__half2*)(oph + (col >> 3) * 16 + (col & 7)) =
                                __floats2half2_rn(c[t][nt][half * 2 + 0] + biasBuf[col],
                                                  c[t][nt][half * 2 + 1] + biasBuf[col + 1]);
                        }
                    } else {
                        float* op = g_skip + (size_t)node * 128;
#pragma unroll
                        for (int nt = 0; nt < 8; ++nt) {
                            int col = wc * 64 + nt * 8 + tig * 2;
                            *(float2*)(op + col) = make_float2(c[t][nt][half * 2 + 0] + biasBuf[col],
                                                               c[t][nt][half * 2 + 1] + biasBuf[col + 1]);
                        }
                    }
                }
            }
        }
    }
}

// ---------------- edge kernel: 8 producer warps + 2x8 consumer-group warps ----------------
// smem: [0,34K) B | [34K,68K) A0 | [68K,102K) A1 | [102K,136K) est0 fp16 | [136K,170K) est1 fp16
#define EB_A0 34816
#define EB_EST0 104448
#define SMEM_EDGE 174080
__global__ __launch_bounds__(768)
void edge_mma_kernel(int layer) {
    extern __shared__ __align__(16) unsigned char smem[];
    uint32_t sb = smem_u32(smem);
    int tid = threadIdx.x, wid = tid >> 5, lane = tid & 31;

    const uint4* bimg = (const uint4*)(g_wimg + (size_t)(layer * 5 + 4) * TBYTES);
    uint4* sB = (uint4*)smem;
    for (int i = tid; i < 2176; i += 768) sB[i] = bimg[i];
    __syncthreads();

    if (wid < 8) {
        // ---- producers ----
        int wr = wid & 3, wc = wid >> 2;
        int gi = lane >> 2, tig = lane & 3;
        int idx = 0;
        for (int tile = blockIdx.x; tile < N_ETILE; tile += 148, ++idx) {
            int b = idx & 1;
            uint32_t aBuf = sb + EB_A0 + b * TBYTES;
            BAR_SYNC(4 + b, 512);
            const unsigned char* src = g_eaimg + (size_t)tile * TBYTES;
            for (int i = tid; i < 2176; i += 256)
                cp_async16(aBuf + i * 16, src + (size_t)i * 16);
            CP_COMMIT();
            CP_WAIT0();
            BAR_SYNC(6, 256);

            unsigned char* est = smem + EB_EST0 + b * TBYTES;
#pragma unroll
            for (int h = 0; h < 2; ++h) {
                int colBase = wc * 64 + h * 32;
                float c[2][4][4];
#pragma unroll
                for (int t = 0; t < 2; ++t)
#pragma unroll
                    for (int nt = 0; nt < 4; ++nt)
#pragma unroll
                        for (int j = 0; j < 4; ++j) c[t][nt][j] = 0.0f;

                gemm_c32(aBuf, sb, lane, wr, colBase, c);

#pragma unroll
                for (int t = 0; t < 2; ++t)
#pragma unroll
                    for (int half = 0; half < 2; ++half) {
                        int r = wr * 32 + t * 16 + gi + half * 8;
#pragma unroll
                        for (int nt = 0; nt < 4; ++nt) {
                            int col = colBase + nt * 8 + tig * 2;
                            *(__half2*)(est + r * TROW + col * 2) =
                                __floats2half2_rn(c[t][nt][half * 2], c[t][nt][half * 2 + 1]);
                        }
                    }
            }
            BAR_ARRIVE(2 + b, 512);
        }
    } else {
        // ---- consumer group g consumes buffer g, tiles with idx%2==g ----
        int g = (wid >= 16) ? 1 : 0;
        int gtid = tid & 255;
        int tx = gtid & 15, ty = gtid >> 4;
        int hd = tx >> 1, cb = tx << 3;
        const unsigned char* est = smem + EB_EST0 + g * TBYTES;
        BAR_ARRIVE(4 + g, 512);
        for (int tile = blockIdx.x + g * 148; tile < N_ETILE; tile += 296) {
            BAR_SYNC(2 + g, 512);
            int e0 = tile << 7;

            int cur_d = -1;
            float qf[8];
            float aN0 = 0.f, aN1 = 0.f, aN2 = 0.f, aN3 = 0.f;
            float aN4 = 0.f, aN5 = 0.f, aN6 = 0.f, aN7 = 0.f;
            float aD = 0.f;
#pragma unroll
            for (int i = 0; i < 8; ++i) {
                int er = ty * 8 + i;
                float e8[8];
                cvt8_h16(*(const uint4*)(est + er * TROW + cb * 2), e8);
                int s = g_src_s[e0 + er];
                int d = g_dst_s[e0 + er];
                if (d != cur_d) {
                    if (cur_d >= 0) {
                        float* np = g_numer + (size_t)cur_d * 128 + cb;
                        red_add4(np,     aN0, aN1, aN2, aN3);
                        red_add4(np + 4, aN4, aN5, aN6, aN7);
                        if (!(tx & 1)) atomicAdd(g_denom + (size_t)cur_d * 8 + hd, aD);
                    }
                    cur_d = d;
                    aN0 = aN1 = aN2 = aN3 = aN4 = aN5 = aN6 = aN7 = 0.f;
                    aD = 0.f;
                    load8_h16(g_qh + (size_t)d * 128 + cb, qf);
                }
                // k and v chunks are adjacent 16B blocks -> one 32B L2 sector
                const __half* kvp = g_kvh + (size_t)s * 256 + tx * 16;
                float kf[8], vf[8];
                load8_h16(kvp, kf);
                load8_h16(kvp + 8, vf);
                float part = qf[0] * (kf[0] + e8[0]) + qf[1] * (kf[1] + e8[1])
                           + qf[2] * (kf[2] + e8[2]) + qf[3] * (kf[3] + e8[3])
                           + qf[4] * (kf[4] + e8[4]) + qf[5] * (kf[5] + e8[5])
                           + qf[6] * (kf[6] + e8[6]) + qf[7] * (kf[7] + e8[7]);
                float full = part + __shfl_xor_sync(0xffffffffu, part, 1);
                float p = __expf(full * 0.25f);  // shift-free softmax (alpha is O(1))
                aN0 += p * (vf[0] + e8[0]); aN1 += p * (vf[1] + e8[1]);
                aN2 += p * (vf[2] + e8[2]); aN3 += p * (vf[3] + e8[3]);
                aN4 += p * (vf[4] + e8[4]); aN5 += p * (vf[5] + e8[5]);
                aN6 += p * (vf[6] + e8[6]); aN7 += p * (vf[7] + e8[7]);
                aD += p;
            }
            {
                float* np = g_numer + (size_t)cur_d * 128 + cb;
                red_add4(np,     aN0, aN1, aN2, aN3);
                red_add4(np + 4, aN4, aN5, aN6, aN7);
                if (!(tx & 1)) atomicAdd(g_denom + (size_t)cur_d * 8 + hd, aD);
            }
            BAR_ARRIVE(4 + g, 512);
        }
    }
}

// ---------------- node update: h -> himg only (no f32 copy) ----------------
__global__ void update_h_kernel() {
    int gid = blockIdx.x * blockDim.x + threadIdx.x;
    if (gid >= N_NODES * 16) return;
    int n = gid >> 4, j = gid & 15, c0 = j * 8;
    float inv = 1.0f / (g_denom[n * 8 + (c0 >> 4)] + 1e-16f);
    float4 n0 = *(const float4*)(g_numer + (size_t)n * 128 + c0);
    float4 n1 = *(const float4*)(g_numer + (size_t)n * 128 + c0 + 4);
    float4 s0 = *(const float4*)(g_skip + (size_t)n * 128 + c0);
    float4 s1 = *(const float4*)(g_skip + (size_t)n * 128 + c0 + 4);
    float v[8];
    v[0] = fmaxf(n0.x * inv + s0.x, 0.f); v[1] = fmaxf(n0.y * inv + s0.y, 0.f);
    v[2] = fmaxf(n0.z * inv + s0.z, 0.f); v[3] = fmaxf(n0.w * inv + s0.w, 0.f);
    v[4] = fmaxf(n1.x * inv + s1.x, 0.f); v[5] = fmaxf(n1.y * inv + s1.y, 0.f);
    v[6] = fmaxf(n1.z * inv + s1.z, 0.f); v[7] = fmaxf(n1.w * inv + s1.w, 0.f);
    store8_h16(g_himg + (size_t)(n >> 7) * TBYTES, (n & 127) * TROW + c0 * 2, v);
    float4 z = make_float4(0.f, 0.f, 0.f, 0.f);
    *(float4*)(g_numer + (size_t)n * 128 + c0)     = z;
    *(float4*)(g_numer + (size_t)n * 128 + c0 + 4) = z;
    if (!(j & 1)) g_denom[n * 8 + (j >> 1)] = 0.0f;
}

// ---------------- output GEMM: reads fp16 himg tiles ----------------
__global__ void out_gemm_kernel(const float* __restrict__ Wout, const float* __restrict__ bout,
                                float* __restrict__ out) {
    __shared__ __align__(16) unsigned char hs[TBYTES];
    __shared__ float ws[128 * 16];
    int tid = threadIdx.x;
    int tile = blockIdx.x;
    const uint4* aimg = (const uint4*)(g_himg + (size_t)tile * TBYTES);
    uint4* sH = (uint4*)hs;
    for (int i = tid; i < 2176; i += 256) sH[i] = aimg[i];
#pragma unroll
    for (int it = 0; it < 8; ++it) ws[it * 256 + tid] = Wout[it * 256 + tid];
    __syncthreads();

    int r = tid >> 1;                 // row 0..127
    int c8 = (tid & 1) * 8;          // col base 0 or 8
    int node = tile * 128 + r;
    if (node >= N_NODES) return;
    const __half* hrow = (const __half*)(hs + r * TROW);
    float acc[8];
#pragma unroll
    for (int j = 0; j < 8; ++j) acc[j] = bout[c8 + j];
    for (int k = 0; k < 128; ++k) {
        float hv = __half2float(hrow[k]);
        const float* wk = ws + k * 16 + c8;
#pragma unroll
        for (int j = 0; j < 8; ++j) acc[j] += hv * wk[j];
    }
    float* op = out + (size_t)node * 16 + c8;
#pragma unroll
    for (int j = 0; j < 8; ++j) op[j] = acc[j];
}

// ---------------- host ----------------
extern "C" void kernel_launch(void* const* d_in, const int* in_sizes, int n_in,
                              void* d_out, int out_size) {
    const float* x     = (const float*)d_in[0];
    const int*   nlu   = (const int*)  d_in[1];
    const int*   ei    = (const int*)  d_in[2];
    const float* eattr = (const float*)d_in[3];
    const int*   elu   = (const int*)  d_in[4];
    const float* Wq    = (const float*)d_in[5];
    const float* bq    = (const float*)d_in[6];
    const float* Wk    = (const float*)d_in[7];
    const float* bk    = (const float*)d_in[8];
    const float* Wv    = (const float*)d_in[9];
    const float* bv    = (const float*)d_in[10];
    const float* We    = (const float*)d_in[11];
    const float* Ws    = (const float*)d_in[12];
    const float* bs    = (const float*)d_in[13];
    const float* Wout  = (const float*)d_in[14];
    const float* bout  = (const float*)d_in[15];
    float* out = (float*)d_out;
    (void)in_sizes; (void)n_in; (void)out_size;

    cudaFuncSetAttribute(node_mma_kernel, cudaFuncAttributeMaxDynamicSharedMemorySize, SMEM_NODE);
    cudaFuncSetAttribute(edge_mma_kernel, cudaFuncAttributeMaxDynamicSharedMemorySize, SMEM_EDGE);

    const int SCAN_BLOCKS = (N_NODES + 1023) / 1024;
    zero_count_kernel<<<(N_NODES + 255) / 256, 256>>>();
    hist_kernel<<<(N_EDGES + 255) / 256, 256>>>(ei);
    scan_p1_kernel<<<SCAN_BLOCKS, 1024>>>();
    scan_p2_kernel<<<1, 32>>>(SCAN_BLOCKS);
    scan_p3_kernel<<<SCAN_BLOCKS, 1024>>>();
    scatter_kernel<<<(N_EDGES + 255) / 256, 256>>>(ei);

    build_h_kernel    <<<(N_NODES * 16 + 255) / 256, 256>>>(x, nlu);
    build_eaimg_kernel<<<(N_EDGES * 16 + 255) / 256, 256>>>(eattr, elu);
    prep_w_kernel     <<<(15 * 2048 + 255) / 256, 256>>>(Wq, Wk, Wv, Ws, We);

    for (int l = 0; l < 3; ++l) {
        node_mma_kernel<<<dim3(N_NTILE, 2), 256, SMEM_NODE>>>(bq, bk, bv, bs, l);
        edge_mma_kernel<<<148, 768, SMEM_EDGE>>>(l);
        update_h_kernel<<<(N_NODES * 16 + 255) / 256, 256>>>();
    }
    out_gemm_kernel<<<N_NTILE, 256>>>(Wout, bout, out);
}

// round 17
// speedup vs baseline: 2.2051x; 1.0323x over previous
#include <cuda_runtime.h>
#include <cuda_fp16.h>
#include <math.h>
#include <stdint.h>

#define N_NODES 100000
#define N_EDGES 800000
#define N_NTILE 782
#define N_ETILE 6250

// fp16 tile image: 128 rows x 136 fp16 (272B stride)
#define TROW 272
#define TBYTES 34816

// ---------------- device scratch ----------------
__device__ __half g_qh[(size_t)N_NODES * 128];
__device__ __half g_kvh[(size_t)N_NODES * 256];   // interleaved: node*256 + (col/8)*16 + col%8 (k), +8 (v)
__device__ float g_skip[(size_t)N_NODES * 128];
__device__ float g_numer[(size_t)N_NODES * 128];
__device__ float g_denom[(size_t)N_NODES * 8];
__device__ unsigned char g_himg[(size_t)N_NTILE * TBYTES];    // h: fp16 (GEMM A + out_gemm input)
__device__ unsigned char g_eaimg[(size_t)N_EDGES * TROW];     // ea rows in ORIGINAL edge order
__device__ unsigned char g_wimg[(size_t)15 * TBYTES];         // W: fp16
// sort scratch
__device__ int g_count[N_NODES];
__device__ int g_off2[N_NODES];
__device__ int g_bsum[128];
__device__ int g_src_s[N_EDGES];
__device__ int g_dst_s[N_EDGES];
__device__ int g_perm[N_EDGES];

// ---------------- PTX helpers ----------------
__device__ __forceinline__ uint32_t smem_u32(const void* p) {
    uint32_t a;
    asm("{ .reg .u64 t; cvta.to.shared.u64 t, %1; cvt.u32.u64 %0, t; }" : "=r"(a) : "l"(p));
    return a;
}
__device__ __forceinline__ void ldsm4(uint32_t* r, uint32_t addr) {
    asm volatile("ldmatrix.sync.aligned.m8n8.x4.shared.b16 {%0,%1,%2,%3}, [%4];"
                 : "=r"(r[0]), "=r"(r[1]), "=r"(r[2]), "=r"(r[3]) : "r"(addr));
}
__device__ __forceinline__ void mma16816h(float* c, const uint32_t* a, uint32_t b0, uint32_t b1) {
    asm volatile("mma.sync.aligned.m16n8k16.row.col.f32.f16.f16.f32 "
                 "{%0,%1,%2,%3}, {%4,%5,%6,%7}, {%8,%9}, {%0,%1,%2,%3};"
                 : "+f"(c[0]), "+f"(c[1]), "+f"(c[2]), "+f"(c[3])
                 : "r"(a[0]), "r"(a[1]), "r"(a[2]), "r"(a[3]), "r"(b0), "r"(b1));
}
__device__ __forceinline__ void red_add4(float* addr, float a, float b, float c, float d) {
    asm volatile("red.global.add.v4.f32 [%0], {%1, %2, %3, %4};"
                 :: "l"(addr), "f"(a), "f"(b), "f"(c), "f"(d) : "memory");
}
__device__ __forceinline__ void cp_async16(uint32_t dst, const void* src) {
    asm volatile("cp.async.cg.shared.global [%0], [%1], 16;" :: "r"(dst), "l"(src));
}
#define CP_COMMIT() asm volatile("cp.async.commit_group;" ::: "memory")
#define CP_WAIT0()  asm volatile("cp.async.wait_group 0;" ::: "memory")
#define BAR_SYNC(id, n)   asm volatile("bar.sync %0, %1;"   :: "r"(id), "r"(n) : "memory")
#define BAR_ARRIVE(id, n) asm volatile("bar.arrive %0, %1;" :: "r"(id), "r"(n) : "memory")

__device__ __forceinline__ float pe_val(int t, int c) {
    int j = c >> 1;
    float freq = expf(-logf(10000.0f) * (float)(2 * j) * (1.0f / 16.0f));
    float ang = (float)t * freq;
    return (c & 1) ? cosf(ang) : sinf(ang);
}
__device__ __forceinline__ void store8_h16(unsigned char* img, int off, const float* v) {
    unsigned int h[4];
#pragma unroll
    for (int i = 0; i < 4; ++i) {
        __half h0 = __float2half_rn(v[2 * i]);
        __half h1 = __float2half_rn(v[2 * i + 1]);
        h[i] = (unsigned int)__half_as_ushort(h0) | ((unsigned int)__half_as_ushort(h1) << 16);
    }
    *(uint4*)(img + off) = make_uint4(h[0], h[1], h[2], h[3]);
}
__device__ __forceinline__ void cvt8_h16(uint4 raw, float* f) {
    const __half2* h2 = (const __half2*)&raw;
#pragma unroll
    for (int i = 0; i < 4; ++i) {
        float2 t = __half22float2(h2[i]);
        f[2 * i] = t.x;
        f[2 * i + 1] = t.y;
    }
}
__device__ __forceinline__ void load8_h16(const __half* p, float* f) {
    cvt8_h16(*(const uint4*)p, f);
}

// single-pass fp16 GEMM, 8-warp layout: warp (wr,wc) -> C[wr*32..+32][wc*64..+64]
__device__ __forceinline__ void gemm1(uint32_t aBase, uint32_t bBase,
                                      int lane, int wr, int wc, float c[2][8][4]) {
    int rA = lane & 15;
    int kA = (lane >> 4) << 3;
    int rB = ((lane >> 4) << 3) + (lane & 7);
    int kB = ((lane >> 3) & 1) << 3;
    uint32_t aRow = aBase + (uint32_t)(wr * 32 + rA) * TROW;
    uint32_t bRow = bBase + (uint32_t)(wc * 64 + rB) * TROW;
#pragma unroll
    for (int k16 = 0; k16 < 8; ++k16) {
        uint32_t ka = (uint32_t)(k16 * 16 + kA) * 2;
        uint32_t kb = (uint32_t)(k16 * 16 + kB) * 2;
        uint32_t a[2][4];
        ldsm4(a[0], aRow + ka);
        ldsm4(a[1], aRow + 16 * TROW + ka);
        uint32_t b[4][4];
#pragma unroll
        for (int p = 0; p < 4; ++p) ldsm4(b[p], bRow + p * 16 * TROW + kb);
#pragma unroll
        for (int t = 0; t < 2; ++t)
#pragma unroll
            for (int nt = 0; nt < 8; ++nt)
                mma16816h(c[t][nt], a[t], b[nt >> 1][(nt & 1) * 2], b[nt >> 1][(nt & 1) * 2 + 1]);
    }
}

// 32x32-chunk fp16 GEMM: warp wr rows [wr*32,+32), cols [colBase,+32), 32 accum regs
__device__ __forceinline__ void gemm_c32(uint32_t aBase, uint32_t bBase,
                                         int lane, int wr, int colBase, float c[2][4][4]) {
    int rA = lane & 15;
    int kA = (lane >> 4) << 3;
    int rB = ((lane >> 4) << 3) + (lane & 7);
    int kB = ((lane >> 3) & 1) << 3;
    uint32_t aRow = aBase + (uint32_t)(wr * 32 + rA) * TROW;
    uint32_t bRow = bBase + (uint32_t)(colBase + rB) * TROW;
#pragma unroll
    for (int k16 = 0; k16 < 8; ++k16) {
        uint32_t ka = (uint32_t)(k16 * 16 + kA) * 2;
        uint32_t kb = (uint32_t)(k16 * 16 + kB) * 2;
        uint32_t a[2][4];
        ldsm4(a[0], aRow + ka);
        ldsm4(a[1], aRow + 16 * TROW + ka);
        uint32_t b[2][4];
        ldsm4(b[0], bRow + kb);
        ldsm4(b[1], bRow + 16 * TROW + kb);
#pragma unroll
        for (int t = 0; t < 2; ++t)
#pragma unroll
            for (int nt = 0; nt < 4; ++nt)
                mma16816h(c[t][nt], a[t], b[nt >> 1][(nt & 1) * 2], b[nt >> 1][(nt & 1) * 2 + 1]);
    }
}

// ---------------- sort-by-dst ----------------
__global__ void zero_count_kernel() {
    int i = blockIdx.x * blockDim.x + threadIdx.x;
    if (i < N_NODES) g_count[i] = 0;
}
__global__ void hist_kernel(const int* __restrict__ ei) {
    int e = blockIdx.x * blockDim.x + threadIdx.x;
    if (e < N_EDGES) atomicAdd(&g_count[ei[N_EDGES + e]], 1);
}
__global__ void scan_p1_kernel() {
    __shared__ int warp_sums[32];
    int tid = threadIdx.x;
    int lane = tid & 31, wid = tid >> 5;
    int idx = blockIdx.x * 1024 + tid;
    int v = (idx < N_NODES) ? g_count[idx] : 0;
    int inc = v;
#pragma unroll
    for (int o = 1; o < 32; o <<= 1) {
        int t = __shfl_up_sync(0xffffffffu, inc, o);
        if (lane >= o) inc += t;
    }
    if (lane == 31) warp_sums[wid] = inc;
    __syncthreads();
    if (wid == 0) {
        int w = warp_sums[lane];
        int wi = w;
#pragma unroll
        for (int o = 1; o < 32; o <<= 1) {
            int t = __shfl_up_sync(0xffffffffu, wi, o);
            if (lane >= o) wi += t;
        }
        warp_sums[lane] = wi - w;
    }
    __syncthreads();
    int ex = inc - v + warp_sums[wid];
    if (idx < N_NODES) g_off2[idx] = ex;
    if (tid == 1023) g_bsum[blockIdx.x] = ex + v;
}
// 128-thread scan of g_bsum
__global__ void scan_p2_kernel(int nblocks) {
    __shared__ int ws[4];
    int tid = threadIdx.x;
    int lane = tid & 31, wid = tid >> 5;
    int v = (tid < nblocks) ? g_bsum[tid] : 0;
    int inc = v;
#pragma unroll
    for (int o = 1; o < 32; o <<= 1) {
        int t = __shfl_up_sync(0xffffffffu, inc, o);
        if (lane >= o) inc += t;
    }
    if (lane == 31) ws[wid] = inc;
    __syncthreads();
    int add = 0;
#pragma unroll
    for (int w = 0; w < 4; ++w) if (w < wid) add += ws[w];
    if (tid < nblocks) g_bsum[tid] = inc - v + add;
}
__global__ void scan_p3_kernel() {
    int idx = blockIdx.x * 1024 + threadIdx.x;
    if (idx < N_NODES) g_off2[idx] += g_bsum[blockIdx.x];
}
__global__ void scatter_kernel(const int* __restrict__ ei) {
    int e = blockIdx.x * blockDim.x + threadIdx.x;
    if (e >= N_EDGES) return;
    int d = ei[N_EDGES + e];
    int pos = atomicAdd(&g_off2[d], 1);
    g_src_s[pos] = ei[e];
    g_dst_s[pos] = d;
    g_perm[pos] = e;
}

// ---------------- builders ----------------
__global__ void build_h_kernel(const float* __restrict__ x, const int* __restrict__ nlu) {
    int gid = blockIdx.x * blockDim.x + threadIdx.x;
    if (gid >= N_NODES * 16) return;
    int n = gid >> 4, j = gid & 15, c0 = j * 8;
    float v[8];
    if (c0 < 96) {
        float4 a = *(const float4*)(x + (size_t)n * 96 + c0);
        float4 b = *(const float4*)(x + (size_t)n * 96 + c0 + 4);
        v[0] = a.x; v[1] = a.y; v[2] = a.z; v[3] = a.w; v[4] = b.x; v[5] = b.y; v[6] = b.z; v[7] = b.w;
    } else {
        int t = nlu[n * 2 + ((c0 - 96) >> 4)];
        int cl = (c0 - 96) & 15;
#pragma unroll
        for (int i = 0; i < 8; ++i) v[i] = pe_val(t, cl + i);
    }
    store8_h16(g_himg + (size_t)(n >> 7) * TBYTES, (n & 127) * TROW + c0 * 2, v);
}
// ea rows in ORIGINAL edge order (fully coalesced); producers apply the sort permutation
__global__ void build_eaimg_kernel(const float* __restrict__ eattr, const int* __restrict__ elu) {
    int gid = blockIdx.x * blockDim.x + threadIdx.x;
    if (gid >= N_EDGES * 16) return;
    int e = gid >> 4, j = gid & 15, c0 = j * 8;
    float v[8];
    if (c0 < 96) {
        float4 a = *(const float4*)(eattr + (size_t)e * 96 + c0);
        float4 b = *(const float4*)(eattr + (size_t)e * 96 + c0 + 4);
        v[0] = a.x; v[1] = a.y; v[2] = a.z; v[3] = a.w; v[4] = b.x; v[5] = b.y; v[6] = b.z; v[7] = b.w;
    } else {
        int t = elu[(size_t)e * 2 + ((c0 - 96) >> 4)];
        int cl = (c0 - 96) & 15;
#pragma unroll
        for (int i = 0; i < 8; ++i) v[i] = pe_val(t, cl + i);
    }
    store8_h16(g_eaimg + (size_t)e * TROW, c0 * 2, v);
}
__global__ void prep_w_kernel(const float* __restrict__ Wq, const float* __restrict__ Wk,
                              const float* __restrict__ Wv, const float* __restrict__ Ws,
                              const float* __restrict__ We) {
    int gid = blockIdx.x * blockDim.x + threadIdx.x;
    if (gid >= 15 * 2048) return;
    int t = gid >> 11, rem = gid & 2047;
    int n = rem >> 4, j = rem & 15, k0 = j * 8;
    int l = t / 5, m = t % 5;
    const float* W = (m == 0) ? Wq : (m == 1) ? Wk : (m == 2) ? Wv : (m == 3) ? Ws : We;
    const float* base = W + (size_t)l * 16384;
    float v[8];
#pragma unroll
    for (int i = 0; i < 8; ++i) v[i] = base[(size_t)(k0 + i) * 128 + n];
    store8_h16(g_wimg + (size_t)t * TBYTES, n * TROW + k0 * 2, v);
}

// ---------------- node GEMM: single-pass fp16; q -> g_qh, k/v -> interleaved g_kvh ----------------
#define OFF_NB 34816
#define OFF_NBIAS 69632
#define SMEM_NODE 70144
__global__ __launch_bounds__(256)
void node_mma_kernel(const float* __restrict__ bq, const float* __restrict__ bk,
                     const float* __restrict__ bv, const float* __restrict__ bsk, int layer) {
    extern __shared__ __align__(16) unsigned char smem[];
    uint32_t sb = smem_u32(smem);
    int tid = threadIdx.x, wid = tid >> 5, lane = tid & 31;
    int wr = wid & 3, wc = wid >> 2;
    int tile = blockIdx.x, ysel = blockIdx.y;
    int gi = lane >> 2, tig = lane & 3;

    const uint4* aimg = (const uint4*)(g_himg + (size_t)tile * TBYTES);
    uint4* sA = (uint4*)smem;
    for (int i = tid; i < 2176; i += 256) sA[i] = aimg[i];

    float* biasBuf = (float*)(smem + OFF_NBIAS);
    uint4* sB = (uint4*)(smem + OFF_NB);

    for (int w2 = 0; w2 < 2; ++w2) {
        int w = ysel * 2 + w2;
        __syncthreads();
        const uint4* bimg = (const uint4*)(g_wimg + (size_t)(layer * 5 + w) * TBYTES);
        for (int i = tid; i < 2176; i += 256) sB[i] = bimg[i];
        if (tid < 128) {
            const float* bias = (w == 0) ? bq : (w == 1) ? bk : (w == 2) ? bv : bsk;
            biasBuf[tid] = bias[layer * 128 + tid];
        }
        __syncthreads();

        float c[2][8][4];
#pragma unroll
        for (int t = 0; t < 2; ++t)
#pragma unroll
            for (int nt = 0; nt < 8; ++nt)
#pragma unroll
                for (int j = 0; j < 4; ++j) c[t][nt][j] = 0.0f;

        gemm1(sb, sb + OFF_NB, lane, wr, wc, c);

#pragma unroll
        for (int t = 0; t < 2; ++t) {
#pragma unroll
            for (int half = 0; half < 2; ++half) {
                int node = tile * 128 + wr * 32 + t * 16 + gi + half * 8;
                if (node < N_NODES) {
                    if (w == 0) {
                        __half* oph = g_qh + (size_t)node * 128;
#pragma unroll
                        for (int nt = 0; nt < 8; ++nt) {
                            int col = wc * 64 + nt * 8 + tig * 2;
                            *(__half2*)(oph + col) = __floats2half2_rn(c[t][nt][half * 2 + 0] + biasBuf[col],
                                                                       c[t][nt][half * 2 + 1] + biasBuf[col + 1]);
                        }
                    } else if (w < 3) {
                        __half* oph = g_kvh + (size_t)node * 256 + (w == 2 ? 8 : 0);
#pragma unroll
                        for (int nt = 0; nt < 8; ++nt) {
                            int col = wc * 64 + nt * 8 + tig * 2;
                            *(__half2*)(oph + (col >> 3) * 16 + (col & 7)) =
                                __floats2half2_rn(c[t][nt][half * 2 + 0] + biasBuf[col],
                                                  c[t][nt][half * 2 + 1] + biasBuf[col + 1]);
                        }
                    } else {
                        float* op = g_skip + (size_t)node * 128;
#pragma unroll
                        for (int nt = 0; nt < 8; ++nt) {
                            int col = wc * 64 + nt * 8 + tig * 2;
                            *(float2*)(op + col) = make_float2(c[t][nt][half * 2 + 0] + biasBuf[col],
                                                               c[t][nt][half * 2 + 1] + biasBuf[col + 1]);
                        }
                    }
                }
            }
        }
    }
}

// ---------------- edge kernel: 8 producer warps + 2x8 consumer-group warps ----------------
// smem: [0,34K) B | [34K,68K) A0 | [68K,102K) A1 | [102K,136K) est0 fp16 | [136K,170K) est1 fp16
#define EB_A0 34816
#define EB_EST0 104448
#define SMEM_EDGE 174080
__global__ __launch_bounds__(768)
void edge_mma_kernel(int layer) {
    extern __shared__ __align__(16) unsigned char smem[];
    uint32_t sb = smem_u32(smem);
    int tid = threadIdx.x, wid = tid >> 5, lane = tid & 31;

    const uint4* bimg = (const uint4*)(g_wimg + (size_t)(layer * 5 + 4) * TBYTES);
    uint4* sB = (uint4*)smem;
    for (int i = tid; i < 2176; i += 768) sB[i] = bimg[i];
    __syncthreads();

    if (wid < 8) {
        // ---- producers: perm-indirect row gather -> gemm -> est ----
        int wr = wid & 3, wc = wid >> 2;
        int gi = lane >> 2, tig = lane & 3;
        int idx = 0;
        for (int tile = blockIdx.x; tile < N_ETILE; tile += 148, ++idx) {
            int b = idx & 1;
            uint32_t aBuf = sb + EB_A0 + b * TBYTES;
            BAR_SYNC(4 + b, 512);
            int e0 = tile << 7;
            for (int i = tid; i < 2176; i += 256) {
                int row = i / 17;
                int chunk = i - row * 17;
                int e = g_perm[e0 + row];
                cp_async16(aBuf + i * 16, g_eaimg + (size_t)e * TROW + chunk * 16);
            }
            CP_COMMIT();
            CP_WAIT0();
            BAR_SYNC(6, 256);

            unsigned char* est = smem + EB_EST0 + b * TBYTES;
#pragma unroll
            for (int h = 0; h < 2; ++h) {
                int colBase = wc * 64 + h * 32;
                float c[2][4][4];
#pragma unroll
                for (int t = 0; t < 2; ++t)
#pragma unroll
                    for (int nt = 0; nt < 4; ++nt)
#pragma unroll
                        for (int j = 0; j < 4; ++j) c[t][nt][j] = 0.0f;

                gemm_c32(aBuf, sb, lane, wr, colBase, c);

#pragma unroll
                for (int t = 0; t < 2; ++t)
#pragma unroll
                    for (int half = 0; half < 2; ++half) {
                        int r = wr * 32 + t * 16 + gi + half * 8;
#pragma unroll
                        for (int nt = 0; nt < 4; ++nt) {
                            int col = colBase + nt * 8 + tig * 2;
                            *(__half2*)(est + r * TROW + col * 2) =
                                __floats2half2_rn(c[t][nt][half * 2], c[t][nt][half * 2 + 1]);
                        }
                    }
            }
            BAR_ARRIVE(2 + b, 512);
        }
    } else {
        // ---- consumer group g: batch-4 kv prefetch, run-coalesced atomics ----
        int g = (wid >= 16) ? 1 : 0;
        int gtid = tid & 255;
        int tx = gtid & 15, ty = gtid >> 4;
        int hd = tx >> 1, cb = tx << 3;
        const unsigned char* est = smem + EB_EST0 + g * TBYTES;
        BAR_ARRIVE(4 + g, 512);
        for (int tile = blockIdx.x + g * 148; tile < N_ETILE; tile += 296) {
            BAR_SYNC(2 + g, 512);
            int e0 = tile << 7;

            int cur_d = -1;
            float qf[8];
            float aN0 = 0.f, aN1 = 0.f, aN2 = 0.f, aN3 = 0.f;
            float aN4 = 0.f, aN5 = 0.f, aN6 = 0.f, aN7 = 0.f;
            float aD = 0.f;
#pragma unroll
            for (int h = 0; h < 2; ++h) {
                int sA[4], dA[4];
                uint4 kraw[4], vraw[4];
#pragma unroll
                for (int i = 0; i < 4; ++i) {
                    int er = ty * 8 + h * 4 + i;
                    sA[i] = g_src_s[e0 + er];
                    dA[i] = g_dst_s[e0 + er];
                    const __half* kvp = g_kvh + (size_t)sA[i] * 256 + tx * 16;
                    kraw[i] = *(const uint4*)kvp;
                    vraw[i] = *(const uint4*)(kvp + 8);
                }
#pragma unroll
                for (int i = 0; i < 4; ++i) {
                    int er = ty * 8 + h * 4 + i;
                    float e8[8];
                    cvt8_h16(*(const uint4*)(est + er * TROW + cb * 2), e8);
                    int d = dA[i];
                    if (d != cur_d) {
                        if (cur_d >= 0) {
                            float* np = g_numer + (size_t)cur_d * 128 + cb;
                            red_add4(np,     aN0, aN1, aN2, aN3);
                            red_add4(np + 4, aN4, aN5, aN6, aN7);
                            if (!(tx & 1)) atomicAdd(g_denom + (size_t)cur_d * 8 + hd, aD);
                        }
                        cur_d = d;
                        aN0 = aN1 = aN2 = aN3 = aN4 = aN5 = aN6 = aN7 = 0.f;
                        aD = 0.f;
                        load8_h16(g_qh + (size_t)d * 128 + cb, qf);
                    }
                    float kf[8], vf[8];
                    cvt8_h16(kraw[i], kf);
                    cvt8_h16(vraw[i], vf);
                    float part = qf[0] * (kf[0] + e8[0]) + qf[1] * (kf[1] + e8[1])
                               + qf[2] * (kf[2] + e8[2]) + qf[3] * (kf[3] + e8[3])
                               + qf[4] * (kf[4] + e8[4]) + qf[5] * (kf[5] + e8[5])
                               + qf[6] * (kf[6] + e8[6]) + qf[7] * (kf[7] + e8[7]);
                    float full = part + __shfl_xor_sync(0xffffffffu, part, 1);
                    float p = __expf(full * 0.25f);  // shift-free softmax (alpha is O(1))
                    aN0 += p * (vf[0] + e8[0]); aN1 += p * (vf[1] + e8[1]);
                    aN2 += p * (vf[2] + e8[2]); aN3 += p * (vf[3] + e8[3]);
                    aN4 += p * (vf[4] + e8[4]); aN5 += p * (vf[5] + e8[5]);
                    aN6 += p * (vf[6] + e8[6]); aN7 += p * (vf[7] + e8[7]);
                    aD += p;
                }
            }
            {
                float* np = g_numer + (size_t)cur_d * 128 + cb;
                red_add4(np,     aN0, aN1, aN2, aN3);
                red_add4(np + 4, aN4, aN5, aN6, aN7);
                if (!(tx & 1)) atomicAdd(g_denom + (size_t)cur_d * 8 + hd, aD);
            }
            BAR_ARRIVE(4 + g, 512);
        }
    }
}

// ---------------- node update: h -> himg only ----------------
__global__ void update_h_kernel() {
    int gid = blockIdx.x * blockDim.x + threadIdx.x;
    if (gid >= N_NODES * 16) return;
    int n = gid >> 4, j = gid & 15, c0 = j * 8;
    float inv = 1.0f / (g_denom[n * 8 + (c0 >> 4)] + 1e-16f);
    float4 n0 = *(const float4*)(g_numer + (size_t)n * 128 + c0);
    float4 n1 = *(const float4*)(g_numer + (size_t)n * 128 + c0 + 4);
    float4 s0 = *(const float4*)(g_skip + (size_t)n * 128 + c0);
    float4 s1 = *(const float4*)(g_skip + (size_t)n * 128 + c0 + 4);
    float v[8];
    v[0] = fmaxf(n0.x * inv + s0.x, 0.f); v[1] = fmaxf(n0.y * inv + s0.y, 0.f);
    v[2] = fmaxf(n0.z * inv + s0.z, 0.f); v[3] = fmaxf(n0.w * inv + s0.w, 0.f);
    v[4] = fmaxf(n1.x * inv + s1.x, 0.f); v[5] = fmaxf(n1.y * inv + s1.y, 0.f);
    v[6] = fmaxf(n1.z * inv + s1.z, 0.f); v[7] = fmaxf(n1.w * inv + s1.w, 0.f);
    store8_h16(g_himg + (size_t)(n >> 7) * TBYTES, (n & 127) * TROW + c0 * 2, v);
    float4 z = make_float4(0.f, 0.f, 0.f, 0.f);
    *(float4*)(g_numer + (size_t)n * 128 + c0)     = z;
    *(float4*)(g_numer + (size_t)n * 128 + c0 + 4) = z;
    if (!(j & 1)) g_denom[n * 8 + (j >> 1)] = 0.0f;
}

// ---------------- output GEMM: reads fp16 himg tiles ----------------
__global__ void out_gemm_kernel(const float* __restrict__ Wout, const float* __restrict__ bout,
                                float* __restrict__ out) {
    __shared__ __align__(16) unsigned char hs[TBYTES];
    __shared__ float ws[128 * 16];
    int tid = threadIdx.x;
    int tile = blockIdx.x;
    const uint4* aimg = (const uint4*)(g_himg + (size_t)tile * TBYTES);
    uint4* sH = (uint4*)hs;
    for (int i = tid; i < 2176; i += 256) sH[i] = aimg[i];
#pragma unroll
    for (int it = 0; it < 8; ++it) ws[it * 256 + tid] = Wout[it * 256 + tid];
    __syncthreads();

    int r = tid >> 1;
    int c8 = (tid & 1) * 8;
    int node = tile * 128 + r;
    if (node >= N_NODES) return;
    const __half* hrow = (const __half*)(hs + r * TROW);
    float acc[8];
#pragma unroll
    for (int j = 0; j < 8; ++j) acc[j] = bout[c8 + j];
    for (int k = 0; k < 128; ++k) {
        float hv = __half2float(hrow[k]);
        const float* wk = ws + k * 16 + c8;
#pragma unroll
        for (int j = 0; j < 8; ++j) acc[j] += hv * wk[j];
    }
    float* op = out + (size_t)node * 16 + c8;
#pragma unroll
    for (int j = 0; j < 8; ++j) op[j] = acc[j];
}

// ---------------- host ----------------
extern "C" void kernel_launch(void* const* d_in, const int* in_sizes, int n_in,
                              void* d_out, int out_size) {
    const float* x     = (const float*)d_in[0];
    const int*   nlu   = (const int*)  d_in[1];
    const int*   ei    = (const int*)  d_in[2];
    const float* eattr = (const float*)d_in[3];
    const int*   elu   = (const int*)  d_in[4];
    const float* Wq    = (const float*)d_in[5];
    const float* bq    = (const float*)d_in[6];
    const float* Wk    = (const float*)d_in[7];
    const float* bk    = (const float*)d_in[8];
    const float* Wv    = (const float*)d_in[9];
    const float* bv    = (const float*)d_in[10];
    const float* We    = (const float*)d_in[11];
    const float* Ws    = (const float*)d_in[12];
    const float* bs    = (const float*)d_in[13];
    const float* Wout  = (const float*)d_in[14];
    const float* bout  = (const float*)d_in[15];
    float* out = (float*)d_out;
    (void)in_sizes; (void)n_in; (void)out_size;

    cudaFuncSetAttribute(node_mma_kernel, cudaFuncAttributeMaxDynamicSharedMemorySize, SMEM_NODE);
    cudaFuncSetAttribute(edge_mma_kernel, cudaFuncAttributeMaxDynamicSharedMemorySize, SMEM_EDGE);

    const int SCAN_BLOCKS = (N_NODES + 1023) / 1024;
    zero_count_kernel<<<(N_NODES + 255) / 256, 256>>>();
    hist_kernel<<<(N_EDGES + 255) / 256, 256>>>(ei);
    scan_p1_kernel<<<SCAN_BLOCKS, 1024>>>();
    scan_p2_kernel<<<1, 128>>>(SCAN_BLOCKS);
    scan_p3_kernel<<<SCAN_BLOCKS, 1024>>>();
    scatter_kernel<<<(N_EDGES + 255) / 256, 256>>>(ei);

    build_h_kernel    <<<(N_NODES * 16 + 255) / 256, 256>>>(x, nlu);
    build_eaimg_kernel<<<(N_EDGES * 16 + 255) / 256, 256>>>(eattr, elu);
    prep_w_kernel     <<<(15 * 2048 + 255) / 256, 256>>>(Wq, Wk, Wv, Ws, We);

    for (int l = 0; l < 3; ++l) {
        node_mma_kernel<<<dim3(N_NTILE, 2), 256, SMEM_NODE>>>(bq, bk, bv, bs, l);
        edge_mma_kernel<<<148, 768, SMEM_EDGE>>>(l);
        update_h_kernel<<<(N_NODES * 16 + 255) / 256, 256>>>();
    }
    out_gemm_kernel<<<N_NTILE, 256>>>(Wout, bout, out);
}